// round 12
// baseline (speedup 1.0000x reference)
#include <cuda_runtime.h>
#include <cuda_fp16.h>
#include <math.h>

// ---------------------------------------------------------------------------
// Problem constants
// ---------------------------------------------------------------------------
namespace {
constexpr int NB = 2, NS = 1024, NHID = 1024, NHEAD = 8, DHEAD = 128;
constexpr int NEXP = 8, NMI = 1024, NSI = 2048;
constexpr int NT = NB * NS;          // 2048 tokens
constexpr int NSLOT = 2 * NT;        // 4096 expert slots (top-2)

// fp16 GEMM tile: 128x128x64(halves), 8 warps of 64x32, 3-stage cp.async
constexpr int BM = 128, BN = 128, BKH = 64;      // 64 halves per k-iter
constexpr int PADW = 36;                         // row stride in b32 (144B)
constexpr int STAGES = 3;
constexpr int STAGE_WORDS = BM * PADW;           // 4608 b32 per tile-stage
constexpr int SMEM_BYTES = 2 * STAGES * STAGE_WORDS * 4;   // 110592

// flash attention smem: Q + 2xK + 2xV tiles of 128 rows x 68 words
constexpr int FPW = 68;                          // words per row (136 halves)
constexpr int FTILE_W = 128 * FPW;               // 8704 words per tile
constexpr int FLASH_SMEM = 5 * FTILE_W * 4;      // 174080 bytes
}

// ---------------------------------------------------------------------------
// Static device scratch (no allocations allowed)
// ---------------------------------------------------------------------------
// fp32 buffers
__device__ float d_xn32[NT * NHID];
__device__ float d_x1[NT * NHID];
__device__ float d_sh[NT * NHID];
// fp16 weights
__device__ __half h_qw[NHID * NHID];
__device__ __half h_kw[NHID * NHID];
__device__ __half h_vw[NHID * NHID];
__device__ __half h_ow[NHID * NHID];
__device__ __half h_eg[NEXP * NMI * NHID];
__device__ __half h_eu[NEXP * NMI * NHID];
__device__ __half h_ed[NEXP * NHID * NMI];
__device__ __half h_sg[NSI * NHID];
__device__ __half h_su[NSI * NHID];
__device__ __half h_sd[NHID * NSI];
// fp16 activations
__device__ __half h_xn[NT * NHID];
__device__ __half h_q0[NT * NHID];    // QKV GEMM outputs, (t, head*128+d)
__device__ __half h_k0[NT * NHID];
__device__ __half h_v0[NT * NHID];
__device__ __half h_qr[NT * NHID];    // rope'd + scaled
__device__ __half h_kr[NT * NHID];
__device__ __half h_ctx[NT * NHID];   // flash output
__device__ __half h_xg[NSLOT * NHID];
__device__ __half h_gbuf[NSLOT * NMI];   // MoE gate GEMM out (half)
__device__ __half h_ubuf[NSLOT * NMI];   // MoE up GEMM out (half)
__device__ __half h_gb[NSLOT * NMI];     // silu(g)*u (half)
__device__ __half h_ybuf[NSLOT * NHID];  // MoE down out (half)
__device__ __half h_gs32[NT * NSI];      // shared gate GEMM out (half)
__device__ __half h_us32[NT * NSI];      // shared up GEMM out (half)
__device__ __half h_gs[NT * NSI];        // silu(g)*u (half)
// routing state
__device__ int   d_cnt[NEXP];
__device__ int   d_off[NEXP];
__device__ int   d_e0[NT], d_e1[NT], d_r0[NT], d_r1[NT], d_s0[NT], d_s1[NT];
__device__ float d_w0[NT], d_w1[NT];

// ---------------------------------------------------------------------------
// helpers
// ---------------------------------------------------------------------------
__device__ __forceinline__ unsigned smem_u32(const void* p) {
    return (unsigned)__cvta_generic_to_shared(p);
}

__device__ __forceinline__ void cp16(unsigned dst, const void* src, bool pred) {
    int sz = pred ? 16 : 0;
    asm volatile("cp.async.cg.shared.global [%0], [%1], 16, %2;\n"
                 :: "r"(dst), "l"(src), "r"(sz));
}

__device__ __forceinline__ void ldsm4(unsigned& r0, unsigned& r1,
                                      unsigned& r2, unsigned& r3, unsigned addr)
{
    asm volatile("ldmatrix.sync.aligned.m8n8.x4.shared.b16 {%0,%1,%2,%3}, [%4];"
                 : "=r"(r0), "=r"(r1), "=r"(r2), "=r"(r3) : "r"(addr));
}

__device__ __forceinline__ void ldsm4t(unsigned& r0, unsigned& r1,
                                       unsigned& r2, unsigned& r3, unsigned addr)
{
    asm volatile("ldmatrix.sync.aligned.m8n8.x4.trans.shared.b16 {%0,%1,%2,%3}, [%4];"
                 : "=r"(r0), "=r"(r1), "=r"(r2), "=r"(r3) : "r"(addr));
}

__device__ __forceinline__ void mma_f16(float c[4],
    unsigned a0, unsigned a1, unsigned a2, unsigned a3,
    unsigned b0, unsigned b1)
{
    asm volatile(
        "mma.sync.aligned.m16n8k16.row.col.f32.f16.f16.f32 "
        "{%0,%1,%2,%3}, {%4,%5,%6,%7}, {%8,%9}, {%0,%1,%2,%3};\n"
        : "+f"(c[0]), "+f"(c[1]), "+f"(c[2]), "+f"(c[3])
        : "r"(a0), "r"(a1), "r"(a2), "r"(a3), "r"(b0), "r"(b1));
}

__device__ __forceinline__ unsigned packh2(float a, float b) {
    __half2 h = __floats2half2_rn(a, b);
    return *reinterpret_cast<unsigned*>(&h);
}

// ---------------------------------------------------------------------------
// FP16 tensor-core GEMM:  C[M,N] = A[M,K] * B^T  (B stored (N,K) row-major,
// offsets in HALVES).  128x128 block, 8 warps of 64x32 (4x4 m16n8k16),
// 3-stage cp.async with 64-half k-chunks (one __syncthreads per 64 halves),
// ldmatrix operand loads.  OutT = float or __half.
// ---------------------------------------------------------------------------
template <typename OutT>
__device__ __forceinline__ void hgemm_body(
    const __half* __restrict__ A, const __half* __restrict__ Bm,
    OutT* __restrict__ C, const float* __restrict__ resid,
    int M, int K, int lda, int ldb, int ldc)
{
    extern __shared__ unsigned smu[];
    unsigned* Asm = smu;                         // [STAGES][BM][PADW]
    unsigned* Bsm = smu + STAGES * STAGE_WORDS;

    const int tid  = threadIdx.x;
    const int wid  = tid >> 5;
    const int lane = tid & 31;
    const int g    = lane >> 2;
    const int tg   = lane & 3;
    const int wm   = (wid & 1) * 64;
    const int wn   = (wid >> 1) * 32;
    const int row0 = blockIdx.y * BM;
    const int col0 = blockIdx.x * BN;
    if (row0 >= M) return;

    const int rA = (lane & 7) + ((lane >> 3) & 1) * 8;
    const int cA = ((lane >> 4) & 1) * 4;
    const int rB = (lane & 7) + ((lane >> 4) & 1) * 8;
    const int cB = ((lane >> 3) & 1) * 4;

    float c[4][4][4];
#pragma unroll
    for (int mi = 0; mi < 4; ++mi)
#pragma unroll
        for (int ni = 0; ni < 4; ++ni)
#pragma unroll
            for (int r = 0; r < 4; ++r) c[mi][ni][r] = 0.f;

    const int lr  = tid >> 1;            // row 0..127
    const int lsh = (tid & 1) * 32;      // half-offset 0/32 (4 x 16B segs)
    const int lsw = (tid & 1) * 16;      // b32-word offset 0/16
    const int niter = K / BKH;

    // ---- prologue: stages 0,1 ----
#pragma unroll
    for (int st = 0; st < STAGES - 1; ++st) {
        if (st < niter) {
            const int k0 = st * BKH;
            const __half* ga = A + (long)(row0 + lr) * lda + k0 + lsh;
            unsigned da = smem_u32(Asm + st * STAGE_WORDS + lr * PADW + lsw);
            bool pa = (row0 + lr) < M;
#pragma unroll
            for (int i = 0; i < 4; ++i) cp16(da + i * 16, ga + i * 8, pa);
            const __half* gb = Bm + (long)(col0 + lr) * ldb + k0 + lsh;
            unsigned db = smem_u32(Bsm + st * STAGE_WORDS + lr * PADW + lsw);
#pragma unroll
            for (int i = 0; i < 4; ++i) cp16(db + i * 16, gb + i * 8, true);
        }
        asm volatile("cp.async.commit_group;\n");
    }

    int s = 0;
    for (int it = 0; it < niter; ++it) {
        asm volatile("cp.async.wait_group 1;\n");
        __syncthreads();

        const int pf = it + STAGES - 1;
        if (pf < niter) {
            int sl = s + STAGES - 1; if (sl >= STAGES) sl -= STAGES;
            const int k0 = pf * BKH;
            const __half* ga = A + (long)(row0 + lr) * lda + k0 + lsh;
            unsigned da = smem_u32(Asm + sl * STAGE_WORDS + lr * PADW + lsw);
            bool pa = (row0 + lr) < M;
#pragma unroll
            for (int i = 0; i < 4; ++i) cp16(da + i * 16, ga + i * 8, pa);
            const __half* gb = Bm + (long)(col0 + lr) * ldb + k0 + lsh;
            unsigned db = smem_u32(Bsm + sl * STAGE_WORDS + lr * PADW + lsw);
#pragma unroll
            for (int i = 0; i < 4; ++i) cp16(db + i * 16, gb + i * 8, true);
        }
        asm volatile("cp.async.commit_group;\n");

        const unsigned a_base = smem_u32(Asm + s * STAGE_WORDS);
        const unsigned b_base = smem_u32(Bsm + s * STAGE_WORDS);
#pragma unroll
        for (int kk = 0; kk < 4; ++kk) {
            const int kb = kk * 8;       // b32 column base (16 halves)
            unsigned af[4][4], bf[4][2];
#pragma unroll
            for (int mi = 0; mi < 4; ++mi) {
                unsigned addr = a_base +
                    4u * ((wm + mi * 16 + rA) * PADW + kb + cA);
                ldsm4(af[mi][0], af[mi][1], af[mi][2], af[mi][3], addr);
            }
#pragma unroll
            for (int p = 0; p < 2; ++p) {
                unsigned addr = b_base +
                    4u * ((wn + p * 16 + rB) * PADW + kb + cB);
                ldsm4(bf[2 * p][0], bf[2 * p][1],
                      bf[2 * p + 1][0], bf[2 * p + 1][1], addr);
            }
#pragma unroll
            for (int mi = 0; mi < 4; ++mi)
#pragma unroll
                for (int ni = 0; ni < 4; ++ni)
                    mma_f16(c[mi][ni], af[mi][0], af[mi][1], af[mi][2], af[mi][3],
                            bf[ni][0], bf[ni][1]);
        }
        if (++s >= STAGES) s = 0;
    }

    // ---- epilogue ----
#pragma unroll
    for (int mi = 0; mi < 4; ++mi) {
#pragma unroll
        for (int half = 0; half < 2; ++half) {
            int r = row0 + wm + mi * 16 + g + half * 8;
            if (r < M) {
#pragma unroll
                for (int ni = 0; ni < 4; ++ni) {
                    long off = (long)r * ldc + col0 + wn + ni * 8 + tg * 2;
                    float vx = c[mi][ni][half * 2 + 0];
                    float vy = c[mi][ni][half * 2 + 1];
                    if (resid) {
                        float2 rr = *(const float2*)(resid + off);
                        vx += rr.x; vy += rr.y;
                    }
                    if constexpr (sizeof(OutT) == 4) {
                        float2 v; v.x = vx; v.y = vy;
                        *(float2*)((float*)C + off) = v;
                    } else {
                        __half2 hv = __floats2half2_rn(vx, vy);
                        *(__half2*)((__half*)C + off) = hv;
                    }
                }
            }
        }
    }
}

// ---- generic batched float-out (O-proj, shared-down)
__global__ __launch_bounds__(256, 2)
void hgemm_bat(
    const __half* __restrict__ A, const __half* __restrict__ Bm,
    float* __restrict__ C, const float* __restrict__ resid,
    int M, int K, int lda, int ldb, int ldc,
    long sA, long sB, long sC)
{
    int z = blockIdx.z;
    hgemm_body<float>(A + (long)z * sA, Bm + (long)z * sB, C + (long)z * sC,
                      resid, M, K, lda, ldb, ldc);
}

// ---- fused Q/K/V projection (half out)
__global__ __launch_bounds__(256, 2)
void hqkv_k(const __half* __restrict__ xn)
{
    int z = blockIdx.z;
    const __half* B = (z == 0) ? h_qw : (z == 1) ? h_kw : h_vw;
    __half* C       = (z == 0) ? h_q0 : (z == 1) ? h_k0 : h_v0;
    hgemm_body<__half>(xn, B, C, nullptr, NT, NHID, NHID, NHID, NHID);
}

// ---- fused shared-MLP gate+up (half out)
__global__ __launch_bounds__(256, 2)
void hshup_k(const __half* __restrict__ xn)
{
    int z = blockIdx.z;
    hgemm_body<__half>(xn, z ? h_su : h_sg, z ? h_us32 : h_gs32, nullptr,
                       NT, NHID, NHID, NHID, NSI);
}

// ---- fused MoE gate+up grouped (half out): z = 2*e + which
__global__ __launch_bounds__(256, 2)
void hmoeup_k(const __half* __restrict__ xg)
{
    int z = blockIdx.z;
    int e = z >> 1;
    int M = d_cnt[e];
    int off = d_off[e];
    const __half* B = (z & 1) ? h_eu : h_eg;
    __half* C       = (z & 1) ? h_ubuf : h_gbuf;
    hgemm_body<__half>(xg + (long)off * NHID, B + (long)e * NMI * NHID,
                       C + (long)off * NMI, nullptr, M, NHID, NHID, NHID, NMI);
}

// ---- MoE down grouped (half out)
__global__ __launch_bounds__(256, 2)
void hmoedn_k(const __half* __restrict__ gb)
{
    int e = blockIdx.z;
    int M = d_cnt[e];
    int off = d_off[e];
    hgemm_body<__half>(gb + (long)off * NMI, h_ed + (long)e * NHID * NMI,
                       h_ybuf + (long)off * NHID, nullptr, M, NMI, NMI, NMI, NHID);
}

// ---------------------------------------------------------------------------
// Flash attention (r8, unchanged): one CTA per (q-tile 128, head).
// ---------------------------------------------------------------------------
__global__ __launch_bounds__(256, 1)
void flash_k(const __half* __restrict__ q, const __half* __restrict__ k,
             const __half* __restrict__ v, __half* __restrict__ o)
{
    extern __shared__ unsigned fsm[];
    unsigned* Qs = fsm;
    unsigned* Ks = fsm + FTILE_W;
    unsigned* Vs = fsm + 3 * FTILE_W;

    const int qi  = blockIdx.x;
    const int bh  = blockIdx.y;
    const int b   = bh >> 3, n = bh & 7;
    const int tid = threadIdx.x, wid = tid >> 5, lane = tid & 31;
    const int g   = lane >> 2, tg = lane & 3;
    const int wq  = wid * 16;
    const int row0 = qi * 128;

    const long qbase  = ((long)b * NS + row0) * NHID + n * DHEAD;
    const long kvbase = ((long)b * NS) * NHID + n * DHEAD;

    const int rA = (lane & 7) + ((lane >> 3) & 1) * 8;
    const int cA = ((lane >> 4) & 1) * 4;
    const int rB = (lane & 7) + ((lane >> 4) & 1) * 8;
    const int cB = ((lane >> 3) & 1) * 4;
    const int rV = lane & 15;
    const int cV = (lane >> 4) * 4;

    {
        int r = tid >> 1, hh = tid & 1;
        const __half* gq = q + qbase + (long)r * NHID + hh * 64;
        unsigned dq = smem_u32(Qs + r * FPW + hh * 32);
#pragma unroll
        for (int c2 = 0; c2 < 8; ++c2) cp16(dq + c2 * 16, gq + c2 * 8, true);
    }
    {
        int r = tid >> 1, hh = tid & 1;
        const __half* gk = k + kvbase + (long)r * NHID + hh * 64;
        const __half* gv = v + kvbase + (long)r * NHID + hh * 64;
        unsigned dk = smem_u32(Ks + r * FPW + hh * 32);
        unsigned dv = smem_u32(Vs + r * FPW + hh * 32);
#pragma unroll
        for (int c2 = 0; c2 < 8; ++c2) {
            cp16(dk + c2 * 16, gk + c2 * 8, true);
            cp16(dv + c2 * 16, gv + c2 * 8, true);
        }
    }
    asm volatile("cp.async.commit_group;\n");
    asm volatile("cp.async.wait_group 0;\n");
    __syncthreads();

    float oacc[16][4];
#pragma unroll
    for (int j = 0; j < 16; ++j)
#pragma unroll
        for (int r = 0; r < 4; ++r) oacc[j][r] = 0.f;
    float m0 = -1e30f, m1 = -1e30f, l0 = 0.f, l1 = 0.f;

    for (int t = 0; t <= qi; ++t) {
        const int cur = t & 1;
        if (t + 1 <= qi) {
            int nxt = (t + 1) & 1;
            int r = tid >> 1, hh = tid & 1;
            const __half* gk = k + kvbase + ((long)(t + 1) * 128 + r) * NHID + hh * 64;
            const __half* gv = v + kvbase + ((long)(t + 1) * 128 + r) * NHID + hh * 64;
            unsigned dk = smem_u32(Ks + nxt * FTILE_W + r * FPW + hh * 32);
            unsigned dv = smem_u32(Vs + nxt * FTILE_W + r * FPW + hh * 32);
#pragma unroll
            for (int c2 = 0; c2 < 8; ++c2) {
                cp16(dk + c2 * 16, gk + c2 * 8, true);
                cp16(dv + c2 * 16, gv + c2 * 8, true);
            }
        }
        asm volatile("cp.async.commit_group;\n");

        const unsigned kbase = smem_u32(Ks + cur * FTILE_W);
        const unsigned vbase = smem_u32(Vs + cur * FTILE_W);
        const unsigned qbse  = smem_u32(Qs);

        float sacc[16][4];
#pragma unroll
        for (int j = 0; j < 16; ++j)
#pragma unroll
            for (int r = 0; r < 4; ++r) sacc[j][r] = 0.f;

#pragma unroll
        for (int ks = 0; ks < 8; ++ks) {
            unsigned qa[4];
            ldsm4(qa[0], qa[1], qa[2], qa[3],
                  qbse + 4u * ((wq + rA) * FPW + ks * 8 + cA));
#pragma unroll
            for (int p = 0; p < 8; ++p) {
                unsigned b0, b1, b2, b3;
                ldsm4(b0, b1, b2, b3,
                      kbase + 4u * ((p * 16 + rB) * FPW + ks * 8 + cB));
                mma_f16(sacc[2 * p],     qa[0], qa[1], qa[2], qa[3], b0, b1);
                mma_f16(sacc[2 * p + 1], qa[0], qa[1], qa[2], qa[3], b2, b3);
            }
        }

        if (t == qi) {
            int r0l = wq + g, r1l = wq + g + 8;
#pragma unroll
            for (int j = 0; j < 16; ++j) {
                int col = 8 * j + 2 * tg;
                if (col     > r0l) sacc[j][0] = -1e30f;
                if (col + 1 > r0l) sacc[j][1] = -1e30f;
                if (col     > r1l) sacc[j][2] = -1e30f;
                if (col + 1 > r1l) sacc[j][3] = -1e30f;
            }
        }

        float tm0 = -1e30f, tm1 = -1e30f;
#pragma unroll
        for (int j = 0; j < 16; ++j) {
            tm0 = fmaxf(tm0, fmaxf(sacc[j][0], sacc[j][1]));
            tm1 = fmaxf(tm1, fmaxf(sacc[j][2], sacc[j][3]));
        }
        tm0 = fmaxf(tm0, __shfl_xor_sync(0xffffffffu, tm0, 1));
        tm0 = fmaxf(tm0, __shfl_xor_sync(0xffffffffu, tm0, 2));
        tm1 = fmaxf(tm1, __shfl_xor_sync(0xffffffffu, tm1, 1));
        tm1 = fmaxf(tm1, __shfl_xor_sync(0xffffffffu, tm1, 2));
        float nm0 = fmaxf(m0, tm0), nm1 = fmaxf(m1, tm1);
        float al0 = __expf(m0 - nm0), al1 = __expf(m1 - nm1);

        float rs0 = 0.f, rs1 = 0.f;
        unsigned pf[8][4];
#pragma unroll
        for (int j = 0; j < 16; ++j) {
            float p0 = __expf(sacc[j][0] - nm0);
            float p1 = __expf(sacc[j][1] - nm0);
            float p2 = __expf(sacc[j][2] - nm1);
            float p3 = __expf(sacc[j][3] - nm1);
            rs0 += p0 + p1; rs1 += p2 + p3;
            int ks = j >> 1;
            if ((j & 1) == 0) { pf[ks][0] = packh2(p0, p1); pf[ks][1] = packh2(p2, p3); }
            else              { pf[ks][2] = packh2(p0, p1); pf[ks][3] = packh2(p2, p3); }
        }
        rs0 += __shfl_xor_sync(0xffffffffu, rs0, 1);
        rs0 += __shfl_xor_sync(0xffffffffu, rs0, 2);
        rs1 += __shfl_xor_sync(0xffffffffu, rs1, 1);
        rs1 += __shfl_xor_sync(0xffffffffu, rs1, 2);
        m0 = nm0; m1 = nm1;
        l0 = l0 * al0 + rs0;
        l1 = l1 * al1 + rs1;

#pragma unroll
        for (int j = 0; j < 16; ++j) {
            oacc[j][0] *= al0; oacc[j][1] *= al0;
            oacc[j][2] *= al1; oacc[j][3] *= al1;
        }

#pragma unroll
        for (int ks = 0; ks < 8; ++ks) {
#pragma unroll
            for (int p = 0; p < 8; ++p) {
                unsigned v0, v1, v2, v3;
                ldsm4t(v0, v1, v2, v3,
                       vbase + 4u * ((ks * 16 + rV) * FPW + p * 8 + cV));
                mma_f16(oacc[2 * p],     pf[ks][0], pf[ks][1], pf[ks][2], pf[ks][3], v0, v1);
                mma_f16(oacc[2 * p + 1], pf[ks][0], pf[ks][1], pf[ks][2], pf[ks][3], v2, v3);
            }
        }

        asm volatile("cp.async.wait_group 0;\n");
        __syncthreads();
    }

    float il0 = 1.f / l0, il1 = 1.f / l1;
    long obase0 = ((long)b * NS + row0 + wq + g) * NHID + n * DHEAD;
    long obase1 = obase0 + 8L * NHID;
#pragma unroll
    for (int j = 0; j < 16; ++j) {
        int col = 8 * j + 2 * tg;
        __half2 h0 = __floats2half2_rn(oacc[j][0] * il0, oacc[j][1] * il0);
        __half2 h1 = __floats2half2_rn(oacc[j][2] * il1, oacc[j][3] * il1);
        *(__half2*)(o + obase0 + col) = h0;
        *(__half2*)(o + obase1 + col) = h1;
    }
}

// ---------------------------------------------------------------------------
// fused weight conversion fp32 -> fp16 (one launch, segment ladder, float4s)
// ---------------------------------------------------------------------------
namespace {
constexpr int W1 = NHID * NHID / 4;
constexpr int WE = NEXP * NMI * NHID / 4;
constexpr int WS = NSI * NHID / 4;
constexpr int CONV_TOT = 4 * W1 + 3 * WE + 3 * WS;
}

__global__ void conv_all_k(
    const float* __restrict__ qw, const float* __restrict__ kw,
    const float* __restrict__ vw, const float* __restrict__ ow,
    const float* __restrict__ eg, const float* __restrict__ eu,
    const float* __restrict__ ed, const float* __restrict__ sg,
    const float* __restrict__ su, const float* __restrict__ sd)
{
    int i = blockIdx.x * 256 + threadIdx.x;
    if (i >= CONV_TOT) return;
    const float* src; __half* dst; int j = i;
    if      (j < 1 * W1) { src = qw; dst = h_qw; }
    else if (j < 2 * W1) { src = kw; dst = h_kw; j -= 1 * W1; }
    else if (j < 3 * W1) { src = vw; dst = h_vw; j -= 2 * W1; }
    else if (j < 4 * W1) { src = ow; dst = h_ow; j -= 3 * W1; }
    else {
        j -= 4 * W1;
        if      (j < 1 * WE) { src = eg; dst = h_eg; }
        else if (j < 2 * WE) { src = eu; dst = h_eu; j -= 1 * WE; }
        else if (j < 3 * WE) { src = ed; dst = h_ed; j -= 2 * WE; }
        else {
            j -= 3 * WE;
            if      (j < 1 * WS) { src = sg; dst = h_sg; }
            else if (j < 2 * WS) { src = su; dst = h_su; j -= 1 * WS; }
            else                 { src = sd; dst = h_sd; j -= 2 * WS; }
        }
    }
    float4 v = *(const float4*)(src + 4 * (long)j);
    __half2 h0 = __floats2half2_rn(v.x, v.y);
    __half2 h1 = __floats2half2_rn(v.z, v.w);
    *(__half2*)(dst + 4 * (long)j)     = h0;
    *(__half2*)(dst + 4 * (long)j + 2) = h1;
}

// ---------------------------------------------------------------------------
// Elementwise / reduction kernels
// ---------------------------------------------------------------------------
__global__ void rmsnorm_k(const float* __restrict__ x,
                          const float* __restrict__ w,
                          __half* __restrict__ oh, float* __restrict__ o32)
{
    int t = blockIdx.x;
    // piggyback: zero expert counters before the (later) gate_k launch
    if (o32 && t == 0 && threadIdx.x < NEXP) d_cnt[threadIdx.x] = 0;
    const float* xr = x + (long)t * NHID;
    __shared__ float red[256];
    float s = 0.f;
    for (int i = threadIdx.x; i < NHID; i += 256) { float v = xr[i]; s += v * v; }
    red[threadIdx.x] = s;
    __syncthreads();
    for (int st = 128; st > 0; st >>= 1) {
        if (threadIdx.x < st) red[threadIdx.x] += red[threadIdx.x + st];
        __syncthreads();
    }
    float scale = rsqrtf(red[0] / (float)NHID + 1e-6f);
    for (int i = threadIdx.x; i < NHID; i += 256) {
        float v = xr[i] * scale * w[i];
        oh[(long)t * NHID + i] = __float2half_rn(v);
        if (o32) o32[(long)t * NHID + i] = v;
    }
}

__global__ void rope_k(const __half* __restrict__ q0, const __half* __restrict__ k0,
                       const float* __restrict__ cosp, const float* __restrict__ sinp,
                       __half* __restrict__ qr, __half* __restrict__ kr)
{
    int t = blockIdx.x;
    int s = t % NS;
    const float inv = 0.08838834764831845f;  // 1/sqrt(128)
    for (int i = threadIdx.x; i < NHEAD * 64; i += 256) {
        int n = i >> 6, d = i & 63;
        long base = (long)t * NHID + n * DHEAD;
        float c  = cosp[s * DHEAD + d];
        float sn = sinp[s * DHEAD + d];
        float a0 = __half2float(q0[base + d]);
        float a1 = __half2float(q0[base + d + 64]);
        qr[base + d]      = __float2half_rn((a0 * c - a1 * sn) * inv);
        qr[base + d + 64] = __float2half_rn((a1 * c + a0 * sn) * inv);
        float b0 = __half2float(k0[base + d]);
        float b1 = __half2float(k0[base + d + 64]);
        kr[base + d]      = __float2half_rn(b0 * c - b1 * sn);
        kr[base + d + 64] = __float2half_rn(b1 * c + b0 * sn);
    }
}

__global__ void gate_k(const float* __restrict__ xn, const float* __restrict__ gw)
{
    int t = blockIdx.x;
    int tid = threadIdx.x, w = tid >> 5, lane = tid & 31;
    const float* xr = xn + (long)t * NHID;
    const float* gr = gw + (long)w * NHID;
    float s = 0.f;
    for (int i = lane; i < NHID; i += 32) s += xr[i] * gr[i];
    for (int o = 16; o; o >>= 1) s += __shfl_xor_sync(0xffffffffu, s, o);
    __shared__ float lg[NEXP];
    if (lane == 0) lg[w] = s;
    __syncthreads();
    if (tid == 0) {
        float mx = lg[0];
        for (int e = 1; e < NEXP; ++e) mx = fmaxf(mx, lg[e]);
        float p[NEXP];
        for (int e = 0; e < NEXP; ++e) p[e] = expf(lg[e] - mx);
        int e0 = 0; float b0 = p[0];
        for (int e = 1; e < NEXP; ++e) if (p[e] > b0) { b0 = p[e]; e0 = e; }
        int e1 = -1; float b1 = -1.f;
        for (int e = 0; e < NEXP; ++e)
            if (e != e0 && p[e] > b1) { b1 = p[e]; e1 = e; }
        float denom = b0 + b1;
        d_e0[t] = e0; d_e1[t] = e1;
        d_w0[t] = b0 / denom; d_w1[t] = b1 / denom;
        d_r0[t] = atomicAdd(&d_cnt[e0], 1);
        d_r1[t] = atomicAdd(&d_cnt[e1], 1);
    }
}

__global__ void scan_k()
{
    if (threadIdx.x == 0) {
        int a = 0;
        for (int e = 0; e < NEXP; ++e) { d_off[e] = a; a += d_cnt[e]; }
    }
}

__global__ void gather_k(const __half* __restrict__ xnh)
{
    int t = blockIdx.x;
    __shared__ int ss[2];
    if (threadIdx.x == 0) {
        int s0 = d_off[d_e0[t]] + d_r0[t];
        int s1 = d_off[d_e1[t]] + d_r1[t];
        d_s0[t] = s0; d_s1[t] = s1;
        ss[0] = s0; ss[1] = s1;
    }
    __syncthreads();
    const uint4* src = (const uint4*)(xnh + (long)t * NHID);
    uint4* dst0 = (uint4*)(h_xg + (long)ss[0] * NHID);
    uint4* dst1 = (uint4*)(h_xg + (long)ss[1] * NHID);
    for (int i = threadIdx.x; i < NHID / 8; i += 256) {
        uint4 v = src[i];
        dst0[i] = v;
        dst1[i] = v;
    }
}

// silu(g)*u, half in / half out, vectorized __half2
__global__ void silumul_k(const __half* __restrict__ g, const __half* __restrict__ u,
                          __half* __restrict__ o, long n2)
{
    long i = (long)blockIdx.x * 256 + threadIdx.x;
    if (i < n2) {
        __half2 gh = ((const __half2*)g)[i];
        __half2 uh = ((const __half2*)u)[i];
        float g0 = __low2float(gh),  g1 = __high2float(gh);
        float u0 = __low2float(uh),  u1 = __high2float(uh);
        float r0 = g0 / (1.f + __expf(-g0)) * u0;
        float r1 = g1 / (1.f + __expf(-g1)) * u1;
        ((__half2*)o)[i] = __floats2half2_rn(r0, r1);
    }
}

// out = x1 + sh + w0*yb[s0] + w1*yb[s1]  (yb half)
__global__ void combine_k(const float* __restrict__ x1,
                          const float* __restrict__ sh,
                          float* __restrict__ out)
{
    int t = blockIdx.x;
    float w0 = d_w0[t], w1 = d_w1[t];
    long o0 = (long)d_s0[t] * NHID;
    long o1 = (long)d_s1[t] * NHID;
    for (int i = threadIdx.x; i < NHID; i += 256) {
        long idx = (long)t * NHID + i;
        out[idx] = x1[idx] + sh[idx]
                 + w0 * __half2float(h_ybuf[o0 + i])
                 + w1 * __half2float(h_ybuf[o1 + i]);
    }
}

// ---------------------------------------------------------------------------
// Launch
// ---------------------------------------------------------------------------
extern "C" void kernel_launch(void* const* d_in, const int* in_sizes, int n_in,
                              void* d_out, int out_size)
{
    (void)in_sizes; (void)n_in; (void)out_size;

    const float* hs   = (const float*)d_in[0];
    const float* ln1  = (const float*)d_in[1];
    const float* ln2  = (const float*)d_in[2];
    const float* q_w  = (const float*)d_in[3];
    const float* k_w  = (const float*)d_in[4];
    const float* v_w  = (const float*)d_in[5];
    const float* o_w  = (const float*)d_in[6];
    const float* cosp = (const float*)d_in[7];
    const float* sinp = (const float*)d_in[8];
    const float* gate = (const float*)d_in[9];
    const float* eg   = (const float*)d_in[10];
    const float* eu   = (const float*)d_in[11];
    const float* ed   = (const float*)d_in[12];
    const float* sg   = (const float*)d_in[13];
    const float* su   = (const float*)d_in[14];
    const float* sd   = (const float*)d_in[15];
    float* out = (float*)d_out;

    float *xn32, *x1, *sh;
    __half *hxn, *hq0, *hk0, *hv0, *hqr, *hkr, *hctx, *hxg;
    __half *hg, *hu, *hgb, *hgs32, *hus32, *hgs, *how2, *hsd2;
    cudaGetSymbolAddress((void**)&xn32, d_xn32);
    cudaGetSymbolAddress((void**)&x1,  d_x1);
    cudaGetSymbolAddress((void**)&sh,  d_sh);
    cudaGetSymbolAddress((void**)&hxn, h_xn);
    cudaGetSymbolAddress((void**)&hq0, h_q0);
    cudaGetSymbolAddress((void**)&hk0, h_k0);
    cudaGetSymbolAddress((void**)&hv0, h_v0);
    cudaGetSymbolAddress((void**)&hqr, h_qr);
    cudaGetSymbolAddress((void**)&hkr, h_kr);
    cudaGetSymbolAddress((void**)&hctx, h_ctx);
    cudaGetSymbolAddress((void**)&hxg, h_xg);
    cudaGetSymbolAddress((void**)&hg,  h_gbuf);
    cudaGetSymbolAddress((void**)&hu,  h_ubuf);
    cudaGetSymbolAddress((void**)&hgb, h_gb);
    cudaGetSymbolAddress((void**)&hgs32, h_gs32);
    cudaGetSymbolAddress((void**)&hus32, h_us32);
    cudaGetSymbolAddress((void**)&hgs, h_gs);
    cudaGetSymbolAddress((void**)&how2, h_ow);
    cudaGetSymbolAddress((void**)&hsd2, h_sd);

    cudaFuncSetAttribute(hgemm_bat,
        cudaFuncAttributeMaxDynamicSharedMemorySize, SMEM_BYTES);
    cudaFuncSetAttribute(hqkv_k,
        cudaFuncAttributeMaxDynamicSharedMemorySize, SMEM_BYTES);
    cudaFuncSetAttribute(hshup_k,
        cudaFuncAttributeMaxDynamicSharedMemorySize, SMEM_BYTES);
    cudaFuncSetAttribute(hmoeup_k,
        cudaFuncAttributeMaxDynamicSharedMemorySize, SMEM_BYTES);
    cudaFuncSetAttribute(hmoedn_k,
        cudaFuncAttributeMaxDynamicSharedMemorySize, SMEM_BYTES);
    cudaFuncSetAttribute(flash_k,
        cudaFuncAttributeMaxDynamicSharedMemorySize, FLASH_SMEM);

    // ---- all weight conversions in one launch ----
    conv_all_k<<<(CONV_TOT + 255) / 256, 256>>>(q_w, k_w, v_w, o_w,
                                                eg, eu, ed, sg, su, sd);

    const dim3 gQKV(NHID / BN, NT / BM, 3);
    const dim3 gFlash(NS / 128, NB * NHEAD);
    const dim3 gProj(NHID / BN, NT / BM);
    const dim3 gShUp(NSI / BN, NT / BM, 2);
    const dim3 gMoeUp(NMI / BN, NSLOT / BM, 2 * NEXP);
    const dim3 gMoeDn(NHID / BN, NSLOT / BM, NEXP);

    // ---- attention ----
    rmsnorm_k<<<NT, 256>>>(hs, ln1, hxn, nullptr);
    hqkv_k<<<gQKV, 256, SMEM_BYTES>>>(hxn);
    rope_k<<<NT, 256>>>(hq0, hk0, cosp, sinp, hqr, hkr);
    flash_k<<<gFlash, 256, FLASH_SMEM>>>(hqr, hkr, hv0, hctx);
    hgemm_bat<<<gProj, 256, SMEM_BYTES>>>(hctx, how2, x1, hs,
        NT, NHID, NHID, NHID, NHID, 0, 0, 0);

    // ---- MoE ----
    rmsnorm_k<<<NT, 256>>>(x1, ln2, hxn, xn32);   // also zeroes d_cnt
    gate_k<<<NT, 256>>>(xn32, gate);
    scan_k<<<1, 1>>>();
    gather_k<<<NT, 256>>>(hxn);

    hmoeup_k<<<gMoeUp, 256, SMEM_BYTES>>>(hxg);
    silumul_k<<<(unsigned)(((long)NSLOT * NMI / 2 + 255) / 256), 256>>>(
        hg, hu, hgb, (long)NSLOT * NMI / 2);
    hmoedn_k<<<gMoeDn, 256, SMEM_BYTES>>>(hgb);

    // ---- shared MLP ----
    hshup_k<<<gShUp, 256, SMEM_BYTES>>>(hxn);
    silumul_k<<<(unsigned)(((long)NT * NSI / 2 + 255) / 256), 256>>>(
        hgs32, hus32, hgs, (long)NT * NSI / 2);
    hgemm_bat<<<gProj, 256, SMEM_BYTES>>>(hgs, hsd2, sh, nullptr,
        NT, NSI, NSI, NSI, NHID, 0, 0, 0);

    // ---- combine ----
    combine_k<<<NT, 256>>>(x1, sh, out);
}

// round 13
// speedup vs baseline: 1.1212x; 1.1212x over previous
#include <cuda_runtime.h>
#include <cuda_fp16.h>
#include <math.h>

// ---------------------------------------------------------------------------
// Problem constants
// ---------------------------------------------------------------------------
namespace {
constexpr int NB = 2, NS = 1024, NHID = 1024, NHEAD = 8, DHEAD = 128;
constexpr int NEXP = 8, NMI = 1024, NSI = 2048;
constexpr int NT = NB * NS;          // 2048 tokens
constexpr int NSLOT = 2 * NT;        // 4096 expert slots (top-2)

// fp16 GEMM tile: 128x128x32(halves), 8 warps of 64x32, 4-stage cp.async
constexpr int BM = 128, BN = 128, BKH = 32;
constexpr int PAD32 = 20;                        // row stride in b32 (80B)
constexpr int STAGES = 4;
constexpr int STAGE_WORDS = BM * PAD32;          // 2560 b32 per tile-stage
constexpr int SMEM_BYTES = 2 * STAGES * STAGE_WORDS * 4;   // 81920

// flash attention smem: Q + 2xK + 2xV tiles of 128 rows x 68 words
constexpr int FPW = 68;                          // words per row (136 halves)
constexpr int FTILE_W = 128 * FPW;               // 8704 words per tile
constexpr int FLASH_SMEM = 5 * FTILE_W * 4;      // 174080 bytes
}

// ---------------------------------------------------------------------------
// Static device scratch (no allocations allowed)
// ---------------------------------------------------------------------------
// fp32 buffers
__device__ float d_xn32[NT * NHID];
__device__ float d_x1[NT * NHID];
// fp16 weights
__device__ __half h_qw[NHID * NHID];
__device__ __half h_kw[NHID * NHID];
__device__ __half h_vw[NHID * NHID];
__device__ __half h_ow[NHID * NHID];
__device__ __half h_eg[NEXP * NMI * NHID];
__device__ __half h_eu[NEXP * NMI * NHID];
__device__ __half h_ed[NEXP * NHID * NMI];
__device__ __half h_sg[NSI * NHID];
__device__ __half h_su[NSI * NHID];
__device__ __half h_sd[NHID * NSI];
// fp16 activations
__device__ __half h_xn[NT * NHID];
__device__ __half h_q0[NT * NHID];    // QKV GEMM outputs, (t, head*128+d)
__device__ __half h_k0[NT * NHID];
__device__ __half h_v0[NT * NHID];
__device__ __half h_qr[NT * NHID];    // rope'd + scaled
__device__ __half h_kr[NT * NHID];
__device__ __half h_ctx[NT * NHID];   // flash output
__device__ __half h_xg[NSLOT * NHID];
__device__ __half h_gbuf[NSLOT * NMI];   // MoE gate GEMM out (half)
__device__ __half h_ubuf[NSLOT * NMI];   // MoE up GEMM out (half)
__device__ __half h_gb[NSLOT * NMI];     // silu(g)*u (half)
__device__ __half h_ybuf[NSLOT * NHID];  // MoE down out (half)
__device__ __half h_gs32[NT * NSI];      // shared gate GEMM out (half)
__device__ __half h_us32[NT * NSI];      // shared up GEMM out (half)
__device__ __half h_gs[NT * NSI];        // silu(g)*u (half)
// routing state
__device__ int   d_cnt[NEXP];
__device__ int   d_off[NEXP];
__device__ int   d_e0[NT], d_e1[NT], d_r0[NT], d_r1[NT], d_s0[NT], d_s1[NT];
__device__ float d_w0[NT], d_w1[NT];

// ---------------------------------------------------------------------------
// helpers
// ---------------------------------------------------------------------------
__device__ __forceinline__ unsigned smem_u32(const void* p) {
    return (unsigned)__cvta_generic_to_shared(p);
}

__device__ __forceinline__ void cp16(unsigned dst, const void* src, bool pred) {
    int sz = pred ? 16 : 0;
    asm volatile("cp.async.cg.shared.global [%0], [%1], 16, %2;\n"
                 :: "r"(dst), "l"(src), "r"(sz));
}

__device__ __forceinline__ void ldsm4(unsigned& r0, unsigned& r1,
                                      unsigned& r2, unsigned& r3, unsigned addr)
{
    asm volatile("ldmatrix.sync.aligned.m8n8.x4.shared.b16 {%0,%1,%2,%3}, [%4];"
                 : "=r"(r0), "=r"(r1), "=r"(r2), "=r"(r3) : "r"(addr));
}

__device__ __forceinline__ void ldsm4t(unsigned& r0, unsigned& r1,
                                       unsigned& r2, unsigned& r3, unsigned addr)
{
    asm volatile("ldmatrix.sync.aligned.m8n8.x4.trans.shared.b16 {%0,%1,%2,%3}, [%4];"
                 : "=r"(r0), "=r"(r1), "=r"(r2), "=r"(r3) : "r"(addr));
}

__device__ __forceinline__ void mma_f16(float c[4],
    unsigned a0, unsigned a1, unsigned a2, unsigned a3,
    unsigned b0, unsigned b1)
{
    asm volatile(
        "mma.sync.aligned.m16n8k16.row.col.f32.f16.f16.f32 "
        "{%0,%1,%2,%3}, {%4,%5,%6,%7}, {%8,%9}, {%0,%1,%2,%3};\n"
        : "+f"(c[0]), "+f"(c[1]), "+f"(c[2]), "+f"(c[3])
        : "r"(a0), "r"(a1), "r"(a2), "r"(a3), "r"(b0), "r"(b1));
}

__device__ __forceinline__ unsigned packh2(float a, float b) {
    __half2 h = __floats2half2_rn(a, b);
    return *reinterpret_cast<unsigned*>(&h);
}

// ---------------------------------------------------------------------------
// FP16 tensor-core GEMM:  C[M,N] = A[M,K] * B^T  (B stored (N,K) row-major,
// offsets in HALVES).  128x128 block, 8 warps of 64x32 (4x4 m16n8k16),
// 4-stage cp.async, ldmatrix operand loads.  OutT = float or __half.
// FINAL: fuse the MoE combine — out = resid + gemm + w0*yb[s0] + w1*yb[s1].
// ---------------------------------------------------------------------------
template <typename OutT, bool FINAL>
__device__ __forceinline__ void hgemm_body(
    const __half* __restrict__ A, const __half* __restrict__ Bm,
    OutT* __restrict__ C, const float* __restrict__ resid,
    int M, int K, int lda, int ldb, int ldc)
{
    extern __shared__ unsigned smu[];
    unsigned* Asm = smu;                         // [STAGES][BM][PAD32]
    unsigned* Bsm = smu + STAGES * STAGE_WORDS;

    const int tid  = threadIdx.x;
    const int wid  = tid >> 5;
    const int lane = tid & 31;
    const int g    = lane >> 2;
    const int tg   = lane & 3;
    const int wm   = (wid & 1) * 64;
    const int wn   = (wid >> 1) * 32;
    const int row0 = blockIdx.y * BM;
    const int col0 = blockIdx.x * BN;
    if (row0 >= M) return;

    const int rA = (lane & 7) + ((lane >> 3) & 1) * 8;
    const int cA = ((lane >> 4) & 1) * 4;
    const int rB = (lane & 7) + ((lane >> 4) & 1) * 8;
    const int cB = ((lane >> 3) & 1) * 4;

    float c[4][4][4];
#pragma unroll
    for (int mi = 0; mi < 4; ++mi)
#pragma unroll
        for (int ni = 0; ni < 4; ++ni)
#pragma unroll
            for (int r = 0; r < 4; ++r) c[mi][ni][r] = 0.f;

    const int lr = tid >> 1;
    const int lqh = (tid & 1) * 16;
    const int lqw = (tid & 1) * 8;
    const int niter = K / BKH;

#pragma unroll
    for (int st = 0; st < STAGES - 1; ++st) {
        if (st < niter) {
            const int k0 = st * BKH;
            const __half* ga = A + (long)(row0 + lr) * lda + k0 + lqh;
            unsigned da = smem_u32(Asm + st * STAGE_WORDS + lr * PAD32 + lqw);
            bool pa = (row0 + lr) < M;
            cp16(da,      ga,     pa);
            cp16(da + 16, ga + 8, pa);
            const __half* gb = Bm + (long)(col0 + lr) * ldb + k0 + lqh;
            unsigned db = smem_u32(Bsm + st * STAGE_WORDS + lr * PAD32 + lqw);
            cp16(db,      gb,     true);
            cp16(db + 16, gb + 8, true);
        }
        asm volatile("cp.async.commit_group;\n");
    }

    int s = 0;
    for (int it = 0; it < niter; ++it) {
        asm volatile("cp.async.wait_group 2;\n");
        __syncthreads();

        const int pf = it + STAGES - 1;
        if (pf < niter) {
            int sl = s + STAGES - 1; if (sl >= STAGES) sl -= STAGES;
            const int k0 = pf * BKH;
            const __half* ga = A + (long)(row0 + lr) * lda + k0 + lqh;
            unsigned da = smem_u32(Asm + sl * STAGE_WORDS + lr * PAD32 + lqw);
            bool pa = (row0 + lr) < M;
            cp16(da,      ga,     pa);
            cp16(da + 16, ga + 8, pa);
            const __half* gb = Bm + (long)(col0 + lr) * ldb + k0 + lqh;
            unsigned db = smem_u32(Bsm + sl * STAGE_WORDS + lr * PAD32 + lqw);
            cp16(db,      gb,     true);
            cp16(db + 16, gb + 8, true);
        }
        asm volatile("cp.async.commit_group;\n");

        const unsigned a_base = smem_u32(Asm + s * STAGE_WORDS);
        const unsigned b_base = smem_u32(Bsm + s * STAGE_WORDS);
#pragma unroll
        for (int kk = 0; kk < 2; ++kk) {
            const int kb = kk * 8;
            unsigned af[4][4], bf[4][2];
#pragma unroll
            for (int mi = 0; mi < 4; ++mi) {
                unsigned addr = a_base +
                    4u * ((wm + mi * 16 + rA) * PAD32 + kb + cA);
                ldsm4(af[mi][0], af[mi][1], af[mi][2], af[mi][3], addr);
            }
#pragma unroll
            for (int p = 0; p < 2; ++p) {
                unsigned addr = b_base +
                    4u * ((wn + p * 16 + rB) * PAD32 + kb + cB);
                ldsm4(bf[2 * p][0], bf[2 * p][1],
                      bf[2 * p + 1][0], bf[2 * p + 1][1], addr);
            }
#pragma unroll
            for (int mi = 0; mi < 4; ++mi)
#pragma unroll
                for (int ni = 0; ni < 4; ++ni)
                    mma_f16(c[mi][ni], af[mi][0], af[mi][1], af[mi][2], af[mi][3],
                            bf[ni][0], bf[ni][1]);
        }
        if (++s >= STAGES) s = 0;
    }

    // ---- epilogue ----
#pragma unroll
    for (int mi = 0; mi < 4; ++mi) {
#pragma unroll
        for (int half = 0; half < 2; ++half) {
            int r = row0 + wm + mi * 16 + g + half * 8;
            if (r < M) {
                float w0 = 0.f, w1 = 0.f;
                long y0 = 0, y1 = 0;
                if (FINAL) {
                    w0 = d_w0[r]; w1 = d_w1[r];
                    y0 = (long)d_s0[r] * NHID;
                    y1 = (long)d_s1[r] * NHID;
                }
#pragma unroll
                for (int ni = 0; ni < 4; ++ni) {
                    int colg = col0 + wn + ni * 8 + tg * 2;
                    long off = (long)r * ldc + colg;
                    float vx = c[mi][ni][half * 2 + 0];
                    float vy = c[mi][ni][half * 2 + 1];
                    if (resid) {
                        float2 rr = *(const float2*)(resid + off);
                        vx += rr.x; vy += rr.y;
                    }
                    if (FINAL) {
                        __half2 a0 = *(const __half2*)(h_ybuf + y0 + colg);
                        __half2 a1 = *(const __half2*)(h_ybuf + y1 + colg);
                        vx += w0 * __low2float(a0)  + w1 * __low2float(a1);
                        vy += w0 * __high2float(a0) + w1 * __high2float(a1);
                    }
                    if constexpr (sizeof(OutT) == 4) {
                        float2 v; v.x = vx; v.y = vy;
                        *(float2*)((float*)C + off) = v;
                    } else {
                        __half2 hv = __floats2half2_rn(vx, vy);
                        *(__half2*)((__half*)C + off) = hv;
                    }
                }
            }
        }
    }
}

// ---- O-proj (float out, residual)
__global__ __launch_bounds__(256, 2)
void hoproj_k(const __half* __restrict__ A, float* __restrict__ C,
              const float* __restrict__ resid)
{
    hgemm_body<float, false>(A, h_ow, C, resid, NT, NHID, NHID, NHID, NHID);
}

// ---- FINAL shared-down GEMM: writes out = x1 + shdown + routed
__global__ __launch_bounds__(256, 2)
void hfinal_k(const __half* __restrict__ A, float* __restrict__ C,
              const float* __restrict__ resid)
{
    hgemm_body<float, true>(A, h_sd, C, resid, NT, NSI, NSI, NSI, NHID);
}

// ---- fused Q/K/V projection (half out)
__global__ __launch_bounds__(256, 2)
void hqkv_k(const __half* __restrict__ xn)
{
    int z = blockIdx.z;
    const __half* B = (z == 0) ? h_qw : (z == 1) ? h_kw : h_vw;
    __half* C       = (z == 0) ? h_q0 : (z == 1) ? h_k0 : h_v0;
    hgemm_body<__half, false>(xn, B, C, nullptr, NT, NHID, NHID, NHID, NHID);
}

// ---- fused shared-MLP gate+up (half out)
__global__ __launch_bounds__(256, 2)
void hshup_k(const __half* __restrict__ xn)
{
    int z = blockIdx.z;
    hgemm_body<__half, false>(xn, z ? h_su : h_sg, z ? h_us32 : h_gs32, nullptr,
                              NT, NHID, NHID, NHID, NSI);
}

// ---- fused MoE gate+up grouped (half out): z = 2*e + which
__global__ __launch_bounds__(256, 2)
void hmoeup_k(const __half* __restrict__ xg)
{
    int z = blockIdx.z;
    int e = z >> 1;
    int M = d_cnt[e];
    int off = d_off[e];
    const __half* B = (z & 1) ? h_eu : h_eg;
    __half* C       = (z & 1) ? h_ubuf : h_gbuf;
    hgemm_body<__half, false>(xg + (long)off * NHID, B + (long)e * NMI * NHID,
                              C + (long)off * NMI, nullptr, M, NHID, NHID, NHID, NMI);
}

// ---- MoE down grouped (half out)
__global__ __launch_bounds__(256, 2)
void hmoedn_k(const __half* __restrict__ gb)
{
    int e = blockIdx.z;
    int M = d_cnt[e];
    int off = d_off[e];
    hgemm_body<__half, false>(gb + (long)off * NMI, h_ed + (long)e * NHID * NMI,
                              h_ybuf + (long)off * NHID, nullptr, M, NMI, NMI, NMI, NHID);
}

// ---------------------------------------------------------------------------
// Flash attention (r8, unchanged): one CTA per (q-tile 128, head).
// ---------------------------------------------------------------------------
__global__ __launch_bounds__(256, 1)
void flash_k(const __half* __restrict__ q, const __half* __restrict__ k,
             const __half* __restrict__ v, __half* __restrict__ o)
{
    extern __shared__ unsigned fsm[];
    unsigned* Qs = fsm;
    unsigned* Ks = fsm + FTILE_W;
    unsigned* Vs = fsm + 3 * FTILE_W;

    const int qi  = blockIdx.x;
    const int bh  = blockIdx.y;
    const int b   = bh >> 3, n = bh & 7;
    const int tid = threadIdx.x, wid = tid >> 5, lane = tid & 31;
    const int g   = lane >> 2, tg = lane & 3;
    const int wq  = wid * 16;
    const int row0 = qi * 128;

    const long qbase  = ((long)b * NS + row0) * NHID + n * DHEAD;
    const long kvbase = ((long)b * NS) * NHID + n * DHEAD;

    const int rA = (lane & 7) + ((lane >> 3) & 1) * 8;
    const int cA = ((lane >> 4) & 1) * 4;
    const int rB = (lane & 7) + ((lane >> 4) & 1) * 8;
    const int cB = ((lane >> 3) & 1) * 4;
    const int rV = lane & 15;
    const int cV = (lane >> 4) * 4;

    {
        int r = tid >> 1, hh = tid & 1;
        const __half* gq = q + qbase + (long)r * NHID + hh * 64;
        unsigned dq = smem_u32(Qs + r * FPW + hh * 32);
#pragma unroll
        for (int c2 = 0; c2 < 8; ++c2) cp16(dq + c2 * 16, gq + c2 * 8, true);
    }
    {
        int r = tid >> 1, hh = tid & 1;
        const __half* gk = k + kvbase + (long)r * NHID + hh * 64;
        const __half* gv = v + kvbase + (long)r * NHID + hh * 64;
        unsigned dk = smem_u32(Ks + r * FPW + hh * 32);
        unsigned dv = smem_u32(Vs + r * FPW + hh * 32);
#pragma unroll
        for (int c2 = 0; c2 < 8; ++c2) {
            cp16(dk + c2 * 16, gk + c2 * 8, true);
            cp16(dv + c2 * 16, gv + c2 * 8, true);
        }
    }
    asm volatile("cp.async.commit_group;\n");
    asm volatile("cp.async.wait_group 0;\n");
    __syncthreads();

    float oacc[16][4];
#pragma unroll
    for (int j = 0; j < 16; ++j)
#pragma unroll
        for (int r = 0; r < 4; ++r) oacc[j][r] = 0.f;
    float m0 = -1e30f, m1 = -1e30f, l0 = 0.f, l1 = 0.f;

    for (int t = 0; t <= qi; ++t) {
        const int cur = t & 1;
        if (t + 1 <= qi) {
            int nxt = (t + 1) & 1;
            int r = tid >> 1, hh = tid & 1;
            const __half* gk = k + kvbase + ((long)(t + 1) * 128 + r) * NHID + hh * 64;
            const __half* gv = v + kvbase + ((long)(t + 1) * 128 + r) * NHID + hh * 64;
            unsigned dk = smem_u32(Ks + nxt * FTILE_W + r * FPW + hh * 32);
            unsigned dv = smem_u32(Vs + nxt * FTILE_W + r * FPW + hh * 32);
#pragma unroll
            for (int c2 = 0; c2 < 8; ++c2) {
                cp16(dk + c2 * 16, gk + c2 * 8, true);
                cp16(dv + c2 * 16, gv + c2 * 8, true);
            }
        }
        asm volatile("cp.async.commit_group;\n");

        const unsigned kbase = smem_u32(Ks + cur * FTILE_W);
        const unsigned vbase = smem_u32(Vs + cur * FTILE_W);
        const unsigned qbse  = smem_u32(Qs);

        float sacc[16][4];
#pragma unroll
        for (int j = 0; j < 16; ++j)
#pragma unroll
            for (int r = 0; r < 4; ++r) sacc[j][r] = 0.f;

#pragma unroll
        for (int ks = 0; ks < 8; ++ks) {
            unsigned qa[4];
            ldsm4(qa[0], qa[1], qa[2], qa[3],
                  qbse + 4u * ((wq + rA) * FPW + ks * 8 + cA));
#pragma unroll
            for (int p = 0; p < 8; ++p) {
                unsigned b0, b1, b2, b3;
                ldsm4(b0, b1, b2, b3,
                      kbase + 4u * ((p * 16 + rB) * FPW + ks * 8 + cB));
                mma_f16(sacc[2 * p],     qa[0], qa[1], qa[2], qa[3], b0, b1);
                mma_f16(sacc[2 * p + 1], qa[0], qa[1], qa[2], qa[3], b2, b3);
            }
        }

        if (t == qi) {
            int r0l = wq + g, r1l = wq + g + 8;
#pragma unroll
            for (int j = 0; j < 16; ++j) {
                int col = 8 * j + 2 * tg;
                if (col     > r0l) sacc[j][0] = -1e30f;
                if (col + 1 > r0l) sacc[j][1] = -1e30f;
                if (col     > r1l) sacc[j][2] = -1e30f;
                if (col + 1 > r1l) sacc[j][3] = -1e30f;
            }
        }

        float tm0 = -1e30f, tm1 = -1e30f;
#pragma unroll
        for (int j = 0; j < 16; ++j) {
            tm0 = fmaxf(tm0, fmaxf(sacc[j][0], sacc[j][1]));
            tm1 = fmaxf(tm1, fmaxf(sacc[j][2], sacc[j][3]));
        }
        tm0 = fmaxf(tm0, __shfl_xor_sync(0xffffffffu, tm0, 1));
        tm0 = fmaxf(tm0, __shfl_xor_sync(0xffffffffu, tm0, 2));
        tm1 = fmaxf(tm1, __shfl_xor_sync(0xffffffffu, tm1, 1));
        tm1 = fmaxf(tm1, __shfl_xor_sync(0xffffffffu, tm1, 2));
        float nm0 = fmaxf(m0, tm0), nm1 = fmaxf(m1, tm1);
        float al0 = __expf(m0 - nm0), al1 = __expf(m1 - nm1);

        float rs0 = 0.f, rs1 = 0.f;
        unsigned pf[8][4];
#pragma unroll
        for (int j = 0; j < 16; ++j) {
            float p0 = __expf(sacc[j][0] - nm0);
            float p1 = __expf(sacc[j][1] - nm0);
            float p2 = __expf(sacc[j][2] - nm1);
            float p3 = __expf(sacc[j][3] - nm1);
            rs0 += p0 + p1; rs1 += p2 + p3;
            int ks = j >> 1;
            if ((j & 1) == 0) { pf[ks][0] = packh2(p0, p1); pf[ks][1] = packh2(p2, p3); }
            else              { pf[ks][2] = packh2(p0, p1); pf[ks][3] = packh2(p2, p3); }
        }
        rs0 += __shfl_xor_sync(0xffffffffu, rs0, 1);
        rs0 += __shfl_xor_sync(0xffffffffu, rs0, 2);
        rs1 += __shfl_xor_sync(0xffffffffu, rs1, 1);
        rs1 += __shfl_xor_sync(0xffffffffu, rs1, 2);
        m0 = nm0; m1 = nm1;
        l0 = l0 * al0 + rs0;
        l1 = l1 * al1 + rs1;

#pragma unroll
        for (int j = 0; j < 16; ++j) {
            oacc[j][0] *= al0; oacc[j][1] *= al0;
            oacc[j][2] *= al1; oacc[j][3] *= al1;
        }

#pragma unroll
        for (int ks = 0; ks < 8; ++ks) {
#pragma unroll
            for (int p = 0; p < 8; ++p) {
                unsigned v0, v1, v2, v3;
                ldsm4t(v0, v1, v2, v3,
                       vbase + 4u * ((ks * 16 + rV) * FPW + p * 8 + cV));
                mma_f16(oacc[2 * p],     pf[ks][0], pf[ks][1], pf[ks][2], pf[ks][3], v0, v1);
                mma_f16(oacc[2 * p + 1], pf[ks][0], pf[ks][1], pf[ks][2], pf[ks][3], v2, v3);
            }
        }

        asm volatile("cp.async.wait_group 0;\n");
        __syncthreads();
    }

    float il0 = 1.f / l0, il1 = 1.f / l1;
    long obase0 = ((long)b * NS + row0 + wq + g) * NHID + n * DHEAD;
    long obase1 = obase0 + 8L * NHID;
#pragma unroll
    for (int j = 0; j < 16; ++j) {
        int col = 8 * j + 2 * tg;
        __half2 h0 = __floats2half2_rn(oacc[j][0] * il0, oacc[j][1] * il0);
        __half2 h1 = __floats2half2_rn(oacc[j][2] * il1, oacc[j][3] * il1);
        *(__half2*)(o + obase0 + col) = h0;
        *(__half2*)(o + obase1 + col) = h1;
    }
}

// ---------------------------------------------------------------------------
// fused weight conversion fp32 -> fp16 (one launch, segment ladder, float4s)
// ---------------------------------------------------------------------------
namespace {
constexpr int W1 = NHID * NHID / 4;
constexpr int WE = NEXP * NMI * NHID / 4;
constexpr int WS = NSI * NHID / 4;
constexpr int CONV_TOT = 4 * W1 + 3 * WE + 3 * WS;
}

__global__ void conv_all_k(
    const float* __restrict__ qw, const float* __restrict__ kw,
    const float* __restrict__ vw, const float* __restrict__ ow,
    const float* __restrict__ eg, const float* __restrict__ eu,
    const float* __restrict__ ed, const float* __restrict__ sg,
    const float* __restrict__ su, const float* __restrict__ sd)
{
    int i = blockIdx.x * 256 + threadIdx.x;
    if (i >= CONV_TOT) return;
    const float* src; __half* dst; int j = i;
    if      (j < 1 * W1) { src = qw; dst = h_qw; }
    else if (j < 2 * W1) { src = kw; dst = h_kw; j -= 1 * W1; }
    else if (j < 3 * W1) { src = vw; dst = h_vw; j -= 2 * W1; }
    else if (j < 4 * W1) { src = ow; dst = h_ow; j -= 3 * W1; }
    else {
        j -= 4 * W1;
        if      (j < 1 * WE) { src = eg; dst = h_eg; }
        else if (j < 2 * WE) { src = eu; dst = h_eu; j -= 1 * WE; }
        else if (j < 3 * WE) { src = ed; dst = h_ed; j -= 2 * WE; }
        else {
            j -= 3 * WE;
            if      (j < 1 * WS) { src = sg; dst = h_sg; }
            else if (j < 2 * WS) { src = su; dst = h_su; j -= 1 * WS; }
            else                 { src = sd; dst = h_sd; j -= 2 * WS; }
        }
    }
    float4 v = *(const float4*)(src + 4 * (long)j);
    __half2 h0 = __floats2half2_rn(v.x, v.y);
    __half2 h1 = __floats2half2_rn(v.z, v.w);
    *(__half2*)(dst + 4 * (long)j)     = h0;
    *(__half2*)(dst + 4 * (long)j + 2) = h1;
}

// ---------------------------------------------------------------------------
// Elementwise / reduction kernels
// ---------------------------------------------------------------------------
__global__ void rmsnorm_k(const float* __restrict__ x,
                          const float* __restrict__ w,
                          __half* __restrict__ oh, float* __restrict__ o32)
{
    int t = blockIdx.x;
    // piggyback: zero expert counters before the (later) gate_k launch
    if (o32 && t == 0 && threadIdx.x < NEXP) d_cnt[threadIdx.x] = 0;
    const float* xr = x + (long)t * NHID;
    __shared__ float red[256];
    float s = 0.f;
    for (int i = threadIdx.x; i < NHID; i += 256) { float v = xr[i]; s += v * v; }
    red[threadIdx.x] = s;
    __syncthreads();
    for (int st = 128; st > 0; st >>= 1) {
        if (threadIdx.x < st) red[threadIdx.x] += red[threadIdx.x + st];
        __syncthreads();
    }
    float scale = rsqrtf(red[0] / (float)NHID + 1e-6f);
    for (int i = threadIdx.x; i < NHID; i += 256) {
        float v = xr[i] * scale * w[i];
        oh[(long)t * NHID + i] = __float2half_rn(v);
        if (o32) o32[(long)t * NHID + i] = v;
    }
}

__global__ void rope_k(const __half* __restrict__ q0, const __half* __restrict__ k0,
                       const float* __restrict__ cosp, const float* __restrict__ sinp,
                       __half* __restrict__ qr, __half* __restrict__ kr)
{
    int t = blockIdx.x;
    int s = t % NS;
    const float inv = 0.08838834764831845f;  // 1/sqrt(128)
    for (int i = threadIdx.x; i < NHEAD * 64; i += 256) {
        int n = i >> 6, d = i & 63;
        long base = (long)t * NHID + n * DHEAD;
        float c  = cosp[s * DHEAD + d];
        float sn = sinp[s * DHEAD + d];
        float a0 = __half2float(q0[base + d]);
        float a1 = __half2float(q0[base + d + 64]);
        qr[base + d]      = __float2half_rn((a0 * c - a1 * sn) * inv);
        qr[base + d + 64] = __float2half_rn((a1 * c + a0 * sn) * inv);
        float b0 = __half2float(k0[base + d]);
        float b1 = __half2float(k0[base + d + 64]);
        kr[base + d]      = __float2half_rn(b0 * c - b1 * sn);
        kr[base + d + 64] = __float2half_rn(b1 * c + b0 * sn);
    }
}

__global__ void gate_k(const float* __restrict__ xn, const float* __restrict__ gw)
{
    int t = blockIdx.x;
    int tid = threadIdx.x, w = tid >> 5, lane = tid & 31;
    const float* xr = xn + (long)t * NHID;
    const float* gr = gw + (long)w * NHID;
    float s = 0.f;
    for (int i = lane; i < NHID; i += 32) s += xr[i] * gr[i];
    for (int o = 16; o; o >>= 1) s += __shfl_xor_sync(0xffffffffu, s, o);
    __shared__ float lg[NEXP];
    if (lane == 0) lg[w] = s;
    __syncthreads();
    if (tid == 0) {
        float mx = lg[0];
        for (int e = 1; e < NEXP; ++e) mx = fmaxf(mx, lg[e]);
        float p[NEXP];
        for (int e = 0; e < NEXP; ++e) p[e] = expf(lg[e] - mx);
        int e0 = 0; float b0 = p[0];
        for (int e = 1; e < NEXP; ++e) if (p[e] > b0) { b0 = p[e]; e0 = e; }
        int e1 = -1; float b1 = -1.f;
        for (int e = 0; e < NEXP; ++e)
            if (e != e0 && p[e] > b1) { b1 = p[e]; e1 = e; }
        float denom = b0 + b1;
        d_e0[t] = e0; d_e1[t] = e1;
        d_w0[t] = b0 / denom; d_w1[t] = b1 / denom;
        d_r0[t] = atomicAdd(&d_cnt[e0], 1);
        d_r1[t] = atomicAdd(&d_cnt[e1], 1);
    }
}

__global__ void scan_k()
{
    if (threadIdx.x == 0) {
        int a = 0;
        for (int e = 0; e < NEXP; ++e) { d_off[e] = a; a += d_cnt[e]; }
    }
}

__global__ void gather_k(const __half* __restrict__ xnh)
{
    int t = blockIdx.x;
    __shared__ int ss[2];
    if (threadIdx.x == 0) {
        int s0 = d_off[d_e0[t]] + d_r0[t];
        int s1 = d_off[d_e1[t]] + d_r1[t];
        d_s0[t] = s0; d_s1[t] = s1;
        ss[0] = s0; ss[1] = s1;
    }
    __syncthreads();
    const uint4* src = (const uint4*)(xnh + (long)t * NHID);
    uint4* dst0 = (uint4*)(h_xg + (long)ss[0] * NHID);
    uint4* dst1 = (uint4*)(h_xg + (long)ss[1] * NHID);
    for (int i = threadIdx.x; i < NHID / 8; i += 256) {
        uint4 v = src[i];
        dst0[i] = v;
        dst1[i] = v;
    }
}

// silu(g)*u, half in / half out, vectorized __half2
__global__ void silumul_k(const __half* __restrict__ g, const __half* __restrict__ u,
                          __half* __restrict__ o, long n2)
{
    long i = (long)blockIdx.x * 256 + threadIdx.x;
    if (i < n2) {
        __half2 gh = ((const __half2*)g)[i];
        __half2 uh = ((const __half2*)u)[i];
        float g0 = __low2float(gh),  g1 = __high2float(gh);
        float u0 = __low2float(uh),  u1 = __high2float(uh);
        float r0 = g0 / (1.f + __expf(-g0)) * u0;
        float r1 = g1 / (1.f + __expf(-g1)) * u1;
        ((__half2*)o)[i] = __floats2half2_rn(r0, r1);
    }
}

// ---------------------------------------------------------------------------
// Launch
// ---------------------------------------------------------------------------
extern "C" void kernel_launch(void* const* d_in, const int* in_sizes, int n_in,
                              void* d_out, int out_size)
{
    (void)in_sizes; (void)n_in; (void)out_size;

    const float* hs   = (const float*)d_in[0];
    const float* ln1  = (const float*)d_in[1];
    const float* ln2  = (const float*)d_in[2];
    const float* q_w  = (const float*)d_in[3];
    const float* k_w  = (const float*)d_in[4];
    const float* v_w  = (const float*)d_in[5];
    const float* o_w  = (const float*)d_in[6];
    const float* cosp = (const float*)d_in[7];
    const float* sinp = (const float*)d_in[8];
    const float* gate = (const float*)d_in[9];
    const float* eg   = (const float*)d_in[10];
    const float* eu   = (const float*)d_in[11];
    const float* ed   = (const float*)d_in[12];
    const float* sg   = (const float*)d_in[13];
    const float* su   = (const float*)d_in[14];
    const float* sd   = (const float*)d_in[15];
    float* out = (float*)d_out;

    float *xn32, *x1;
    __half *hxn, *hq0, *hk0, *hv0, *hqr, *hkr, *hctx, *hxg;
    __half *hg, *hu, *hgb, *hgs32, *hus32, *hgs;
    cudaGetSymbolAddress((void**)&xn32, d_xn32);
    cudaGetSymbolAddress((void**)&x1,  d_x1);
    cudaGetSymbolAddress((void**)&hxn, h_xn);
    cudaGetSymbolAddress((void**)&hq0, h_q0);
    cudaGetSymbolAddress((void**)&hk0, h_k0);
    cudaGetSymbolAddress((void**)&hv0, h_v0);
    cudaGetSymbolAddress((void**)&hqr, h_qr);
    cudaGetSymbolAddress((void**)&hkr, h_kr);
    cudaGetSymbolAddress((void**)&hctx, h_ctx);
    cudaGetSymbolAddress((void**)&hxg, h_xg);
    cudaGetSymbolAddress((void**)&hg,  h_gbuf);
    cudaGetSymbolAddress((void**)&hu,  h_ubuf);
    cudaGetSymbolAddress((void**)&hgb, h_gb);
    cudaGetSymbolAddress((void**)&hgs32, h_gs32);
    cudaGetSymbolAddress((void**)&hus32, h_us32);
    cudaGetSymbolAddress((void**)&hgs, h_gs);

    cudaFuncSetAttribute(hoproj_k,
        cudaFuncAttributeMaxDynamicSharedMemorySize, SMEM_BYTES);
    cudaFuncSetAttribute(hfinal_k,
        cudaFuncAttributeMaxDynamicSharedMemorySize, SMEM_BYTES);
    cudaFuncSetAttribute(hqkv_k,
        cudaFuncAttributeMaxDynamicSharedMemorySize, SMEM_BYTES);
    cudaFuncSetAttribute(hshup_k,
        cudaFuncAttributeMaxDynamicSharedMemorySize, SMEM_BYTES);
    cudaFuncSetAttribute(hmoeup_k,
        cudaFuncAttributeMaxDynamicSharedMemorySize, SMEM_BYTES);
    cudaFuncSetAttribute(hmoedn_k,
        cudaFuncAttributeMaxDynamicSharedMemorySize, SMEM_BYTES);
    cudaFuncSetAttribute(flash_k,
        cudaFuncAttributeMaxDynamicSharedMemorySize, FLASH_SMEM);

    // ---- all weight conversions in one launch ----
    conv_all_k<<<(CONV_TOT + 255) / 256, 256>>>(q_w, k_w, v_w, o_w,
                                                eg, eu, ed, sg, su, sd);

    const dim3 gQKV(NHID / BN, NT / BM, 3);
    const dim3 gFlash(NS / 128, NB * NHEAD);
    const dim3 gProj(NHID / BN, NT / BM);
    const dim3 gShUp(NSI / BN, NT / BM, 2);
    const dim3 gMoeUp(NMI / BN, NSLOT / BM, 2 * NEXP);
    const dim3 gMoeDn(NHID / BN, NSLOT / BM, NEXP);

    // ---- attention ----
    rmsnorm_k<<<NT, 256>>>(hs, ln1, hxn, nullptr);
    hqkv_k<<<gQKV, 256, SMEM_BYTES>>>(hxn);
    rope_k<<<NT, 256>>>(hq0, hk0, cosp, sinp, hqr, hkr);
    flash_k<<<gFlash, 256, FLASH_SMEM>>>(hqr, hkr, hv0, hctx);
    hoproj_k<<<gProj, 256, SMEM_BYTES>>>(hctx, x1, hs);

    // ---- MoE ----
    rmsnorm_k<<<NT, 256>>>(x1, ln2, hxn, xn32);   // also zeroes d_cnt
    gate_k<<<NT, 256>>>(xn32, gate);
    scan_k<<<1, 1>>>();
    gather_k<<<NT, 256>>>(hxn);

    hmoeup_k<<<gMoeUp, 256, SMEM_BYTES>>>(hxg);
    silumul_k<<<(unsigned)(((long)NSLOT * NMI / 2 + 255) / 256), 256>>>(
        hg, hu, hgb, (long)NSLOT * NMI / 2);
    hmoedn_k<<<gMoeDn, 256, SMEM_BYTES>>>(hgb);

    // ---- shared MLP ----
    hshup_k<<<gShUp, 256, SMEM_BYTES>>>(hxn);
    silumul_k<<<(unsigned)(((long)NT * NSI / 2 + 255) / 256), 256>>>(
        hgs32, hus32, hgs, (long)NT * NSI / 2);

    // ---- final GEMM with fused combine: out = x1 + shdown + routed ----
    hfinal_k<<<gProj, 256, SMEM_BYTES>>>(hgs, out, x1);
}

// round 14
// speedup vs baseline: 1.1383x; 1.0152x over previous
#include <cuda_runtime.h>
#include <cuda_fp16.h>
#include <math.h>

// ---------------------------------------------------------------------------
// Problem constants
// ---------------------------------------------------------------------------
namespace {
constexpr int NB = 2, NS = 1024, NHID = 1024, NHEAD = 8, DHEAD = 128;
constexpr int NEXP = 8, NMI = 1024, NSI = 2048;
constexpr int NT = NB * NS;          // 2048 tokens
constexpr int NSLOT = 2 * NT;        // 4096 expert slots (top-2)

// fp16 GEMM tile: 128x128x32(halves), 8 warps of 64x32, 4-stage cp.async
constexpr int BM = 128, BN = 128, BKH = 32;
constexpr int PAD32 = 20;                        // row stride in b32 (80B)
constexpr int STAGES = 4;
constexpr int STAGE_WORDS = BM * PAD32;          // 2560 b32 per tile-stage
constexpr int SMEM_BYTES = 2 * STAGES * STAGE_WORDS * 4;   // 81920

// flash attention smem: Q + 2xK + 2xV tiles of 128 rows x 68 words
constexpr int FPW = 68;                          // words per row (136 halves)
constexpr int FTILE_W = 128 * FPW;               // 8704 words per tile
constexpr int FLASH_SMEM = 5 * FTILE_W * 4;      // 174080 bytes
}

// ---------------------------------------------------------------------------
// Static device scratch (no allocations allowed)
// ---------------------------------------------------------------------------
// fp32 buffers
__device__ float d_x1[NT * NHID];
// fp16 weights
__device__ __half h_qw[NHID * NHID];
__device__ __half h_kw[NHID * NHID];
__device__ __half h_vw[NHID * NHID];
__device__ __half h_ow[NHID * NHID];
__device__ __half h_eg[NEXP * NMI * NHID];
__device__ __half h_eu[NEXP * NMI * NHID];
__device__ __half h_ed[NEXP * NHID * NMI];
__device__ __half h_sg[NSI * NHID];
__device__ __half h_su[NSI * NHID];
__device__ __half h_sd[NHID * NSI];
// fp16 activations
__device__ __half h_xn[NT * NHID];
__device__ __half h_q0[NT * NHID];    // QKV GEMM outputs, (t, head*128+d)
__device__ __half h_k0[NT * NHID];
__device__ __half h_v0[NT * NHID];
__device__ __half h_qr[NT * NHID];    // rope'd + scaled
__device__ __half h_kr[NT * NHID];
__device__ __half h_ctx[NT * NHID];   // flash output
__device__ __half h_xg[NSLOT * NHID];
__device__ __half h_gbuf[NSLOT * NMI];   // MoE gate GEMM out (half)
__device__ __half h_ubuf[NSLOT * NMI];   // MoE up GEMM out (half)
__device__ __half h_gb[NSLOT * NMI];     // silu(g)*u (half)
__device__ __half h_ybuf[NSLOT * NHID];  // MoE down out (half)
__device__ __half h_gs32[NT * NSI];      // shared gate GEMM out (half)
__device__ __half h_us32[NT * NSI];      // shared up GEMM out (half)
__device__ __half h_gs[NT * NSI];        // silu(g)*u (half)
// routing state
__device__ int   d_cnt[NEXP];
__device__ int   d_e0[NT], d_e1[NT], d_r0[NT], d_r1[NT], d_s0[NT], d_s1[NT];
__device__ float d_w0[NT], d_w1[NT];

// ---------------------------------------------------------------------------
// helpers
// ---------------------------------------------------------------------------
__device__ __forceinline__ unsigned smem_u32(const void* p) {
    return (unsigned)__cvta_generic_to_shared(p);
}

__device__ __forceinline__ void cp16(unsigned dst, const void* src, bool pred) {
    int sz = pred ? 16 : 0;
    asm volatile("cp.async.cg.shared.global [%0], [%1], 16, %2;\n"
                 :: "r"(dst), "l"(src), "r"(sz));
}

__device__ __forceinline__ void ldsm4(unsigned& r0, unsigned& r1,
                                      unsigned& r2, unsigned& r3, unsigned addr)
{
    asm volatile("ldmatrix.sync.aligned.m8n8.x4.shared.b16 {%0,%1,%2,%3}, [%4];"
                 : "=r"(r0), "=r"(r1), "=r"(r2), "=r"(r3) : "r"(addr));
}

__device__ __forceinline__ void ldsm4t(unsigned& r0, unsigned& r1,
                                       unsigned& r2, unsigned& r3, unsigned addr)
{
    asm volatile("ldmatrix.sync.aligned.m8n8.x4.trans.shared.b16 {%0,%1,%2,%3}, [%4];"
                 : "=r"(r0), "=r"(r1), "=r"(r2), "=r"(r3) : "r"(addr));
}

__device__ __forceinline__ void mma_f16(float c[4],
    unsigned a0, unsigned a1, unsigned a2, unsigned a3,
    unsigned b0, unsigned b1)
{
    asm volatile(
        "mma.sync.aligned.m16n8k16.row.col.f32.f16.f16.f32 "
        "{%0,%1,%2,%3}, {%4,%5,%6,%7}, {%8,%9}, {%0,%1,%2,%3};\n"
        : "+f"(c[0]), "+f"(c[1]), "+f"(c[2]), "+f"(c[3])
        : "r"(a0), "r"(a1), "r"(a2), "r"(a3), "r"(b0), "r"(b1));
}

__device__ __forceinline__ unsigned packh2(float a, float b) {
    __half2 h = __floats2half2_rn(a, b);
    return *reinterpret_cast<unsigned*>(&h);
}

// ---------------------------------------------------------------------------
// FP16 tensor-core GEMM:  C[M,N] = A[M,K] * B^T  (B stored (N,K) row-major,
// offsets in HALVES).  128x128 block, 8 warps of 64x32 (4x4 m16n8k16),
// 4-stage cp.async, ldmatrix operand loads.  OutT = float or __half.
// FINAL: fuse the MoE combine — out = resid + gemm + w0*yb[s0] + w1*yb[s1].
// ---------------------------------------------------------------------------
template <typename OutT, bool FINAL>
__device__ __forceinline__ void hgemm_body(
    const __half* __restrict__ A, const __half* __restrict__ Bm,
    OutT* __restrict__ C, const float* __restrict__ resid,
    int M, int K, int lda, int ldb, int ldc)
{
    extern __shared__ unsigned smu[];
    unsigned* Asm = smu;                         // [STAGES][BM][PAD32]
    unsigned* Bsm = smu + STAGES * STAGE_WORDS;

    const int tid  = threadIdx.x;
    const int wid  = tid >> 5;
    const int lane = tid & 31;
    const int g    = lane >> 2;
    const int tg   = lane & 3;
    const int wm   = (wid & 1) * 64;
    const int wn   = (wid >> 1) * 32;
    const int row0 = blockIdx.y * BM;
    const int col0 = blockIdx.x * BN;
    if (row0 >= M) return;

    const int rA = (lane & 7) + ((lane >> 3) & 1) * 8;
    const int cA = ((lane >> 4) & 1) * 4;
    const int rB = (lane & 7) + ((lane >> 4) & 1) * 8;
    const int cB = ((lane >> 3) & 1) * 4;

    float c[4][4][4];
#pragma unroll
    for (int mi = 0; mi < 4; ++mi)
#pragma unroll
        for (int ni = 0; ni < 4; ++ni)
#pragma unroll
            for (int r = 0; r < 4; ++r) c[mi][ni][r] = 0.f;

    const int lr = tid >> 1;
    const int lqh = (tid & 1) * 16;
    const int lqw = (tid & 1) * 8;
    const int niter = K / BKH;

#pragma unroll
    for (int st = 0; st < STAGES - 1; ++st) {
        if (st < niter) {
            const int k0 = st * BKH;
            const __half* ga = A + (long)(row0 + lr) * lda + k0 + lqh;
            unsigned da = smem_u32(Asm + st * STAGE_WORDS + lr * PAD32 + lqw);
            bool pa = (row0 + lr) < M;
            cp16(da,      ga,     pa);
            cp16(da + 16, ga + 8, pa);
            const __half* gb = Bm + (long)(col0 + lr) * ldb + k0 + lqh;
            unsigned db = smem_u32(Bsm + st * STAGE_WORDS + lr * PAD32 + lqw);
            cp16(db,      gb,     true);
            cp16(db + 16, gb + 8, true);
        }
        asm volatile("cp.async.commit_group;\n");
    }

    int s = 0;
    for (int it = 0; it < niter; ++it) {
        asm volatile("cp.async.wait_group 2;\n");
        __syncthreads();

        const int pf = it + STAGES - 1;
        if (pf < niter) {
            int sl = s + STAGES - 1; if (sl >= STAGES) sl -= STAGES;
            const int k0 = pf * BKH;
            const __half* ga = A + (long)(row0 + lr) * lda + k0 + lqh;
            unsigned da = smem_u32(Asm + sl * STAGE_WORDS + lr * PAD32 + lqw);
            bool pa = (row0 + lr) < M;
            cp16(da,      ga,     pa);
            cp16(da + 16, ga + 8, pa);
            const __half* gb = Bm + (long)(col0 + lr) * ldb + k0 + lqh;
            unsigned db = smem_u32(Bsm + sl * STAGE_WORDS + lr * PAD32 + lqw);
            cp16(db,      gb,     true);
            cp16(db + 16, gb + 8, true);
        }
        asm volatile("cp.async.commit_group;\n");

        const unsigned a_base = smem_u32(Asm + s * STAGE_WORDS);
        const unsigned b_base = smem_u32(Bsm + s * STAGE_WORDS);
#pragma unroll
        for (int kk = 0; kk < 2; ++kk) {
            const int kb = kk * 8;
            unsigned af[4][4], bf[4][2];
#pragma unroll
            for (int mi = 0; mi < 4; ++mi) {
                unsigned addr = a_base +
                    4u * ((wm + mi * 16 + rA) * PAD32 + kb + cA);
                ldsm4(af[mi][0], af[mi][1], af[mi][2], af[mi][3], addr);
            }
#pragma unroll
            for (int p = 0; p < 2; ++p) {
                unsigned addr = b_base +
                    4u * ((wn + p * 16 + rB) * PAD32 + kb + cB);
                ldsm4(bf[2 * p][0], bf[2 * p][1],
                      bf[2 * p + 1][0], bf[2 * p + 1][1], addr);
            }
#pragma unroll
            for (int mi = 0; mi < 4; ++mi)
#pragma unroll
                for (int ni = 0; ni < 4; ++ni)
                    mma_f16(c[mi][ni], af[mi][0], af[mi][1], af[mi][2], af[mi][3],
                            bf[ni][0], bf[ni][1]);
        }
        if (++s >= STAGES) s = 0;
    }

    // ---- epilogue ----
#pragma unroll
    for (int mi = 0; mi < 4; ++mi) {
#pragma unroll
        for (int half = 0; half < 2; ++half) {
            int r = row0 + wm + mi * 16 + g + half * 8;
            if (r < M) {
                float w0 = 0.f, w1 = 0.f;
                long y0 = 0, y1 = 0;
                if (FINAL) {
                    w0 = d_w0[r]; w1 = d_w1[r];
                    y0 = (long)d_s0[r] * NHID;
                    y1 = (long)d_s1[r] * NHID;
                }
#pragma unroll
                for (int ni = 0; ni < 4; ++ni) {
                    int colg = col0 + wn + ni * 8 + tg * 2;
                    long off = (long)r * ldc + colg;
                    float vx = c[mi][ni][half * 2 + 0];
                    float vy = c[mi][ni][half * 2 + 1];
                    if (resid) {
                        float2 rr = *(const float2*)(resid + off);
                        vx += rr.x; vy += rr.y;
                    }
                    if (FINAL) {
                        __half2 a0 = *(const __half2*)(h_ybuf + y0 + colg);
                        __half2 a1 = *(const __half2*)(h_ybuf + y1 + colg);
                        vx += w0 * __low2float(a0)  + w1 * __low2float(a1);
                        vy += w0 * __high2float(a0) + w1 * __high2float(a1);
                    }
                    if constexpr (sizeof(OutT) == 4) {
                        float2 v; v.x = vx; v.y = vy;
                        *(float2*)((float*)C + off) = v;
                    } else {
                        __half2 hv = __floats2half2_rn(vx, vy);
                        *(__half2*)((__half*)C + off) = hv;
                    }
                }
            }
        }
    }
}

// ---- O-proj (float out, residual)
__global__ __launch_bounds__(256, 2)
void hoproj_k(const __half* __restrict__ A, float* __restrict__ C,
              const float* __restrict__ resid)
{
    hgemm_body<float, false>(A, h_ow, C, resid, NT, NHID, NHID, NHID, NHID);
}

// ---- FINAL shared-down GEMM: writes out = x1 + shdown + routed
__global__ __launch_bounds__(256, 2)
void hfinal_k(const __half* __restrict__ A, float* __restrict__ C,
              const float* __restrict__ resid)
{
    hgemm_body<float, true>(A, h_sd, C, resid, NT, NSI, NSI, NSI, NHID);
}

// ---- fused Q/K/V projection (half out)
__global__ __launch_bounds__(256, 2)
void hqkv_k(const __half* __restrict__ xn)
{
    int z = blockIdx.z;
    const __half* B = (z == 0) ? h_qw : (z == 1) ? h_kw : h_vw;
    __half* C       = (z == 0) ? h_q0 : (z == 1) ? h_k0 : h_v0;
    hgemm_body<__half, false>(xn, B, C, nullptr, NT, NHID, NHID, NHID, NHID);
}

// ---- fused shared-MLP gate+up (half out)
__global__ __launch_bounds__(256, 2)
void hshup_k(const __half* __restrict__ xn)
{
    int z = blockIdx.z;
    hgemm_body<__half, false>(xn, z ? h_su : h_sg, z ? h_us32 : h_gs32, nullptr,
                              NT, NHID, NHID, NHID, NSI);
}

// ---- fused MoE gate+up grouped (half out): z = 2*e + which
__global__ __launch_bounds__(256, 2)
void hmoeup_k(const __half* __restrict__ xg)
{
    int z = blockIdx.z;
    int e = z >> 1;
    int M = d_cnt[e];
    int off = 0;
    for (int i = 0; i < NEXP; ++i) if (i < e) off += d_cnt[i];
    const __half* B = (z & 1) ? h_eu : h_eg;
    __half* C       = (z & 1) ? h_ubuf : h_gbuf;
    hgemm_body<__half, false>(xg + (long)off * NHID, B + (long)e * NMI * NHID,
                              C + (long)off * NMI, nullptr, M, NHID, NHID, NHID, NMI);
}

// ---- MoE down grouped (half out)
__global__ __launch_bounds__(256, 2)
void hmoedn_k(const __half* __restrict__ gb)
{
    int e = blockIdx.z;
    int M = d_cnt[e];
    int off = 0;
    for (int i = 0; i < NEXP; ++i) if (i < e) off += d_cnt[i];
    hgemm_body<__half, false>(gb + (long)off * NMI, h_ed + (long)e * NHID * NMI,
                              h_ybuf + (long)off * NHID, nullptr, M, NMI, NMI, NMI, NHID);
}

// ---------------------------------------------------------------------------
// Flash attention (r8, unchanged): one CTA per (q-tile 128, head).
// ---------------------------------------------------------------------------
__global__ __launch_bounds__(256, 1)
void flash_k(const __half* __restrict__ q, const __half* __restrict__ k,
             const __half* __restrict__ v, __half* __restrict__ o)
{
    extern __shared__ unsigned fsm[];
    unsigned* Qs = fsm;
    unsigned* Ks = fsm + FTILE_W;
    unsigned* Vs = fsm + 3 * FTILE_W;

    const int qi  = blockIdx.x;
    const int bh  = blockIdx.y;
    const int b   = bh >> 3, n = bh & 7;
    const int tid = threadIdx.x, wid = tid >> 5, lane = tid & 31;
    const int g   = lane >> 2, tg = lane & 3;
    const int wq  = wid * 16;
    const int row0 = qi * 128;

    const long qbase  = ((long)b * NS + row0) * NHID + n * DHEAD;
    const long kvbase = ((long)b * NS) * NHID + n * DHEAD;

    const int rA = (lane & 7) + ((lane >> 3) & 1) * 8;
    const int cA = ((lane >> 4) & 1) * 4;
    const int rB = (lane & 7) + ((lane >> 4) & 1) * 8;
    const int cB = ((lane >> 3) & 1) * 4;
    const int rV = lane & 15;
    const int cV = (lane >> 4) * 4;

    {
        int r = tid >> 1, hh = tid & 1;
        const __half* gq = q + qbase + (long)r * NHID + hh * 64;
        unsigned dq = smem_u32(Qs + r * FPW + hh * 32);
#pragma unroll
        for (int c2 = 0; c2 < 8; ++c2) cp16(dq + c2 * 16, gq + c2 * 8, true);
    }
    {
        int r = tid >> 1, hh = tid & 1;
        const __half* gk = k + kvbase + (long)r * NHID + hh * 64;
        const __half* gv = v + kvbase + (long)r * NHID + hh * 64;
        unsigned dk = smem_u32(Ks + r * FPW + hh * 32);
        unsigned dv = smem_u32(Vs + r * FPW + hh * 32);
#pragma unroll
        for (int c2 = 0; c2 < 8; ++c2) {
            cp16(dk + c2 * 16, gk + c2 * 8, true);
            cp16(dv + c2 * 16, gv + c2 * 8, true);
        }
    }
    asm volatile("cp.async.commit_group;\n");
    asm volatile("cp.async.wait_group 0;\n");
    __syncthreads();

    float oacc[16][4];
#pragma unroll
    for (int j = 0; j < 16; ++j)
#pragma unroll
        for (int r = 0; r < 4; ++r) oacc[j][r] = 0.f;
    float m0 = -1e30f, m1 = -1e30f, l0 = 0.f, l1 = 0.f;

    for (int t = 0; t <= qi; ++t) {
        const int cur = t & 1;
        if (t + 1 <= qi) {
            int nxt = (t + 1) & 1;
            int r = tid >> 1, hh = tid & 1;
            const __half* gk = k + kvbase + ((long)(t + 1) * 128 + r) * NHID + hh * 64;
            const __half* gv = v + kvbase + ((long)(t + 1) * 128 + r) * NHID + hh * 64;
            unsigned dk = smem_u32(Ks + nxt * FTILE_W + r * FPW + hh * 32);
            unsigned dv = smem_u32(Vs + nxt * FTILE_W + r * FPW + hh * 32);
#pragma unroll
            for (int c2 = 0; c2 < 8; ++c2) {
                cp16(dk + c2 * 16, gk + c2 * 8, true);
                cp16(dv + c2 * 16, gv + c2 * 8, true);
            }
        }
        asm volatile("cp.async.commit_group;\n");

        const unsigned kbase = smem_u32(Ks + cur * FTILE_W);
        const unsigned vbase = smem_u32(Vs + cur * FTILE_W);
        const unsigned qbse  = smem_u32(Qs);

        float sacc[16][4];
#pragma unroll
        for (int j = 0; j < 16; ++j)
#pragma unroll
            for (int r = 0; r < 4; ++r) sacc[j][r] = 0.f;

#pragma unroll
        for (int ks = 0; ks < 8; ++ks) {
            unsigned qa[4];
            ldsm4(qa[0], qa[1], qa[2], qa[3],
                  qbse + 4u * ((wq + rA) * FPW + ks * 8 + cA));
#pragma unroll
            for (int p = 0; p < 8; ++p) {
                unsigned b0, b1, b2, b3;
                ldsm4(b0, b1, b2, b3,
                      kbase + 4u * ((p * 16 + rB) * FPW + ks * 8 + cB));
                mma_f16(sacc[2 * p],     qa[0], qa[1], qa[2], qa[3], b0, b1);
                mma_f16(sacc[2 * p + 1], qa[0], qa[1], qa[2], qa[3], b2, b3);
            }
        }

        if (t == qi) {
            int r0l = wq + g, r1l = wq + g + 8;
#pragma unroll
            for (int j = 0; j < 16; ++j) {
                int col = 8 * j + 2 * tg;
                if (col     > r0l) sacc[j][0] = -1e30f;
                if (col + 1 > r0l) sacc[j][1] = -1e30f;
                if (col     > r1l) sacc[j][2] = -1e30f;
                if (col + 1 > r1l) sacc[j][3] = -1e30f;
            }
        }

        float tm0 = -1e30f, tm1 = -1e30f;
#pragma unroll
        for (int j = 0; j < 16; ++j) {
            tm0 = fmaxf(tm0, fmaxf(sacc[j][0], sacc[j][1]));
            tm1 = fmaxf(tm1, fmaxf(sacc[j][2], sacc[j][3]));
        }
        tm0 = fmaxf(tm0, __shfl_xor_sync(0xffffffffu, tm0, 1));
        tm0 = fmaxf(tm0, __shfl_xor_sync(0xffffffffu, tm0, 2));
        tm1 = fmaxf(tm1, __shfl_xor_sync(0xffffffffu, tm1, 1));
        tm1 = fmaxf(tm1, __shfl_xor_sync(0xffffffffu, tm1, 2));
        float nm0 = fmaxf(m0, tm0), nm1 = fmaxf(m1, tm1);
        float al0 = __expf(m0 - nm0), al1 = __expf(m1 - nm1);

        float rs0 = 0.f, rs1 = 0.f;
        unsigned pf[8][4];
#pragma unroll
        for (int j = 0; j < 16; ++j) {
            float p0 = __expf(sacc[j][0] - nm0);
            float p1 = __expf(sacc[j][1] - nm0);
            float p2 = __expf(sacc[j][2] - nm1);
            float p3 = __expf(sacc[j][3] - nm1);
            rs0 += p0 + p1; rs1 += p2 + p3;
            int ks = j >> 1;
            if ((j & 1) == 0) { pf[ks][0] = packh2(p0, p1); pf[ks][1] = packh2(p2, p3); }
            else              { pf[ks][2] = packh2(p0, p1); pf[ks][3] = packh2(p2, p3); }
        }
        rs0 += __shfl_xor_sync(0xffffffffu, rs0, 1);
        rs0 += __shfl_xor_sync(0xffffffffu, rs0, 2);
        rs1 += __shfl_xor_sync(0xffffffffu, rs1, 1);
        rs1 += __shfl_xor_sync(0xffffffffu, rs1, 2);
        m0 = nm0; m1 = nm1;
        l0 = l0 * al0 + rs0;
        l1 = l1 * al1 + rs1;

#pragma unroll
        for (int j = 0; j < 16; ++j) {
            oacc[j][0] *= al0; oacc[j][1] *= al0;
            oacc[j][2] *= al1; oacc[j][3] *= al1;
        }

#pragma unroll
        for (int ks = 0; ks < 8; ++ks) {
#pragma unroll
            for (int p = 0; p < 8; ++p) {
                unsigned v0, v1, v2, v3;
                ldsm4t(v0, v1, v2, v3,
                       vbase + 4u * ((ks * 16 + rV) * FPW + p * 8 + cV));
                mma_f16(oacc[2 * p],     pf[ks][0], pf[ks][1], pf[ks][2], pf[ks][3], v0, v1);
                mma_f16(oacc[2 * p + 1], pf[ks][0], pf[ks][1], pf[ks][2], pf[ks][3], v2, v3);
            }
        }

        asm volatile("cp.async.wait_group 0;\n");
        __syncthreads();
    }

    float il0 = 1.f / l0, il1 = 1.f / l1;
    long obase0 = ((long)b * NS + row0 + wq + g) * NHID + n * DHEAD;
    long obase1 = obase0 + 8L * NHID;
#pragma unroll
    for (int j = 0; j < 16; ++j) {
        int col = 8 * j + 2 * tg;
        __half2 h0 = __floats2half2_rn(oacc[j][0] * il0, oacc[j][1] * il0);
        __half2 h1 = __floats2half2_rn(oacc[j][2] * il1, oacc[j][3] * il1);
        *(__half2*)(o + obase0 + col) = h0;
        *(__half2*)(o + obase1 + col) = h1;
    }
}

// ---------------------------------------------------------------------------
// fused weight conversion fp32 -> fp16 (one launch, segment ladder, float4s)
// ---------------------------------------------------------------------------
namespace {
constexpr int W1 = NHID * NHID / 4;
constexpr int WE = NEXP * NMI * NHID / 4;
constexpr int WS = NSI * NHID / 4;
constexpr int CONV_TOT = 4 * W1 + 3 * WE + 3 * WS;
}

__global__ void conv_all_k(
    const float* __restrict__ qw, const float* __restrict__ kw,
    const float* __restrict__ vw, const float* __restrict__ ow,
    const float* __restrict__ eg, const float* __restrict__ eu,
    const float* __restrict__ ed, const float* __restrict__ sg,
    const float* __restrict__ su, const float* __restrict__ sd)
{
    int i = blockIdx.x * 256 + threadIdx.x;
    if (i >= CONV_TOT) return;
    const float* src; __half* dst; int j = i;
    if      (j < 1 * W1) { src = qw; dst = h_qw; }
    else if (j < 2 * W1) { src = kw; dst = h_kw; j -= 1 * W1; }
    else if (j < 3 * W1) { src = vw; dst = h_vw; j -= 2 * W1; }
    else if (j < 4 * W1) { src = ow; dst = h_ow; j -= 3 * W1; }
    else {
        j -= 4 * W1;
        if      (j < 1 * WE) { src = eg; dst = h_eg; }
        else if (j < 2 * WE) { src = eu; dst = h_eu; j -= 1 * WE; }
        else if (j < 3 * WE) { src = ed; dst = h_ed; j -= 2 * WE; }
        else {
            j -= 3 * WE;
            if      (j < 1 * WS) { src = sg; dst = h_sg; }
            else if (j < 2 * WS) { src = su; dst = h_su; j -= 1 * WS; }
            else                 { src = sd; dst = h_sd; j -= 2 * WS; }
        }
    }
    float4 v = *(const float4*)(src + 4 * (long)j);
    __half2 h0 = __floats2half2_rn(v.x, v.y);
    __half2 h1 = __floats2half2_rn(v.z, v.w);
    *(__half2*)(dst + 4 * (long)j)     = h0;
    *(__half2*)(dst + 4 * (long)j + 2) = h1;
}

// ---------------------------------------------------------------------------
// Elementwise / reduction kernels
// ---------------------------------------------------------------------------
// rmsnorm (attention pre-norm); also zeroes d_cnt for the later routing pass
__global__ void rmsnorm_k(const float* __restrict__ x,
                          const float* __restrict__ w,
                          __half* __restrict__ oh)
{
    int t = blockIdx.x;
    if (t == 0 && threadIdx.x < NEXP) d_cnt[threadIdx.x] = 0;
    const float* xr = x + (long)t * NHID;
    __shared__ float red[256];
    float s = 0.f;
    for (int i = threadIdx.x; i < NHID; i += 256) { float v = xr[i]; s += v * v; }
    red[threadIdx.x] = s;
    __syncthreads();
    for (int st = 128; st > 0; st >>= 1) {
        if (threadIdx.x < st) red[threadIdx.x] += red[threadIdx.x + st];
        __syncthreads();
    }
    float scale = rsqrtf(red[0] / (float)NHID + 1e-6f);
    for (int i = threadIdx.x; i < NHID; i += 256)
        oh[(long)t * NHID + i] = __float2half_rn(xr[i] * scale * w[i]);
}

// rmsnorm + MoE gating fused: one block per token. Normalized row kept in
// smem (fp32, identical values to the old xn32 path) and used for the 8
// expert logits; thread 0 does top-2 + atomicAdd ticketing.
__global__ void rmsnorm_gate_k(const float* __restrict__ x,
                               const float* __restrict__ w,
                               const float* __restrict__ gw,
                               __half* __restrict__ oh)
{
    int t = blockIdx.x;
    int tid = threadIdx.x, wd = tid >> 5, lane = tid & 31;
    const float* xr = x + (long)t * NHID;
    __shared__ float red[256];
    __shared__ float xs[NHID];
    float s = 0.f;
    for (int i = tid; i < NHID; i += 256) { float v = xr[i]; s += v * v; }
    red[tid] = s;
    __syncthreads();
    for (int st = 128; st > 0; st >>= 1) {
        if (tid < st) red[tid] += red[tid + st];
        __syncthreads();
    }
    float scale = rsqrtf(red[0] / (float)NHID + 1e-6f);
    for (int i = tid; i < NHID; i += 256) {
        float v = xr[i] * scale * w[i];
        xs[i] = v;
        oh[(long)t * NHID + i] = __float2half_rn(v);
    }
    __syncthreads();

    // gating: warp wd computes logit for expert wd
    const float* gr = gw + (long)wd * NHID;
    float gsum = 0.f;
    for (int i = lane; i < NHID; i += 32) gsum += xs[i] * gr[i];
    for (int o = 16; o; o >>= 1) gsum += __shfl_xor_sync(0xffffffffu, gsum, o);
    __shared__ float lg[NEXP];
    if (lane == 0) lg[wd] = gsum;
    __syncthreads();
    if (tid == 0) {
        float mx = lg[0];
        for (int e = 1; e < NEXP; ++e) mx = fmaxf(mx, lg[e]);
        float p[NEXP];
        for (int e = 0; e < NEXP; ++e) p[e] = expf(lg[e] - mx);
        int e0 = 0; float b0 = p[0];
        for (int e = 1; e < NEXP; ++e) if (p[e] > b0) { b0 = p[e]; e0 = e; }
        int e1 = -1; float b1 = -1.f;
        for (int e = 0; e < NEXP; ++e)
            if (e != e0 && p[e] > b1) { b1 = p[e]; e1 = e; }
        float denom = b0 + b1;
        d_e0[t] = e0; d_e1[t] = e1;
        d_w0[t] = b0 / denom; d_w1[t] = b1 / denom;
        d_r0[t] = atomicAdd(&d_cnt[e0], 1);
        d_r1[t] = atomicAdd(&d_cnt[e1], 1);
    }
}

__global__ void rope_k(const __half* __restrict__ q0, const __half* __restrict__ k0,
                       const float* __restrict__ cosp, const float* __restrict__ sinp,
                       __half* __restrict__ qr, __half* __restrict__ kr)
{
    int t = blockIdx.x;
    int s = t % NS;
    const float inv = 0.08838834764831845f;  // 1/sqrt(128)
    for (int i = threadIdx.x; i < NHEAD * 64; i += 256) {
        int n = i >> 6, d = i & 63;
        long base = (long)t * NHID + n * DHEAD;
        float c  = cosp[s * DHEAD + d];
        float sn = sinp[s * DHEAD + d];
        float a0 = __half2float(q0[base + d]);
        float a1 = __half2float(q0[base + d + 64]);
        qr[base + d]      = __float2half_rn((a0 * c - a1 * sn) * inv);
        qr[base + d + 64] = __float2half_rn((a1 * c + a0 * sn) * inv);
        float b0 = __half2float(k0[base + d]);
        float b1 = __half2float(k0[base + d + 64]);
        kr[base + d]      = __float2half_rn(b0 * c - b1 * sn);
        kr[base + d + 64] = __float2half_rn(b1 * c + b0 * sn);
    }
}

// gather: computes slot = prefix(d_cnt)[e] + rank inline (d_cnt final here)
__global__ void gather_k(const __half* __restrict__ xnh)
{
    int t = blockIdx.x;
    __shared__ int ss[2];
    if (threadIdx.x == 0) {
        int pre[NEXP];
        int a = 0;
        for (int e = 0; e < NEXP; ++e) { pre[e] = a; a += d_cnt[e]; }
        int s0 = pre[d_e0[t]] + d_r0[t];
        int s1 = pre[d_e1[t]] + d_r1[t];
        d_s0[t] = s0; d_s1[t] = s1;
        ss[0] = s0; ss[1] = s1;
    }
    __syncthreads();
    const uint4* src = (const uint4*)(xnh + (long)t * NHID);
    uint4* dst0 = (uint4*)(h_xg + (long)ss[0] * NHID);
    uint4* dst1 = (uint4*)(h_xg + (long)ss[1] * NHID);
    for (int i = threadIdx.x; i < NHID / 8; i += 256) {
        uint4 v = src[i];
        dst0[i] = v;
        dst1[i] = v;
    }
}

// silu(g)*u, half in / half out, vectorized __half2
__global__ void silumul_k(const __half* __restrict__ g, const __half* __restrict__ u,
                          __half* __restrict__ o, long n2)
{
    long i = (long)blockIdx.x * 256 + threadIdx.x;
    if (i < n2) {
        __half2 gh = ((const __half2*)g)[i];
        __half2 uh = ((const __half2*)u)[i];
        float g0 = __low2float(gh),  g1 = __high2float(gh);
        float u0 = __low2float(uh),  u1 = __high2float(uh);
        float r0 = g0 / (1.f + __expf(-g0)) * u0;
        float r1 = g1 / (1.f + __expf(-g1)) * u1;
        ((__half2*)o)[i] = __floats2half2_rn(r0, r1);
    }
}

// ---------------------------------------------------------------------------
// Launch
// ---------------------------------------------------------------------------
extern "C" void kernel_launch(void* const* d_in, const int* in_sizes, int n_in,
                              void* d_out, int out_size)
{
    (void)in_sizes; (void)n_in; (void)out_size;

    const float* hs   = (const float*)d_in[0];
    const float* ln1  = (const float*)d_in[1];
    const float* ln2  = (const float*)d_in[2];
    const float* q_w  = (const float*)d_in[3];
    const float* k_w  = (const float*)d_in[4];
    const float* v_w  = (const float*)d_in[5];
    const float* o_w  = (const float*)d_in[6];
    const float* cosp = (const float*)d_in[7];
    const float* sinp = (const float*)d_in[8];
    const float* gate = (const float*)d_in[9];
    const float* eg   = (const float*)d_in[10];
    const float* eu   = (const float*)d_in[11];
    const float* ed   = (const float*)d_in[12];
    const float* sg   = (const float*)d_in[13];
    const float* su   = (const float*)d_in[14];
    const float* sd   = (const float*)d_in[15];
    float* out = (float*)d_out;

    float* x1;
    __half *hxn, *hq0, *hk0, *hv0, *hqr, *hkr, *hctx, *hxg;
    __half *hg, *hu, *hgb, *hgs32, *hus32, *hgs;
    cudaGetSymbolAddress((void**)&x1,  d_x1);
    cudaGetSymbolAddress((void**)&hxn, h_xn);
    cudaGetSymbolAddress((void**)&hq0, h_q0);
    cudaGetSymbolAddress((void**)&hk0, h_k0);
    cudaGetSymbolAddress((void**)&hv0, h_v0);
    cudaGetSymbolAddress((void**)&hqr, h_qr);
    cudaGetSymbolAddress((void**)&hkr, h_kr);
    cudaGetSymbolAddress((void**)&hctx, h_ctx);
    cudaGetSymbolAddress((void**)&hxg, h_xg);
    cudaGetSymbolAddress((void**)&hg,  h_gbuf);
    cudaGetSymbolAddress((void**)&hu,  h_ubuf);
    cudaGetSymbolAddress((void**)&hgb, h_gb);
    cudaGetSymbolAddress((void**)&hgs32, h_gs32);
    cudaGetSymbolAddress((void**)&hus32, h_us32);
    cudaGetSymbolAddress((void**)&hgs, h_gs);

    cudaFuncSetAttribute(hoproj_k,
        cudaFuncAttributeMaxDynamicSharedMemorySize, SMEM_BYTES);
    cudaFuncSetAttribute(hfinal_k,
        cudaFuncAttributeMaxDynamicSharedMemorySize, SMEM_BYTES);
    cudaFuncSetAttribute(hqkv_k,
        cudaFuncAttributeMaxDynamicSharedMemorySize, SMEM_BYTES);
    cudaFuncSetAttribute(hshup_k,
        cudaFuncAttributeMaxDynamicSharedMemorySize, SMEM_BYTES);
    cudaFuncSetAttribute(hmoeup_k,
        cudaFuncAttributeMaxDynamicSharedMemorySize, SMEM_BYTES);
    cudaFuncSetAttribute(hmoedn_k,
        cudaFuncAttributeMaxDynamicSharedMemorySize, SMEM_BYTES);
    cudaFuncSetAttribute(flash_k,
        cudaFuncAttributeMaxDynamicSharedMemorySize, FLASH_SMEM);

    // ---- all weight conversions in one launch ----
    conv_all_k<<<(CONV_TOT + 255) / 256, 256>>>(q_w, k_w, v_w, o_w,
                                                eg, eu, ed, sg, su, sd);

    const dim3 gQKV(NHID / BN, NT / BM, 3);
    const dim3 gFlash(NS / 128, NB * NHEAD);
    const dim3 gProj(NHID / BN, NT / BM);
    const dim3 gShUp(NSI / BN, NT / BM, 2);
    const dim3 gMoeUp(NMI / BN, NSLOT / BM, 2 * NEXP);
    const dim3 gMoeDn(NHID / BN, NSLOT / BM, NEXP);

    // ---- attention ----
    rmsnorm_k<<<NT, 256>>>(hs, ln1, hxn);          // also zeroes d_cnt
    hqkv_k<<<gQKV, 256, SMEM_BYTES>>>(hxn);
    rope_k<<<NT, 256>>>(hq0, hk0, cosp, sinp, hqr, hkr);
    flash_k<<<gFlash, 256, FLASH_SMEM>>>(hqr, hkr, hv0, hctx);
    hoproj_k<<<gProj, 256, SMEM_BYTES>>>(hctx, x1, hs);

    // ---- MoE: fused rmsnorm + gating, then gather (inline prefix scan) ----
    rmsnorm_gate_k<<<NT, 256>>>(x1, ln2, gate, hxn);
    gather_k<<<NT, 256>>>(hxn);

    hmoeup_k<<<gMoeUp, 256, SMEM_BYTES>>>(hxg);
    silumul_k<<<(unsigned)(((long)NSLOT * NMI / 2 + 255) / 256), 256>>>(
        hg, hu, hgb, (long)NSLOT * NMI / 2);
    hmoedn_k<<<gMoeDn, 256, SMEM_BYTES>>>(hgb);

    // ---- shared MLP ----
    hshup_k<<<gShUp, 256, SMEM_BYTES>>>(hxn);
    silumul_k<<<(unsigned)(((long)NT * NSI / 2 + 255) / 256), 256>>>(
        hgs32, hus32, hgs, (long)NT * NSI / 2);

    // ---- final GEMM with fused combine: out = x1 + shdown + routed ----
    hfinal_k<<<gProj, 256, SMEM_BYTES>>>(hgs, out, x1);
}

// round 15
// speedup vs baseline: 1.1700x; 1.0278x over previous
#include <cuda_runtime.h>
#include <cuda_fp16.h>
#include <math.h>

// ---------------------------------------------------------------------------
// Problem constants
// ---------------------------------------------------------------------------
namespace {
constexpr int NB = 2, NS = 1024, NHID = 1024, NHEAD = 8, DHEAD = 128;
constexpr int NEXP = 8, NMI = 1024, NSI = 2048;
constexpr int NT = NB * NS;          // 2048 tokens
constexpr int NSLOT = 2 * NT;        // 4096 expert slots (top-2)

// fp16 GEMM tile: 128x128x32(halves), 8 warps of 64x32, 4-stage cp.async
constexpr int BM = 128, BN = 128, BKH = 32;
constexpr int PAD32 = 20;                        // row stride in b32 (80B)
constexpr int STAGES = 4;
constexpr int STAGE_WORDS = BM * PAD32;          // 2560 b32 per tile-stage
constexpr int SMEM_BYTES = 2 * STAGES * STAGE_WORDS * 4;   // 81920

// flash attention smem: Q + 2xK + 2xV tiles of 128 rows x 68 words
constexpr int FPW = 68;                          // words per row (136 halves)
constexpr int FTILE_W = 128 * FPW;               // 8704 words per tile
constexpr int FLASH_SMEM = 5 * FTILE_W * 4;      // 174080 bytes
}

// ---------------------------------------------------------------------------
// Static device scratch (no allocations allowed)
// ---------------------------------------------------------------------------
// fp32 buffers
__device__ float d_x1[NT * NHID];
// fp16 weights
__device__ __half h_qw[NHID * NHID];
__device__ __half h_kw[NHID * NHID];
__device__ __half h_vw[NHID * NHID];
__device__ __half h_ow[NHID * NHID];
__device__ __half h_eg[NEXP * NMI * NHID];
__device__ __half h_eu[NEXP * NMI * NHID];
__device__ __half h_ed[NEXP * NHID * NMI];
__device__ __half h_sg[NSI * NHID];
__device__ __half h_su[NSI * NHID];
__device__ __half h_sd[NHID * NSI];
// fp16 activations
__device__ __half h_xn[NT * NHID];
__device__ __half h_q0[NT * NHID];    // QKV GEMM outputs, (t, head*128+d)
__device__ __half h_k0[NT * NHID];
__device__ __half h_v0[NT * NHID];
__device__ __half h_qr[NT * NHID];    // rope'd + scaled
__device__ __half h_kr[NT * NHID];
__device__ __half h_ctx[NT * NHID];   // flash output
__device__ __half h_xg[NSLOT * NHID];
__device__ __half h_gbuf[NSLOT * NMI];   // MoE gate GEMM out (half)
__device__ __half h_ubuf[NSLOT * NMI];   // MoE up GEMM out (half)
__device__ __half h_gb[NSLOT * NMI];     // silu(g)*u (half)
__device__ __half h_ybuf[NSLOT * NHID];  // MoE down out (half)
__device__ __half h_gs32[NT * NSI];      // shared gate GEMM out (half)
__device__ __half h_us32[NT * NSI];      // shared up GEMM out (half)
__device__ __half h_gs[NT * NSI];        // silu(g)*u (half)
// routing state
__device__ int   d_cnt[NEXP];
__device__ int   d_e0[NT], d_e1[NT], d_r0[NT], d_r1[NT], d_s0[NT], d_s1[NT];
__device__ float d_w0[NT], d_w1[NT];

// ---------------------------------------------------------------------------
// helpers
// ---------------------------------------------------------------------------
__device__ __forceinline__ unsigned smem_u32(const void* p) {
    return (unsigned)__cvta_generic_to_shared(p);
}

__device__ __forceinline__ void cp16(unsigned dst, const void* src, bool pred) {
    int sz = pred ? 16 : 0;
    asm volatile("cp.async.cg.shared.global [%0], [%1], 16, %2;\n"
                 :: "r"(dst), "l"(src), "r"(sz));
}

__device__ __forceinline__ void ldsm4(unsigned& r0, unsigned& r1,
                                      unsigned& r2, unsigned& r3, unsigned addr)
{
    asm volatile("ldmatrix.sync.aligned.m8n8.x4.shared.b16 {%0,%1,%2,%3}, [%4];"
                 : "=r"(r0), "=r"(r1), "=r"(r2), "=r"(r3) : "r"(addr));
}

__device__ __forceinline__ void ldsm4t(unsigned& r0, unsigned& r1,
                                       unsigned& r2, unsigned& r3, unsigned addr)
{
    asm volatile("ldmatrix.sync.aligned.m8n8.x4.trans.shared.b16 {%0,%1,%2,%3}, [%4];"
                 : "=r"(r0), "=r"(r1), "=r"(r2), "=r"(r3) : "r"(addr));
}

__device__ __forceinline__ void mma_f16(float c[4],
    unsigned a0, unsigned a1, unsigned a2, unsigned a3,
    unsigned b0, unsigned b1)
{
    asm volatile(
        "mma.sync.aligned.m16n8k16.row.col.f32.f16.f16.f32 "
        "{%0,%1,%2,%3}, {%4,%5,%6,%7}, {%8,%9}, {%0,%1,%2,%3};\n"
        : "+f"(c[0]), "+f"(c[1]), "+f"(c[2]), "+f"(c[3])
        : "r"(a0), "r"(a1), "r"(a2), "r"(a3), "r"(b0), "r"(b1));
}

__device__ __forceinline__ unsigned packh2(float a, float b) {
    __half2 h = __floats2half2_rn(a, b);
    return *reinterpret_cast<unsigned*>(&h);
}

// ---------------------------------------------------------------------------
// FP16 tensor-core GEMM:  C[M,N] = A[M,K] * B^T  (B stored (N,K) row-major,
// offsets in HALVES).  128x128 block, 8 warps of 64x32 (4x4 m16n8k16),
// 4-stage cp.async, ldmatrix operand loads.  OutT = float or __half.
// FINAL: fuse the MoE combine — out = resid + gemm + w0*yb[s0] + w1*yb[s1].
// ---------------------------------------------------------------------------
template <typename OutT, bool FINAL>
__device__ __forceinline__ void hgemm_body(
    const __half* __restrict__ A, const __half* __restrict__ Bm,
    OutT* __restrict__ C, const float* __restrict__ resid,
    int M, int K, int lda, int ldb, int ldc)
{
    extern __shared__ unsigned smu[];
    unsigned* Asm = smu;                         // [STAGES][BM][PAD32]
    unsigned* Bsm = smu + STAGES * STAGE_WORDS;

    const int tid  = threadIdx.x;
    const int wid  = tid >> 5;
    const int lane = tid & 31;
    const int g    = lane >> 2;
    const int tg   = lane & 3;
    const int wm   = (wid & 1) * 64;
    const int wn   = (wid >> 1) * 32;
    const int row0 = blockIdx.y * BM;
    const int col0 = blockIdx.x * BN;
    if (row0 >= M) return;

    const int rA = (lane & 7) + ((lane >> 3) & 1) * 8;
    const int cA = ((lane >> 4) & 1) * 4;
    const int rB = (lane & 7) + ((lane >> 4) & 1) * 8;
    const int cB = ((lane >> 3) & 1) * 4;

    float c[4][4][4];
#pragma unroll
    for (int mi = 0; mi < 4; ++mi)
#pragma unroll
        for (int ni = 0; ni < 4; ++ni)
#pragma unroll
            for (int r = 0; r < 4; ++r) c[mi][ni][r] = 0.f;

    const int lr = tid >> 1;
    const int lqh = (tid & 1) * 16;
    const int lqw = (tid & 1) * 8;
    const int niter = K / BKH;

#pragma unroll
    for (int st = 0; st < STAGES - 1; ++st) {
        if (st < niter) {
            const int k0 = st * BKH;
            const __half* ga = A + (long)(row0 + lr) * lda + k0 + lqh;
            unsigned da = smem_u32(Asm + st * STAGE_WORDS + lr * PAD32 + lqw);
            bool pa = (row0 + lr) < M;
            cp16(da,      ga,     pa);
            cp16(da + 16, ga + 8, pa);
            const __half* gb = Bm + (long)(col0 + lr) * ldb + k0 + lqh;
            unsigned db = smem_u32(Bsm + st * STAGE_WORDS + lr * PAD32 + lqw);
            cp16(db,      gb,     true);
            cp16(db + 16, gb + 8, true);
        }
        asm volatile("cp.async.commit_group;\n");
    }

    int s = 0;
    for (int it = 0; it < niter; ++it) {
        asm volatile("cp.async.wait_group 2;\n");
        __syncthreads();

        const int pf = it + STAGES - 1;
        if (pf < niter) {
            int sl = s + STAGES - 1; if (sl >= STAGES) sl -= STAGES;
            const int k0 = pf * BKH;
            const __half* ga = A + (long)(row0 + lr) * lda + k0 + lqh;
            unsigned da = smem_u32(Asm + sl * STAGE_WORDS + lr * PAD32 + lqw);
            bool pa = (row0 + lr) < M;
            cp16(da,      ga,     pa);
            cp16(da + 16, ga + 8, pa);
            const __half* gb = Bm + (long)(col0 + lr) * ldb + k0 + lqh;
            unsigned db = smem_u32(Bsm + sl * STAGE_WORDS + lr * PAD32 + lqw);
            cp16(db,      gb,     true);
            cp16(db + 16, gb + 8, true);
        }
        asm volatile("cp.async.commit_group;\n");

        const unsigned a_base = smem_u32(Asm + s * STAGE_WORDS);
        const unsigned b_base = smem_u32(Bsm + s * STAGE_WORDS);
#pragma unroll
        for (int kk = 0; kk < 2; ++kk) {
            const int kb = kk * 8;
            unsigned af[4][4], bf[4][2];
#pragma unroll
            for (int mi = 0; mi < 4; ++mi) {
                unsigned addr = a_base +
                    4u * ((wm + mi * 16 + rA) * PAD32 + kb + cA);
                ldsm4(af[mi][0], af[mi][1], af[mi][2], af[mi][3], addr);
            }
#pragma unroll
            for (int p = 0; p < 2; ++p) {
                unsigned addr = b_base +
                    4u * ((wn + p * 16 + rB) * PAD32 + kb + cB);
                ldsm4(bf[2 * p][0], bf[2 * p][1],
                      bf[2 * p + 1][0], bf[2 * p + 1][1], addr);
            }
#pragma unroll
            for (int mi = 0; mi < 4; ++mi)
#pragma unroll
                for (int ni = 0; ni < 4; ++ni)
                    mma_f16(c[mi][ni], af[mi][0], af[mi][1], af[mi][2], af[mi][3],
                            bf[ni][0], bf[ni][1]);
        }
        if (++s >= STAGES) s = 0;
    }

    // ---- epilogue ----
#pragma unroll
    for (int mi = 0; mi < 4; ++mi) {
#pragma unroll
        for (int half = 0; half < 2; ++half) {
            int r = row0 + wm + mi * 16 + g + half * 8;
            if (r < M) {
                float w0 = 0.f, w1 = 0.f;
                long y0 = 0, y1 = 0;
                if (FINAL) {
                    w0 = d_w0[r]; w1 = d_w1[r];
                    y0 = (long)d_s0[r] * NHID;
                    y1 = (long)d_s1[r] * NHID;
                }
#pragma unroll
                for (int ni = 0; ni < 4; ++ni) {
                    int colg = col0 + wn + ni * 8 + tg * 2;
                    long off = (long)r * ldc + colg;
                    float vx = c[mi][ni][half * 2 + 0];
                    float vy = c[mi][ni][half * 2 + 1];
                    if (resid) {
                        float2 rr = *(const float2*)(resid + off);
                        vx += rr.x; vy += rr.y;
                    }
                    if (FINAL) {
                        __half2 a0 = *(const __half2*)(h_ybuf + y0 + colg);
                        __half2 a1 = *(const __half2*)(h_ybuf + y1 + colg);
                        vx += w0 * __low2float(a0)  + w1 * __low2float(a1);
                        vy += w0 * __high2float(a0) + w1 * __high2float(a1);
                    }
                    if constexpr (sizeof(OutT) == 4) {
                        float2 v; v.x = vx; v.y = vy;
                        *(float2*)((float*)C + off) = v;
                    } else {
                        __half2 hv = __floats2half2_rn(vx, vy);
                        *(__half2*)((__half*)C + off) = hv;
                    }
                }
            }
        }
    }
}

// ---- O-proj (float out, residual)
__global__ __launch_bounds__(256, 2)
void hoproj_k(const __half* __restrict__ A, float* __restrict__ C,
              const float* __restrict__ resid)
{
    hgemm_body<float, false>(A, h_ow, C, resid, NT, NHID, NHID, NHID, NHID);
}

// ---- FINAL shared-down GEMM: writes out = x1 + shdown + routed
__global__ __launch_bounds__(256, 2)
void hfinal_k(const __half* __restrict__ A, float* __restrict__ C,
              const float* __restrict__ resid)
{
    hgemm_body<float, true>(A, h_sd, C, resid, NT, NSI, NSI, NSI, NHID);
}

// ---- fused Q/K/V projection (half out)
__global__ __launch_bounds__(256, 2)
void hqkv_k(const __half* __restrict__ xn)
{
    int z = blockIdx.z;
    const __half* B = (z == 0) ? h_qw : (z == 1) ? h_kw : h_vw;
    __half* C       = (z == 0) ? h_q0 : (z == 1) ? h_k0 : h_v0;
    hgemm_body<__half, false>(xn, B, C, nullptr, NT, NHID, NHID, NHID, NHID);
}

// ---- merged up-projection launch:
//   z 0..15 : MoE gate/up grouped (z = 2*e + which), needs grid.x<8, M ragged
//   z 16,17 : shared-MLP gate/up, needs grid.y<16
// grid = (NSI/BN=16, NSLOT/BM=32, 18); excess CTAs exit immediately.
__global__ __launch_bounds__(256, 2)
void hup_all_k(const __half* __restrict__ xg, const __half* __restrict__ xn)
{
    int z = blockIdx.z;
    if (z < 2 * NEXP) {
        if (blockIdx.x >= NMI / BN) return;
        int e = z >> 1;
        int M = d_cnt[e];
        int off = 0;
        for (int i = 0; i < NEXP; ++i) if (i < e) off += d_cnt[i];
        const __half* B = (z & 1) ? h_eu : h_eg;
        __half* C       = (z & 1) ? h_ubuf : h_gbuf;
        hgemm_body<__half, false>(xg + (long)off * NHID, B + (long)e * NMI * NHID,
                                  C + (long)off * NMI, nullptr,
                                  M, NHID, NHID, NHID, NMI);
    } else {
        if (blockIdx.y >= NT / BM) return;
        int w = z - 2 * NEXP;
        hgemm_body<__half, false>(xn, w ? h_su : h_sg, w ? h_us32 : h_gs32,
                                  nullptr, NT, NHID, NHID, NHID, NSI);
    }
}

// ---- MoE down grouped (half out)
__global__ __launch_bounds__(256, 2)
void hmoedn_k(const __half* __restrict__ gb)
{
    int e = blockIdx.z;
    int M = d_cnt[e];
    int off = 0;
    for (int i = 0; i < NEXP; ++i) if (i < e) off += d_cnt[i];
    hgemm_body<__half, false>(gb + (long)off * NMI, h_ed + (long)e * NHID * NMI,
                              h_ybuf + (long)off * NHID, nullptr, M, NMI, NMI, NMI, NHID);
}

// ---------------------------------------------------------------------------
// Flash attention (r8, unchanged): one CTA per (q-tile 128, head).
// ---------------------------------------------------------------------------
__global__ __launch_bounds__(256, 1)
void flash_k(const __half* __restrict__ q, const __half* __restrict__ k,
             const __half* __restrict__ v, __half* __restrict__ o)
{
    extern __shared__ unsigned fsm[];
    unsigned* Qs = fsm;
    unsigned* Ks = fsm + FTILE_W;
    unsigned* Vs = fsm + 3 * FTILE_W;

    const int qi  = blockIdx.x;
    const int bh  = blockIdx.y;
    const int b   = bh >> 3, n = bh & 7;
    const int tid = threadIdx.x, wid = tid >> 5, lane = tid & 31;
    const int g   = lane >> 2, tg = lane & 3;
    const int wq  = wid * 16;
    const int row0 = qi * 128;

    const long qbase  = ((long)b * NS + row0) * NHID + n * DHEAD;
    const long kvbase = ((long)b * NS) * NHID + n * DHEAD;

    const int rA = (lane & 7) + ((lane >> 3) & 1) * 8;
    const int cA = ((lane >> 4) & 1) * 4;
    const int rB = (lane & 7) + ((lane >> 4) & 1) * 8;
    const int cB = ((lane >> 3) & 1) * 4;
    const int rV = lane & 15;
    const int cV = (lane >> 4) * 4;

    {
        int r = tid >> 1, hh = tid & 1;
        const __half* gq = q + qbase + (long)r * NHID + hh * 64;
        unsigned dq = smem_u32(Qs + r * FPW + hh * 32);
#pragma unroll
        for (int c2 = 0; c2 < 8; ++c2) cp16(dq + c2 * 16, gq + c2 * 8, true);
    }
    {
        int r = tid >> 1, hh = tid & 1;
        const __half* gk = k + kvbase + (long)r * NHID + hh * 64;
        const __half* gv = v + kvbase + (long)r * NHID + hh * 64;
        unsigned dk = smem_u32(Ks + r * FPW + hh * 32);
        unsigned dv = smem_u32(Vs + r * FPW + hh * 32);
#pragma unroll
        for (int c2 = 0; c2 < 8; ++c2) {
            cp16(dk + c2 * 16, gk + c2 * 8, true);
            cp16(dv + c2 * 16, gv + c2 * 8, true);
        }
    }
    asm volatile("cp.async.commit_group;\n");
    asm volatile("cp.async.wait_group 0;\n");
    __syncthreads();

    float oacc[16][4];
#pragma unroll
    for (int j = 0; j < 16; ++j)
#pragma unroll
        for (int r = 0; r < 4; ++r) oacc[j][r] = 0.f;
    float m0 = -1e30f, m1 = -1e30f, l0 = 0.f, l1 = 0.f;

    for (int t = 0; t <= qi; ++t) {
        const int cur = t & 1;
        if (t + 1 <= qi) {
            int nxt = (t + 1) & 1;
            int r = tid >> 1, hh = tid & 1;
            const __half* gk = k + kvbase + ((long)(t + 1) * 128 + r) * NHID + hh * 64;
            const __half* gv = v + kvbase + ((long)(t + 1) * 128 + r) * NHID + hh * 64;
            unsigned dk = smem_u32(Ks + nxt * FTILE_W + r * FPW + hh * 32);
            unsigned dv = smem_u32(Vs + nxt * FTILE_W + r * FPW + hh * 32);
#pragma unroll
            for (int c2 = 0; c2 < 8; ++c2) {
                cp16(dk + c2 * 16, gk + c2 * 8, true);
                cp16(dv + c2 * 16, gv + c2 * 8, true);
            }
        }
        asm volatile("cp.async.commit_group;\n");

        const unsigned kbase = smem_u32(Ks + cur * FTILE_W);
        const unsigned vbase = smem_u32(Vs + cur * FTILE_W);
        const unsigned qbse  = smem_u32(Qs);

        float sacc[16][4];
#pragma unroll
        for (int j = 0; j < 16; ++j)
#pragma unroll
            for (int r = 0; r < 4; ++r) sacc[j][r] = 0.f;

#pragma unroll
        for (int ks = 0; ks < 8; ++ks) {
            unsigned qa[4];
            ldsm4(qa[0], qa[1], qa[2], qa[3],
                  qbse + 4u * ((wq + rA) * FPW + ks * 8 + cA));
#pragma unroll
            for (int p = 0; p < 8; ++p) {
                unsigned b0, b1, b2, b3;
                ldsm4(b0, b1, b2, b3,
                      kbase + 4u * ((p * 16 + rB) * FPW + ks * 8 + cB));
                mma_f16(sacc[2 * p],     qa[0], qa[1], qa[2], qa[3], b0, b1);
                mma_f16(sacc[2 * p + 1], qa[0], qa[1], qa[2], qa[3], b2, b3);
            }
        }

        if (t == qi) {
            int r0l = wq + g, r1l = wq + g + 8;
#pragma unroll
            for (int j = 0; j < 16; ++j) {
                int col = 8 * j + 2 * tg;
                if (col     > r0l) sacc[j][0] = -1e30f;
                if (col + 1 > r0l) sacc[j][1] = -1e30f;
                if (col     > r1l) sacc[j][2] = -1e30f;
                if (col + 1 > r1l) sacc[j][3] = -1e30f;
            }
        }

        float tm0 = -1e30f, tm1 = -1e30f;
#pragma unroll
        for (int j = 0; j < 16; ++j) {
            tm0 = fmaxf(tm0, fmaxf(sacc[j][0], sacc[j][1]));
            tm1 = fmaxf(tm1, fmaxf(sacc[j][2], sacc[j][3]));
        }
        tm0 = fmaxf(tm0, __shfl_xor_sync(0xffffffffu, tm0, 1));
        tm0 = fmaxf(tm0, __shfl_xor_sync(0xffffffffu, tm0, 2));
        tm1 = fmaxf(tm1, __shfl_xor_sync(0xffffffffu, tm1, 1));
        tm1 = fmaxf(tm1, __shfl_xor_sync(0xffffffffu, tm1, 2));
        float nm0 = fmaxf(m0, tm0), nm1 = fmaxf(m1, tm1);
        float al0 = __expf(m0 - nm0), al1 = __expf(m1 - nm1);

        float rs0 = 0.f, rs1 = 0.f;
        unsigned pf[8][4];
#pragma unroll
        for (int j = 0; j < 16; ++j) {
            float p0 = __expf(sacc[j][0] - nm0);
            float p1 = __expf(sacc[j][1] - nm0);
            float p2 = __expf(sacc[j][2] - nm1);
            float p3 = __expf(sacc[j][3] - nm1);
            rs0 += p0 + p1; rs1 += p2 + p3;
            int ks = j >> 1;
            if ((j & 1) == 0) { pf[ks][0] = packh2(p0, p1); pf[ks][1] = packh2(p2, p3); }
            else              { pf[ks][2] = packh2(p0, p1); pf[ks][3] = packh2(p2, p3); }
        }
        rs0 += __shfl_xor_sync(0xffffffffu, rs0, 1);
        rs0 += __shfl_xor_sync(0xffffffffu, rs0, 2);
        rs1 += __shfl_xor_sync(0xffffffffu, rs1, 1);
        rs1 += __shfl_xor_sync(0xffffffffu, rs1, 2);
        m0 = nm0; m1 = nm1;
        l0 = l0 * al0 + rs0;
        l1 = l1 * al1 + rs1;

#pragma unroll
        for (int j = 0; j < 16; ++j) {
            oacc[j][0] *= al0; oacc[j][1] *= al0;
            oacc[j][2] *= al1; oacc[j][3] *= al1;
        }

#pragma unroll
        for (int ks = 0; ks < 8; ++ks) {
#pragma unroll
            for (int p = 0; p < 8; ++p) {
                unsigned v0, v1, v2, v3;
                ldsm4t(v0, v1, v2, v3,
                       vbase + 4u * ((ks * 16 + rV) * FPW + p * 8 + cV));
                mma_f16(oacc[2 * p],     pf[ks][0], pf[ks][1], pf[ks][2], pf[ks][3], v0, v1);
                mma_f16(oacc[2 * p + 1], pf[ks][0], pf[ks][1], pf[ks][2], pf[ks][3], v2, v3);
            }
        }

        asm volatile("cp.async.wait_group 0;\n");
        __syncthreads();
    }

    float il0 = 1.f / l0, il1 = 1.f / l1;
    long obase0 = ((long)b * NS + row0 + wq + g) * NHID + n * DHEAD;
    long obase1 = obase0 + 8L * NHID;
#pragma unroll
    for (int j = 0; j < 16; ++j) {
        int col = 8 * j + 2 * tg;
        __half2 h0 = __floats2half2_rn(oacc[j][0] * il0, oacc[j][1] * il0);
        __half2 h1 = __floats2half2_rn(oacc[j][2] * il1, oacc[j][3] * il1);
        *(__half2*)(o + obase0 + col) = h0;
        *(__half2*)(o + obase1 + col) = h1;
    }
}

// ---------------------------------------------------------------------------
// fused weight conversion fp32 -> fp16, ILP=4 float4s per thread
// ---------------------------------------------------------------------------
namespace {
constexpr int W1 = NHID * NHID / 4;
constexpr int WE = NEXP * NMI * NHID / 4;
constexpr int WS = NSI * NHID / 4;
constexpr int CONV_TOT = 4 * W1 + 3 * WE + 3 * WS;
}

__device__ __forceinline__ void conv_one(
    int i,
    const float* qw, const float* kw, const float* vw, const float* ow,
    const float* eg, const float* eu, const float* ed,
    const float* sg, const float* su, const float* sd)
{
    const float* src; __half* dst; int j = i;
    if      (j < 1 * W1) { src = qw; dst = h_qw; }
    else if (j < 2 * W1) { src = kw; dst = h_kw; j -= 1 * W1; }
    else if (j < 3 * W1) { src = vw; dst = h_vw; j -= 2 * W1; }
    else if (j < 4 * W1) { src = ow; dst = h_ow; j -= 3 * W1; }
    else {
        j -= 4 * W1;
        if      (j < 1 * WE) { src = eg; dst = h_eg; }
        else if (j < 2 * WE) { src = eu; dst = h_eu; j -= 1 * WE; }
        else if (j < 3 * WE) { src = ed; dst = h_ed; j -= 2 * WE; }
        else {
            j -= 3 * WE;
            if      (j < 1 * WS) { src = sg; dst = h_sg; }
            else if (j < 2 * WS) { src = su; dst = h_su; j -= 1 * WS; }
            else                 { src = sd; dst = h_sd; j -= 2 * WS; }
        }
    }
    float4 v = *(const float4*)(src + 4 * (long)j);
    __half2 h0 = __floats2half2_rn(v.x, v.y);
    __half2 h1 = __floats2half2_rn(v.z, v.w);
    *(__half2*)(dst + 4 * (long)j)     = h0;
    *(__half2*)(dst + 4 * (long)j + 2) = h1;
}

__global__ void conv_all_k(
    const float* __restrict__ qw, const float* __restrict__ kw,
    const float* __restrict__ vw, const float* __restrict__ ow,
    const float* __restrict__ eg, const float* __restrict__ eu,
    const float* __restrict__ ed, const float* __restrict__ sg,
    const float* __restrict__ su, const float* __restrict__ sd)
{
    int base = blockIdx.x * 1024 + threadIdx.x;
#pragma unroll
    for (int u = 0; u < 4; ++u) {
        int i = base + u * 256;
        if (i < CONV_TOT)
            conv_one(i, qw, kw, vw, ow, eg, eu, ed, sg, su, sd);
    }
}

// ---------------------------------------------------------------------------
// Elementwise / reduction kernels
// ---------------------------------------------------------------------------
// rmsnorm (attention pre-norm); also zeroes d_cnt for the later routing pass
__global__ void rmsnorm_k(const float* __restrict__ x,
                          const float* __restrict__ w,
                          __half* __restrict__ oh)
{
    int t = blockIdx.x;
    if (t == 0 && threadIdx.x < NEXP) d_cnt[threadIdx.x] = 0;
    const float* xr = x + (long)t * NHID;
    __shared__ float red[256];
    float s = 0.f;
    for (int i = threadIdx.x; i < NHID; i += 256) { float v = xr[i]; s += v * v; }
    red[threadIdx.x] = s;
    __syncthreads();
    for (int st = 128; st > 0; st >>= 1) {
        if (threadIdx.x < st) red[threadIdx.x] += red[threadIdx.x + st];
        __syncthreads();
    }
    float scale = rsqrtf(red[0] / (float)NHID + 1e-6f);
    for (int i = threadIdx.x; i < NHID; i += 256)
        oh[(long)t * NHID + i] = __float2half_rn(xr[i] * scale * w[i]);
}

// rmsnorm + MoE gating fused (identical math to split version)
__global__ void rmsnorm_gate_k(const float* __restrict__ x,
                               const float* __restrict__ w,
                               const float* __restrict__ gw,
                               __half* __restrict__ oh)
{
    int t = blockIdx.x;
    int tid = threadIdx.x, wd = tid >> 5, lane = tid & 31;
    const float* xr = x + (long)t * NHID;
    __shared__ float red[256];
    __shared__ float xs[NHID];
    float s = 0.f;
    for (int i = tid; i < NHID; i += 256) { float v = xr[i]; s += v * v; }
    red[tid] = s;
    __syncthreads();
    for (int st = 128; st > 0; st >>= 1) {
        if (tid < st) red[tid] += red[tid + st];
        __syncthreads();
    }
    float scale = rsqrtf(red[0] / (float)NHID + 1e-6f);
    for (int i = tid; i < NHID; i += 256) {
        float v = xr[i] * scale * w[i];
        xs[i] = v;
        oh[(long)t * NHID + i] = __float2half_rn(v);
    }
    __syncthreads();

    const float* gr = gw + (long)wd * NHID;
    float gsum = 0.f;
    for (int i = lane; i < NHID; i += 32) gsum += xs[i] * gr[i];
    for (int o = 16; o; o >>= 1) gsum += __shfl_xor_sync(0xffffffffu, gsum, o);
    __shared__ float lg[NEXP];
    if (lane == 0) lg[wd] = gsum;
    __syncthreads();
    if (tid == 0) {
        float mx = lg[0];
        for (int e = 1; e < NEXP; ++e) mx = fmaxf(mx, lg[e]);
        float p[NEXP];
        for (int e = 0; e < NEXP; ++e) p[e] = expf(lg[e] - mx);
        int e0 = 0; float b0 = p[0];
        for (int e = 1; e < NEXP; ++e) if (p[e] > b0) { b0 = p[e]; e0 = e; }
        int e1 = -1; float b1 = -1.f;
        for (int e = 0; e < NEXP; ++e)
            if (e != e0 && p[e] > b1) { b1 = p[e]; e1 = e; }
        float denom = b0 + b1;
        d_e0[t] = e0; d_e1[t] = e1;
        d_w0[t] = b0 / denom; d_w1[t] = b1 / denom;
        d_r0[t] = atomicAdd(&d_cnt[e0], 1);
        d_r1[t] = atomicAdd(&d_cnt[e1], 1);
    }
}

// RoPE, __half2-vectorized: one (n, d-pair) element per thread.
__global__ void rope_k(const __half* __restrict__ q0, const __half* __restrict__ k0,
                       const float* __restrict__ cosp, const float* __restrict__ sinp,
                       __half* __restrict__ qr, __half* __restrict__ kr)
{
    int t = blockIdx.x;
    int s = t % NS;
    const float inv = 0.08838834764831845f;  // 1/sqrt(128)
    int i = threadIdx.x;                     // 0..255 = NHEAD*32 exactly
    int n = i >> 5, d = (i & 31) * 2;
    long base = (long)t * NHID + n * DHEAD;
    float2 c  = *(const float2*)(cosp + s * DHEAD + d);
    float2 sn = *(const float2*)(sinp + s * DHEAD + d);

    __half2 a0 = *(const __half2*)(q0 + base + d);
    __half2 a1 = *(const __half2*)(q0 + base + d + 64);
    float a0x = __low2float(a0), a0y = __high2float(a0);
    float a1x = __low2float(a1), a1y = __high2float(a1);
    *(__half2*)(qr + base + d) =
        __floats2half2_rn((a0x * c.x - a1x * sn.x) * inv,
                          (a0y * c.y - a1y * sn.y) * inv);
    *(__half2*)(qr + base + d + 64) =
        __floats2half2_rn((a1x * c.x + a0x * sn.x) * inv,
                          (a1y * c.y + a0y * sn.y) * inv);

    __half2 b0 = *(const __half2*)(k0 + base + d);
    __half2 b1 = *(const __half2*)(k0 + base + d + 64);
    float b0x = __low2float(b0), b0y = __high2float(b0);
    float b1x = __low2float(b1), b1y = __high2float(b1);
    *(__half2*)(kr + base + d) =
        __floats2half2_rn(b0x * c.x - b1x * sn.x,
                          b0y * c.y - b1y * sn.y);
    *(__half2*)(kr + base + d + 64) =
        __floats2half2_rn(b1x * c.x + b0x * sn.x,
                          b1y * c.y + b0y * sn.y);
}

// gather: computes slot = prefix(d_cnt)[e] + rank inline (d_cnt final here)
__global__ void gather_k(const __half* __restrict__ xnh)
{
    int t = blockIdx.x;
    __shared__ int ss[2];
    if (threadIdx.x == 0) {
        int pre[NEXP];
        int a = 0;
        for (int e = 0; e < NEXP; ++e) { pre[e] = a; a += d_cnt[e]; }
        int s0 = pre[d_e0[t]] + d_r0[t];
        int s1 = pre[d_e1[t]] + d_r1[t];
        d_s0[t] = s0; d_s1[t] = s1;
        ss[0] = s0; ss[1] = s1;
    }
    __syncthreads();
    const uint4* src = (const uint4*)(xnh + (long)t * NHID);
    uint4* dst0 = (uint4*)(h_xg + (long)ss[0] * NHID);
    uint4* dst1 = (uint4*)(h_xg + (long)ss[1] * NHID);
    for (int i = threadIdx.x; i < NHID / 8; i += 256) {
        uint4 v = src[i];
        dst0[i] = v;
        dst1[i] = v;
    }
}

// merged silu(g)*u over MoE + shared regions (half2 elements)
namespace {
constexpr long N2_MOE = (long)NSLOT * NMI / 2;
constexpr long N2_SH  = (long)NT * NSI / 2;
}
__global__ void silumul_all_k()
{
    long i = (long)blockIdx.x * 256 + threadIdx.x;
    const __half2* g; const __half2* u; __half2* o; long j;
    if (i < N2_MOE) {
        g = (const __half2*)h_gbuf; u = (const __half2*)h_ubuf;
        o = (__half2*)h_gb; j = i;
    } else if (i < N2_MOE + N2_SH) {
        g = (const __half2*)h_gs32; u = (const __half2*)h_us32;
        o = (__half2*)h_gs; j = i - N2_MOE;
    } else return;
    __half2 gh = g[j];
    __half2 uh = u[j];
    float g0 = __low2float(gh),  g1 = __high2float(gh);
    float u0 = __low2float(uh),  u1 = __high2float(uh);
    float r0 = g0 / (1.f + __expf(-g0)) * u0;
    float r1 = g1 / (1.f + __expf(-g1)) * u1;
    o[j] = __floats2half2_rn(r0, r1);
}

// ---------------------------------------------------------------------------
// Launch
// ---------------------------------------------------------------------------
extern "C" void kernel_launch(void* const* d_in, const int* in_sizes, int n_in,
                              void* d_out, int out_size)
{
    (void)in_sizes; (void)n_in; (void)out_size;

    const float* hs   = (const float*)d_in[0];
    const float* ln1  = (const float*)d_in[1];
    const float* ln2  = (const float*)d_in[2];
    const float* q_w  = (const float*)d_in[3];
    const float* k_w  = (const float*)d_in[4];
    const float* v_w  = (const float*)d_in[5];
    const float* o_w  = (const float*)d_in[6];
    const float* cosp = (const float*)d_in[7];
    const float* sinp = (const float*)d_in[8];
    const float* gate = (const float*)d_in[9];
    const float* eg   = (const float*)d_in[10];
    const float* eu   = (const float*)d_in[11];
    const float* ed   = (const float*)d_in[12];
    const float* sg   = (const float*)d_in[13];
    const float* su   = (const float*)d_in[14];
    const float* sd   = (const float*)d_in[15];
    float* out = (float*)d_out;

    float* x1;
    __half *hxn, *hq0, *hk0, *hv0, *hqr, *hkr, *hctx, *hxg, *hgb, *hgs;
    cudaGetSymbolAddress((void**)&x1,  d_x1);
    cudaGetSymbolAddress((void**)&hxn, h_xn);
    cudaGetSymbolAddress((void**)&hq0, h_q0);
    cudaGetSymbolAddress((void**)&hk0, h_k0);
    cudaGetSymbolAddress((void**)&hv0, h_v0);
    cudaGetSymbolAddress((void**)&hqr, h_qr);
    cudaGetSymbolAddress((void**)&hkr, h_kr);
    cudaGetSymbolAddress((void**)&hctx, h_ctx);
    cudaGetSymbolAddress((void**)&hxg, h_xg);
    cudaGetSymbolAddress((void**)&hgb, h_gb);
    cudaGetSymbolAddress((void**)&hgs, h_gs);

    cudaFuncSetAttribute(hoproj_k,
        cudaFuncAttributeMaxDynamicSharedMemorySize, SMEM_BYTES);
    cudaFuncSetAttribute(hfinal_k,
        cudaFuncAttributeMaxDynamicSharedMemorySize, SMEM_BYTES);
    cudaFuncSetAttribute(hqkv_k,
        cudaFuncAttributeMaxDynamicSharedMemorySize, SMEM_BYTES);
    cudaFuncSetAttribute(hup_all_k,
        cudaFuncAttributeMaxDynamicSharedMemorySize, SMEM_BYTES);
    cudaFuncSetAttribute(hmoedn_k,
        cudaFuncAttributeMaxDynamicSharedMemorySize, SMEM_BYTES);
    cudaFuncSetAttribute(flash_k,
        cudaFuncAttributeMaxDynamicSharedMemorySize, FLASH_SMEM);

    // ---- all weight conversions in one launch (ILP=4) ----
    conv_all_k<<<(CONV_TOT + 1023) / 1024, 256>>>(q_w, k_w, v_w, o_w,
                                                  eg, eu, ed, sg, su, sd);

    const dim3 gQKV(NHID / BN, NT / BM, 3);
    const dim3 gFlash(NS / 128, NB * NHEAD);
    const dim3 gProj(NHID / BN, NT / BM);
    const dim3 gUpAll(NSI / BN, NSLOT / BM, 2 * NEXP + 2);   // (16, 32, 18)
    const dim3 gMoeDn(NHID / BN, NSLOT / BM, NEXP);

    // ---- attention ----
    rmsnorm_k<<<NT, 256>>>(hs, ln1, hxn);          // also zeroes d_cnt
    hqkv_k<<<gQKV, 256, SMEM_BYTES>>>(hxn);
    rope_k<<<NT, 256>>>(hq0, hk0, cosp, sinp, hqr, hkr);
    flash_k<<<gFlash, 256, FLASH_SMEM>>>(hqr, hkr, hv0, hctx);
    hoproj_k<<<gProj, 256, SMEM_BYTES>>>(hctx, x1, hs);

    // ---- MoE routing (fused rmsnorm + gating), gather ----
    rmsnorm_gate_k<<<NT, 256>>>(x1, ln2, gate, hxn);
    gather_k<<<NT, 256>>>(hxn);

    // ---- merged MoE-up + shared-up GEMMs ----
    hup_all_k<<<gUpAll, 256, SMEM_BYTES>>>(hxg, hxn);

    // ---- merged silu·mul over both regions ----
    silumul_all_k<<<(unsigned)((N2_MOE + N2_SH + 255) / 256), 256>>>();

    // ---- MoE down ----
    hmoedn_k<<<gMoeDn, 256, SMEM_BYTES>>>(hgb);

    // ---- final GEMM with fused combine: out = x1 + shdown + routed ----
    hfinal_k<<<gProj, 256, SMEM_BYTES>>>(hgs, out, x1);
}

// round 16
// speedup vs baseline: 1.1765x; 1.0056x over previous
#include <cuda_runtime.h>
#include <cuda_fp16.h>
#include <math.h>

// ---------------------------------------------------------------------------
// Problem constants
// ---------------------------------------------------------------------------
namespace {
constexpr int NB = 2, NS = 1024, NHID = 1024, NHEAD = 8, DHEAD = 128;
constexpr int NEXP = 8, NMI = 1024, NSI = 2048;
constexpr int NT = NB * NS;          // 2048 tokens
constexpr int NSLOT = 2 * NT;        // 4096 expert slots (top-2)

// fp16 GEMM tile: 128x128x32(halves), 8 warps of 64x32, 4-stage cp.async
constexpr int BM = 128, BN = 128, BKH = 32;
constexpr int PAD32 = 20;                        // row stride in b32 (80B)
constexpr int STAGES = 4;
constexpr int STAGE_WORDS = BM * PAD32;          // 2560 b32 per tile-stage
constexpr int SMEM_BYTES = 2 * STAGES * STAGE_WORDS * 4;   // 81920

// flash attention smem: Q + 2xK + 2xV tiles of 128 rows x 68 words
constexpr int FPW = 68;                          // words per row (136 halves)
constexpr int FTILE_W = 128 * FPW;               // 8704 words per tile
constexpr int FLASH_SMEM = 5 * FTILE_W * 4;      // 174080 bytes

constexpr int KVCH = 4;                          // KV tiles per split chunk
}

// ---------------------------------------------------------------------------
// Static device scratch (no allocations allowed)
// ---------------------------------------------------------------------------
// fp32 buffers
__device__ float d_x1[NT * NHID];
__device__ float d_pO0[NT * NHID];    // flash split-KV partial O, chunk 0
__device__ float d_pO1[NT * NHID];    // chunk 1
__device__ float d_pm0[NB * NHEAD * NS], d_pl0[NB * NHEAD * NS];
__device__ float d_pm1[NB * NHEAD * NS], d_pl1[NB * NHEAD * NS];
// fp16 weights
__device__ __half h_qw[NHID * NHID];
__device__ __half h_kw[NHID * NHID];
__device__ __half h_vw[NHID * NHID];
__device__ __half h_ow[NHID * NHID];
__device__ __half h_eg[NEXP * NMI * NHID];
__device__ __half h_eu[NEXP * NMI * NHID];
__device__ __half h_ed[NEXP * NHID * NMI];
__device__ __half h_sg[NSI * NHID];
__device__ __half h_su[NSI * NHID];
__device__ __half h_sd[NHID * NSI];
// fp16 activations
__device__ __half h_xn[NT * NHID];
__device__ __half h_q0[NT * NHID];    // QKV GEMM outputs, (t, head*128+d)
__device__ __half h_k0[NT * NHID];
__device__ __half h_v0[NT * NHID];
__device__ __half h_qr[NT * NHID];    // rope'd + scaled
__device__ __half h_kr[NT * NHID];
__device__ __half h_ctx[NT * NHID];   // flash output
__device__ __half h_xg[NSLOT * NHID];
__device__ __half h_gbuf[NSLOT * NMI];   // MoE gate GEMM out (half)
__device__ __half h_ubuf[NSLOT * NMI];   // MoE up GEMM out (half)
__device__ __half h_gb[NSLOT * NMI];     // silu(g)*u (half)
__device__ __half h_ybuf[NSLOT * NHID];  // MoE down out (half)
__device__ __half h_gs32[NT * NSI];      // shared gate GEMM out (half)
__device__ __half h_us32[NT * NSI];      // shared up GEMM out (half)
__device__ __half h_gs[NT * NSI];        // silu(g)*u (half)
// routing state
__device__ int   d_cnt[NEXP];
__device__ int   d_e0[NT], d_e1[NT], d_r0[NT], d_r1[NT], d_s0[NT], d_s1[NT];
__device__ float d_w0[NT], d_w1[NT];

// ---------------------------------------------------------------------------
// helpers
// ---------------------------------------------------------------------------
__device__ __forceinline__ unsigned smem_u32(const void* p) {
    return (unsigned)__cvta_generic_to_shared(p);
}

__device__ __forceinline__ void cp16(unsigned dst, const void* src, bool pred) {
    int sz = pred ? 16 : 0;
    asm volatile("cp.async.cg.shared.global [%0], [%1], 16, %2;\n"
                 :: "r"(dst), "l"(src), "r"(sz));
}

__device__ __forceinline__ void ldsm4(unsigned& r0, unsigned& r1,
                                      unsigned& r2, unsigned& r3, unsigned addr)
{
    asm volatile("ldmatrix.sync.aligned.m8n8.x4.shared.b16 {%0,%1,%2,%3}, [%4];"
                 : "=r"(r0), "=r"(r1), "=r"(r2), "=r"(r3) : "r"(addr));
}

__device__ __forceinline__ void ldsm4t(unsigned& r0, unsigned& r1,
                                       unsigned& r2, unsigned& r3, unsigned addr)
{
    asm volatile("ldmatrix.sync.aligned.m8n8.x4.trans.shared.b16 {%0,%1,%2,%3}, [%4];"
                 : "=r"(r0), "=r"(r1), "=r"(r2), "=r"(r3) : "r"(addr));
}

__device__ __forceinline__ void mma_f16(float c[4],
    unsigned a0, unsigned a1, unsigned a2, unsigned a3,
    unsigned b0, unsigned b1)
{
    asm volatile(
        "mma.sync.aligned.m16n8k16.row.col.f32.f16.f16.f32 "
        "{%0,%1,%2,%3}, {%4,%5,%6,%7}, {%8,%9}, {%0,%1,%2,%3};\n"
        : "+f"(c[0]), "+f"(c[1]), "+f"(c[2]), "+f"(c[3])
        : "r"(a0), "r"(a1), "r"(a2), "r"(a3), "r"(b0), "r"(b1));
}

__device__ __forceinline__ unsigned packh2(float a, float b) {
    __half2 h = __floats2half2_rn(a, b);
    return *reinterpret_cast<unsigned*>(&h);
}

// ---------------------------------------------------------------------------
// FP16 tensor-core GEMM:  C[M,N] = A[M,K] * B^T  (B stored (N,K) row-major,
// offsets in HALVES).  128x128 block, 8 warps of 64x32 (4x4 m16n8k16),
// 4-stage cp.async, ldmatrix operand loads.  OutT = float or __half.
// FINAL: fuse the MoE combine — out = resid + gemm + w0*yb[s0] + w1*yb[s1].
// ---------------------------------------------------------------------------
template <typename OutT, bool FINAL>
__device__ __forceinline__ void hgemm_body(
    const __half* __restrict__ A, const __half* __restrict__ Bm,
    OutT* __restrict__ C, const float* __restrict__ resid,
    int M, int K, int lda, int ldb, int ldc)
{
    extern __shared__ unsigned smu[];
    unsigned* Asm = smu;                         // [STAGES][BM][PAD32]
    unsigned* Bsm = smu + STAGES * STAGE_WORDS;

    const int tid  = threadIdx.x;
    const int wid  = tid >> 5;
    const int lane = tid & 31;
    const int g    = lane >> 2;
    const int tg   = lane & 3;
    const int wm   = (wid & 1) * 64;
    const int wn   = (wid >> 1) * 32;
    const int row0 = blockIdx.y * BM;
    const int col0 = blockIdx.x * BN;
    if (row0 >= M) return;

    const int rA = (lane & 7) + ((lane >> 3) & 1) * 8;
    const int cA = ((lane >> 4) & 1) * 4;
    const int rB = (lane & 7) + ((lane >> 4) & 1) * 8;
    const int cB = ((lane >> 3) & 1) * 4;

    float c[4][4][4];
#pragma unroll
    for (int mi = 0; mi < 4; ++mi)
#pragma unroll
        for (int ni = 0; ni < 4; ++ni)
#pragma unroll
            for (int r = 0; r < 4; ++r) c[mi][ni][r] = 0.f;

    const int lr = tid >> 1;
    const int lqh = (tid & 1) * 16;
    const int lqw = (tid & 1) * 8;
    const int niter = K / BKH;

#pragma unroll
    for (int st = 0; st < STAGES - 1; ++st) {
        if (st < niter) {
            const int k0 = st * BKH;
            const __half* ga = A + (long)(row0 + lr) * lda + k0 + lqh;
            unsigned da = smem_u32(Asm + st * STAGE_WORDS + lr * PAD32 + lqw);
            bool pa = (row0 + lr) < M;
            cp16(da,      ga,     pa);
            cp16(da + 16, ga + 8, pa);
            const __half* gb = Bm + (long)(col0 + lr) * ldb + k0 + lqh;
            unsigned db = smem_u32(Bsm + st * STAGE_WORDS + lr * PAD32 + lqw);
            cp16(db,      gb,     true);
            cp16(db + 16, gb + 8, true);
        }
        asm volatile("cp.async.commit_group;\n");
    }

    int s = 0;
    for (int it = 0; it < niter; ++it) {
        asm volatile("cp.async.wait_group 2;\n");
        __syncthreads();

        const int pf = it + STAGES - 1;
        if (pf < niter) {
            int sl = s + STAGES - 1; if (sl >= STAGES) sl -= STAGES;
            const int k0 = pf * BKH;
            const __half* ga = A + (long)(row0 + lr) * lda + k0 + lqh;
            unsigned da = smem_u32(Asm + sl * STAGE_WORDS + lr * PAD32 + lqw);
            bool pa = (row0 + lr) < M;
            cp16(da,      ga,     pa);
            cp16(da + 16, ga + 8, pa);
            const __half* gb = Bm + (long)(col0 + lr) * ldb + k0 + lqh;
            unsigned db = smem_u32(Bsm + sl * STAGE_WORDS + lr * PAD32 + lqw);
            cp16(db,      gb,     true);
            cp16(db + 16, gb + 8, true);
        }
        asm volatile("cp.async.commit_group;\n");

        const unsigned a_base = smem_u32(Asm + s * STAGE_WORDS);
        const unsigned b_base = smem_u32(Bsm + s * STAGE_WORDS);
#pragma unroll
        for (int kk = 0; kk < 2; ++kk) {
            const int kb = kk * 8;
            unsigned af[4][4], bf[4][2];
#pragma unroll
            for (int mi = 0; mi < 4; ++mi) {
                unsigned addr = a_base +
                    4u * ((wm + mi * 16 + rA) * PAD32 + kb + cA);
                ldsm4(af[mi][0], af[mi][1], af[mi][2], af[mi][3], addr);
            }
#pragma unroll
            for (int p = 0; p < 2; ++p) {
                unsigned addr = b_base +
                    4u * ((wn + p * 16 + rB) * PAD32 + kb + cB);
                ldsm4(bf[2 * p][0], bf[2 * p][1],
                      bf[2 * p + 1][0], bf[2 * p + 1][1], addr);
            }
#pragma unroll
            for (int mi = 0; mi < 4; ++mi)
#pragma unroll
                for (int ni = 0; ni < 4; ++ni)
                    mma_f16(c[mi][ni], af[mi][0], af[mi][1], af[mi][2], af[mi][3],
                            bf[ni][0], bf[ni][1]);
        }
        if (++s >= STAGES) s = 0;
    }

    // ---- epilogue ----
#pragma unroll
    for (int mi = 0; mi < 4; ++mi) {
#pragma unroll
        for (int half = 0; half < 2; ++half) {
            int r = row0 + wm + mi * 16 + g + half * 8;
            if (r < M) {
                float w0 = 0.f, w1 = 0.f;
                long y0 = 0, y1 = 0;
                if (FINAL) {
                    w0 = d_w0[r]; w1 = d_w1[r];
                    y0 = (long)d_s0[r] * NHID;
                    y1 = (long)d_s1[r] * NHID;
                }
#pragma unroll
                for (int ni = 0; ni < 4; ++ni) {
                    int colg = col0 + wn + ni * 8 + tg * 2;
                    long off = (long)r * ldc + colg;
                    float vx = c[mi][ni][half * 2 + 0];
                    float vy = c[mi][ni][half * 2 + 1];
                    if (resid) {
                        float2 rr = *(const float2*)(resid + off);
                        vx += rr.x; vy += rr.y;
                    }
                    if (FINAL) {
                        __half2 a0 = *(const __half2*)(h_ybuf + y0 + colg);
                        __half2 a1 = *(const __half2*)(h_ybuf + y1 + colg);
                        vx += w0 * __low2float(a0)  + w1 * __low2float(a1);
                        vy += w0 * __high2float(a0) + w1 * __high2float(a1);
                    }
                    if constexpr (sizeof(OutT) == 4) {
                        float2 v; v.x = vx; v.y = vy;
                        *(float2*)((float*)C + off) = v;
                    } else {
                        __half2 hv = __floats2half2_rn(vx, vy);
                        *(__half2*)((__half*)C + off) = hv;
                    }
                }
            }
        }
    }
}

// ---- O-proj (float out, residual)
__global__ __launch_bounds__(256, 2)
void hoproj_k(const __half* __restrict__ A, float* __restrict__ C,
              const float* __restrict__ resid)
{
    hgemm_body<float, false>(A, h_ow, C, resid, NT, NHID, NHID, NHID, NHID);
}

// ---- FINAL shared-down GEMM: writes out = x1 + shdown + routed
__global__ __launch_bounds__(256, 2)
void hfinal_k(const __half* __restrict__ A, float* __restrict__ C,
              const float* __restrict__ resid)
{
    hgemm_body<float, true>(A, h_sd, C, resid, NT, NSI, NSI, NSI, NHID);
}

// ---- fused Q/K/V projection (half out)
__global__ __launch_bounds__(256, 2)
void hqkv_k(const __half* __restrict__ xn)
{
    int z = blockIdx.z;
    const __half* B = (z == 0) ? h_qw : (z == 1) ? h_kw : h_vw;
    __half* C       = (z == 0) ? h_q0 : (z == 1) ? h_k0 : h_v0;
    hgemm_body<__half, false>(xn, B, C, nullptr, NT, NHID, NHID, NHID, NHID);
}

// ---- merged up-projection launch (MoE grouped + shared)
__global__ __launch_bounds__(256, 2)
void hup_all_k(const __half* __restrict__ xg, const __half* __restrict__ xn)
{
    int z = blockIdx.z;
    if (z < 2 * NEXP) {
        if (blockIdx.x >= NMI / BN) return;
        int e = z >> 1;
        int M = d_cnt[e];
        int off = 0;
        for (int i = 0; i < NEXP; ++i) if (i < e) off += d_cnt[i];
        const __half* B = (z & 1) ? h_eu : h_eg;
        __half* C       = (z & 1) ? h_ubuf : h_gbuf;
        hgemm_body<__half, false>(xg + (long)off * NHID, B + (long)e * NMI * NHID,
                                  C + (long)off * NMI, nullptr,
                                  M, NHID, NHID, NHID, NMI);
    } else {
        if (blockIdx.y >= NT / BM) return;
        int w = z - 2 * NEXP;
        hgemm_body<__half, false>(xn, w ? h_su : h_sg, w ? h_us32 : h_gs32,
                                  nullptr, NT, NHID, NHID, NHID, NSI);
    }
}

// ---- MoE down grouped (half out)
__global__ __launch_bounds__(256, 2)
void hmoedn_k(const __half* __restrict__ gb)
{
    int e = blockIdx.z;
    int M = d_cnt[e];
    int off = 0;
    for (int i = 0; i < NEXP; ++i) if (i < e) off += d_cnt[i];
    hgemm_body<__half, false>(gb + (long)off * NMI, h_ed + (long)e * NHID * NMI,
                              h_ybuf + (long)off * NHID, nullptr, M, NMI, NMI, NMI, NHID);
}

// ---------------------------------------------------------------------------
// Flash attention, split-KV: grid (qi=8, bh=16, chunk=2). Chunk 0 covers KV
// tiles [0, min(qi+1,4)), chunk 1 covers [4, qi+1) (qi>=4 only). Writes
// UNNORMALIZED fp32 partial O + per-row (m, l); merge_k recombines.
// ---------------------------------------------------------------------------
__global__ __launch_bounds__(256, 1)
void flash_part_k(const __half* __restrict__ q, const __half* __restrict__ k,
                  const __half* __restrict__ v)
{
    const int qi  = blockIdx.x;
    const int ch  = blockIdx.z;
    const int t0  = ch * KVCH;
    const int t1  = min(qi + 1, t0 + KVCH);
    if (t0 >= qi + 1) return;

    extern __shared__ unsigned fsm[];
    unsigned* Qs = fsm;
    unsigned* Ks = fsm + FTILE_W;
    unsigned* Vs = fsm + 3 * FTILE_W;

    const int bh  = blockIdx.y;
    const int b   = bh >> 3, n = bh & 7;
    const int tid = threadIdx.x, wid = tid >> 5, lane = tid & 31;
    const int g   = lane >> 2, tg = lane & 3;
    const int wq  = wid * 16;
    const int row0 = qi * 128;

    const long qbase  = ((long)b * NS + row0) * NHID + n * DHEAD;
    const long kvbase = ((long)b * NS) * NHID + n * DHEAD;

    const int rA = (lane & 7) + ((lane >> 3) & 1) * 8;
    const int cA = ((lane >> 4) & 1) * 4;
    const int rB = (lane & 7) + ((lane >> 4) & 1) * 8;
    const int cB = ((lane >> 3) & 1) * 4;
    const int rV = lane & 15;
    const int cV = (lane >> 4) * 4;

    {
        int r = tid >> 1, hh = tid & 1;
        const __half* gq = q + qbase + (long)r * NHID + hh * 64;
        unsigned dq = smem_u32(Qs + r * FPW + hh * 32);
#pragma unroll
        for (int c2 = 0; c2 < 8; ++c2) cp16(dq + c2 * 16, gq + c2 * 8, true);
    }
    {
        int r = tid >> 1, hh = tid & 1;
        const __half* gk = k + kvbase + ((long)t0 * 128 + r) * NHID + hh * 64;
        const __half* gv = v + kvbase + ((long)t0 * 128 + r) * NHID + hh * 64;
        unsigned dk = smem_u32(Ks + r * FPW + hh * 32);
        unsigned dv = smem_u32(Vs + r * FPW + hh * 32);
#pragma unroll
        for (int c2 = 0; c2 < 8; ++c2) {
            cp16(dk + c2 * 16, gk + c2 * 8, true);
            cp16(dv + c2 * 16, gv + c2 * 8, true);
        }
    }
    asm volatile("cp.async.commit_group;\n");
    asm volatile("cp.async.wait_group 0;\n");
    __syncthreads();

    float oacc[16][4];
#pragma unroll
    for (int j = 0; j < 16; ++j)
#pragma unroll
        for (int r = 0; r < 4; ++r) oacc[j][r] = 0.f;
    float m0 = -1e30f, m1 = -1e30f, l0 = 0.f, l1 = 0.f;

    for (int t = t0; t < t1; ++t) {
        const int cur = (t - t0) & 1;
        if (t + 1 < t1) {
            int nxt = (t + 1 - t0) & 1;
            int r = tid >> 1, hh = tid & 1;
            const __half* gk = k + kvbase + ((long)(t + 1) * 128 + r) * NHID + hh * 64;
            const __half* gv = v + kvbase + ((long)(t + 1) * 128 + r) * NHID + hh * 64;
            unsigned dk = smem_u32(Ks + nxt * FTILE_W + r * FPW + hh * 32);
            unsigned dv = smem_u32(Vs + nxt * FTILE_W + r * FPW + hh * 32);
#pragma unroll
            for (int c2 = 0; c2 < 8; ++c2) {
                cp16(dk + c2 * 16, gk + c2 * 8, true);
                cp16(dv + c2 * 16, gv + c2 * 8, true);
            }
        }
        asm volatile("cp.async.commit_group;\n");

        const unsigned kbase = smem_u32(Ks + cur * FTILE_W);
        const unsigned vbase = smem_u32(Vs + cur * FTILE_W);
        const unsigned qbse  = smem_u32(Qs);

        float sacc[16][4];
#pragma unroll
        for (int j = 0; j < 16; ++j)
#pragma unroll
            for (int r = 0; r < 4; ++r) sacc[j][r] = 0.f;

#pragma unroll
        for (int ks = 0; ks < 8; ++ks) {
            unsigned qa[4];
            ldsm4(qa[0], qa[1], qa[2], qa[3],
                  qbse + 4u * ((wq + rA) * FPW + ks * 8 + cA));
#pragma unroll
            for (int p = 0; p < 8; ++p) {
                unsigned b0, b1, b2, b3;
                ldsm4(b0, b1, b2, b3,
                      kbase + 4u * ((p * 16 + rB) * FPW + ks * 8 + cB));
                mma_f16(sacc[2 * p],     qa[0], qa[1], qa[2], qa[3], b0, b1);
                mma_f16(sacc[2 * p + 1], qa[0], qa[1], qa[2], qa[3], b2, b3);
            }
        }

        if (t == qi) {
            int r0l = wq + g, r1l = wq + g + 8;
#pragma unroll
            for (int j = 0; j < 16; ++j) {
                int col = 8 * j + 2 * tg;
                if (col     > r0l) sacc[j][0] = -1e30f;
                if (col + 1 > r0l) sacc[j][1] = -1e30f;
                if (col     > r1l) sacc[j][2] = -1e30f;
                if (col + 1 > r1l) sacc[j][3] = -1e30f;
            }
        }

        float tm0 = -1e30f, tm1 = -1e30f;
#pragma unroll
        for (int j = 0; j < 16; ++j) {
            tm0 = fmaxf(tm0, fmaxf(sacc[j][0], sacc[j][1]));
            tm1 = fmaxf(tm1, fmaxf(sacc[j][2], sacc[j][3]));
        }
        tm0 = fmaxf(tm0, __shfl_xor_sync(0xffffffffu, tm0, 1));
        tm0 = fmaxf(tm0, __shfl_xor_sync(0xffffffffu, tm0, 2));
        tm1 = fmaxf(tm1, __shfl_xor_sync(0xffffffffu, tm1, 1));
        tm1 = fmaxf(tm1, __shfl_xor_sync(0xffffffffu, tm1, 2));
        float nm0 = fmaxf(m0, tm0), nm1 = fmaxf(m1, tm1);
        float al0 = __expf(m0 - nm0), al1 = __expf(m1 - nm1);

        float rs0 = 0.f, rs1 = 0.f;
        unsigned pf[8][4];
#pragma unroll
        for (int j = 0; j < 16; ++j) {
            float p0 = __expf(sacc[j][0] - nm0);
            float p1 = __expf(sacc[j][1] - nm0);
            float p2 = __expf(sacc[j][2] - nm1);
            float p3 = __expf(sacc[j][3] - nm1);
            rs0 += p0 + p1; rs1 += p2 + p3;
            int ks = j >> 1;
            if ((j & 1) == 0) { pf[ks][0] = packh2(p0, p1); pf[ks][1] = packh2(p2, p3); }
            else              { pf[ks][2] = packh2(p0, p1); pf[ks][3] = packh2(p2, p3); }
        }
        rs0 += __shfl_xor_sync(0xffffffffu, rs0, 1);
        rs0 += __shfl_xor_sync(0xffffffffu, rs0, 2);
        rs1 += __shfl_xor_sync(0xffffffffu, rs1, 1);
        rs1 += __shfl_xor_sync(0xffffffffu, rs1, 2);
        m0 = nm0; m1 = nm1;
        l0 = l0 * al0 + rs0;
        l1 = l1 * al1 + rs1;

#pragma unroll
        for (int j = 0; j < 16; ++j) {
            oacc[j][0] *= al0; oacc[j][1] *= al0;
            oacc[j][2] *= al1; oacc[j][3] *= al1;
        }

#pragma unroll
        for (int ks = 0; ks < 8; ++ks) {
#pragma unroll
            for (int p = 0; p < 8; ++p) {
                unsigned v0, v1, v2, v3;
                ldsm4t(v0, v1, v2, v3,
                       vbase + 4u * ((ks * 16 + rV) * FPW + p * 8 + cV));
                mma_f16(oacc[2 * p],     pf[ks][0], pf[ks][1], pf[ks][2], pf[ks][3], v0, v1);
                mma_f16(oacc[2 * p + 1], pf[ks][0], pf[ks][1], pf[ks][2], pf[ks][3], v2, v3);
            }
        }

        asm volatile("cp.async.wait_group 0;\n");
        __syncthreads();
    }

    // ---- store UNNORMALIZED partial O (fp32) + per-row m, l ----
    float* pO = ch ? d_pO1 : d_pO0;
    float* pm = ch ? d_pm1 : d_pm0;
    float* pl = ch ? d_pl1 : d_pl0;
    long obase0 = ((long)b * NS + row0 + wq + g) * NHID + n * DHEAD;
    long obase1 = obase0 + 8L * NHID;
#pragma unroll
    for (int j = 0; j < 16; ++j) {
        int col = 8 * j + 2 * tg;
        float2 v0; v0.x = oacc[j][0]; v0.y = oacc[j][1];
        float2 v1; v1.x = oacc[j][2]; v1.y = oacc[j][3];
        *(float2*)(pO + obase0 + col) = v0;
        *(float2*)(pO + obase1 + col) = v1;
    }
    if (tg == 0) {
        int midx = bh * NS + row0 + wq + g;
        pm[midx]     = m0; pl[midx]     = l0;
        pm[midx + 8] = m1; pl[midx + 8] = l1;
    }
}

// ---- merge split-KV partials into half ctx; one block per token ----
__global__ void flash_merge_k(__half* __restrict__ o)
{
    int t = blockIdx.x;
    int b = t / NS, s = t % NS;
    int qi = s >> 7;
    __shared__ float sc0[NHEAD], sc1[NHEAD];
    int tid = threadIdx.x;
    if (tid < NHEAD) {
        int midx = (b * NHEAD + tid) * NS + s;
        if (qi < KVCH) {
            sc0[tid] = 1.f / d_pl0[midx];
            sc1[tid] = 0.f;
        } else {
            float m0 = d_pm0[midx], m1 = d_pm1[midx];
            float M = fmaxf(m0, m1);
            float e0 = __expf(m0 - M), e1 = __expf(m1 - M);
            float inv = 1.f / (e0 * d_pl0[midx] + e1 * d_pl1[midx]);
            sc0[tid] = e0 * inv;
            sc1[tid] = e1 * inv;
        }
    }
    __syncthreads();
    long base = (long)t * NHID;
    bool two = (qi >= KVCH);
#pragma unroll
    for (int u = 0; u < 2; ++u) {
        int e2 = tid + u * 256;              // half2 index 0..511
        int n = e2 >> 6;                     // head
        long off = base + 2 * e2;
        float2 v = *(const float2*)(d_pO0 + off);
        float r0 = v.x * sc0[n], r1 = v.y * sc0[n];
        if (two) {
            float2 w = *(const float2*)(d_pO1 + off);
            r0 += w.x * sc1[n]; r1 += w.y * sc1[n];
        }
        *(__half2*)(o + off) = __floats2half2_rn(r0, r1);
    }
}

// ---------------------------------------------------------------------------
// fused weight conversion fp32 -> fp16, ILP=4 float4s per thread
// ---------------------------------------------------------------------------
namespace {
constexpr int W1 = NHID * NHID / 4;
constexpr int WE = NEXP * NMI * NHID / 4;
constexpr int WS = NSI * NHID / 4;
constexpr int CONV_TOT = 4 * W1 + 3 * WE + 3 * WS;
}

__device__ __forceinline__ void conv_one(
    int i,
    const float* qw, const float* kw, const float* vw, const float* ow,
    const float* eg, const float* eu, const float* ed,
    const float* sg, const float* su, const float* sd)
{
    const float* src; __half* dst; int j = i;
    if      (j < 1 * W1) { src = qw; dst = h_qw; }
    else if (j < 2 * W1) { src = kw; dst = h_kw; j -= 1 * W1; }
    else if (j < 3 * W1) { src = vw; dst = h_vw; j -= 2 * W1; }
    else if (j < 4 * W1) { src = ow; dst = h_ow; j -= 3 * W1; }
    else {
        j -= 4 * W1;
        if      (j < 1 * WE) { src = eg; dst = h_eg; }
        else if (j < 2 * WE) { src = eu; dst = h_eu; j -= 1 * WE; }
        else if (j < 3 * WE) { src = ed; dst = h_ed; j -= 2 * WE; }
        else {
            j -= 3 * WE;
            if      (j < 1 * WS) { src = sg; dst = h_sg; }
            else if (j < 2 * WS) { src = su; dst = h_su; j -= 1 * WS; }
            else                 { src = sd; dst = h_sd; j -= 2 * WS; }
        }
    }
    float4 v = *(const float4*)(src + 4 * (long)j);
    __half2 h0 = __floats2half2_rn(v.x, v.y);
    __half2 h1 = __floats2half2_rn(v.z, v.w);
    *(__half2*)(dst + 4 * (long)j)     = h0;
    *(__half2*)(dst + 4 * (long)j + 2) = h1;
}

__global__ void conv_all_k(
    const float* __restrict__ qw, const float* __restrict__ kw,
    const float* __restrict__ vw, const float* __restrict__ ow,
    const float* __restrict__ eg, const float* __restrict__ eu,
    const float* __restrict__ ed, const float* __restrict__ sg,
    const float* __restrict__ su, const float* __restrict__ sd)
{
    int base = blockIdx.x * 1024 + threadIdx.x;
#pragma unroll
    for (int u = 0; u < 4; ++u) {
        int i = base + u * 256;
        if (i < CONV_TOT)
            conv_one(i, qw, kw, vw, ow, eg, eu, ed, sg, su, sd);
    }
}

// ---------------------------------------------------------------------------
// Elementwise / reduction kernels
// ---------------------------------------------------------------------------
__global__ void rmsnorm_k(const float* __restrict__ x,
                          const float* __restrict__ w,
                          __half* __restrict__ oh)
{
    int t = blockIdx.x;
    if (t == 0 && threadIdx.x < NEXP) d_cnt[threadIdx.x] = 0;
    const float* xr = x + (long)t * NHID;
    __shared__ float red[256];
    float s = 0.f;
    for (int i = threadIdx.x; i < NHID; i += 256) { float v = xr[i]; s += v * v; }
    red[threadIdx.x] = s;
    __syncthreads();
    for (int st = 128; st > 0; st >>= 1) {
        if (threadIdx.x < st) red[threadIdx.x] += red[threadIdx.x + st];
        __syncthreads();
    }
    float scale = rsqrtf(red[0] / (float)NHID + 1e-6f);
    for (int i = threadIdx.x; i < NHID; i += 256)
        oh[(long)t * NHID + i] = __float2half_rn(xr[i] * scale * w[i]);
}

__global__ void rmsnorm_gate_k(const float* __restrict__ x,
                               const float* __restrict__ w,
                               const float* __restrict__ gw,
                               __half* __restrict__ oh)
{
    int t = blockIdx.x;
    int tid = threadIdx.x, wd = tid >> 5, lane = tid & 31;
    const float* xr = x + (long)t * NHID;
    __shared__ float red[256];
    __shared__ float xs[NHID];
    float s = 0.f;
    for (int i = tid; i < NHID; i += 256) { float v = xr[i]; s += v * v; }
    red[tid] = s;
    __syncthreads();
    for (int st = 128; st > 0; st >>= 1) {
        if (tid < st) red[tid] += red[tid + st];
        __syncthreads();
    }
    float scale = rsqrtf(red[0] / (float)NHID + 1e-6f);
    for (int i = tid; i < NHID; i += 256) {
        float v = xr[i] * scale * w[i];
        xs[i] = v;
        oh[(long)t * NHID + i] = __float2half_rn(v);
    }
    __syncthreads();

    const float* gr = gw + (long)wd * NHID;
    float gsum = 0.f;
    for (int i = lane; i < NHID; i += 32) gsum += xs[i] * gr[i];
    for (int o = 16; o; o >>= 1) gsum += __shfl_xor_sync(0xffffffffu, gsum, o);
    __shared__ float lg[NEXP];
    if (lane == 0) lg[wd] = gsum;
    __syncthreads();
    if (tid == 0) {
        float mx = lg[0];
        for (int e = 1; e < NEXP; ++e) mx = fmaxf(mx, lg[e]);
        float p[NEXP];
        for (int e = 0; e < NEXP; ++e) p[e] = expf(lg[e] - mx);
        int e0 = 0; float b0 = p[0];
        for (int e = 1; e < NEXP; ++e) if (p[e] > b0) { b0 = p[e]; e0 = e; }
        int e1 = -1; float b1 = -1.f;
        for (int e = 0; e < NEXP; ++e)
            if (e != e0 && p[e] > b1) { b1 = p[e]; e1 = e; }
        float denom = b0 + b1;
        d_e0[t] = e0; d_e1[t] = e1;
        d_w0[t] = b0 / denom; d_w1[t] = b1 / denom;
        d_r0[t] = atomicAdd(&d_cnt[e0], 1);
        d_r1[t] = atomicAdd(&d_cnt[e1], 1);
    }
}

// RoPE, __half2-vectorized: one (n, d-pair) element per thread.
__global__ void rope_k(const __half* __restrict__ q0, const __half* __restrict__ k0,
                       const float* __restrict__ cosp, const float* __restrict__ sinp,
                       __half* __restrict__ qr, __half* __restrict__ kr)
{
    int t = blockIdx.x;
    int s = t % NS;
    const float inv = 0.08838834764831845f;  // 1/sqrt(128)
    int i = threadIdx.x;                     // 0..255 = NHEAD*32 exactly
    int n = i >> 5, d = (i & 31) * 2;
    long base = (long)t * NHID + n * DHEAD;
    float2 c  = *(const float2*)(cosp + s * DHEAD + d);
    float2 sn = *(const float2*)(sinp + s * DHEAD + d);

    __half2 a0 = *(const __half2*)(q0 + base + d);
    __half2 a1 = *(const __half2*)(q0 + base + d + 64);
    float a0x = __low2float(a0), a0y = __high2float(a0);
    float a1x = __low2float(a1), a1y = __high2float(a1);
    *(__half2*)(qr + base + d) =
        __floats2half2_rn((a0x * c.x - a1x * sn.x) * inv,
                          (a0y * c.y - a1y * sn.y) * inv);
    *(__half2*)(qr + base + d + 64) =
        __floats2half2_rn((a1x * c.x + a0x * sn.x) * inv,
                          (a1y * c.y + a0y * sn.y) * inv);

    __half2 b0 = *(const __half2*)(k0 + base + d);
    __half2 b1 = *(const __half2*)(k0 + base + d + 64);
    float b0x = __low2float(b0), b0y = __high2float(b0);
    float b1x = __low2float(b1), b1y = __high2float(b1);
    *(__half2*)(kr + base + d) =
        __floats2half2_rn(b0x * c.x - b1x * sn.x,
                          b0y * c.y - b1y * sn.y);
    *(__half2*)(kr + base + d + 64) =
        __floats2half2_rn(b1x * c.x + b0x * sn.x,
                          b1y * c.y + b0y * sn.y);
}

// gather: computes slot = prefix(d_cnt)[e] + rank inline (d_cnt final here)
__global__ void gather_k(const __half* __restrict__ xnh)
{
    int t = blockIdx.x;
    __shared__ int ss[2];
    if (threadIdx.x == 0) {
        int pre[NEXP];
        int a = 0;
        for (int e = 0; e < NEXP; ++e) { pre[e] = a; a += d_cnt[e]; }
        int s0 = pre[d_e0[t]] + d_r0[t];
        int s1 = pre[d_e1[t]] + d_r1[t];
        d_s0[t] = s0; d_s1[t] = s1;
        ss[0] = s0; ss[1] = s1;
    }
    __syncthreads();
    const uint4* src = (const uint4*)(xnh + (long)t * NHID);
    uint4* dst0 = (uint4*)(h_xg + (long)ss[0] * NHID);
    uint4* dst1 = (uint4*)(h_xg + (long)ss[1] * NHID);
    for (int i = threadIdx.x; i < NHID / 8; i += 256) {
        uint4 v = src[i];
        dst0[i] = v;
        dst1[i] = v;
    }
}

// merged silu(g)*u over MoE + shared regions (half2 elements)
namespace {
constexpr long N2_MOE = (long)NSLOT * NMI / 2;
constexpr long N2_SH  = (long)NT * NSI / 2;
}
__global__ void silumul_all_k()
{
    long i = (long)blockIdx.x * 256 + threadIdx.x;
    const __half2* g; const __half2* u; __half2* o; long j;
    if (i < N2_MOE) {
        g = (const __half2*)h_gbuf; u = (const __half2*)h_ubuf;
        o = (__half2*)h_gb; j = i;
    } else if (i < N2_MOE + N2_SH) {
        g = (const __half2*)h_gs32; u = (const __half2*)h_us32;
        o = (__half2*)h_gs; j = i - N2_MOE;
    } else return;
    __half2 gh = g[j];
    __half2 uh = u[j];
    float g0 = __low2float(gh),  g1 = __high2float(gh);
    float u0 = __low2float(uh),  u1 = __high2float(uh);
    float r0 = g0 / (1.f + __expf(-g0)) * u0;
    float r1 = g1 / (1.f + __expf(-g1)) * u1;
    o[j] = __floats2half2_rn(r0, r1);
}

// ---------------------------------------------------------------------------
// Launch
// ---------------------------------------------------------------------------
extern "C" void kernel_launch(void* const* d_in, const int* in_sizes, int n_in,
                              void* d_out, int out_size)
{
    (void)in_sizes; (void)n_in; (void)out_size;

    const float* hs   = (const float*)d_in[0];
    const float* ln1  = (const float*)d_in[1];
    const float* ln2  = (const float*)d_in[2];
    const float* q_w  = (const float*)d_in[3];
    const float* k_w  = (const float*)d_in[4];
    const float* v_w  = (const float*)d_in[5];
    const float* o_w  = (const float*)d_in[6];
    const float* cosp = (const float*)d_in[7];
    const float* sinp = (const float*)d_in[8];
    const float* gate = (const float*)d_in[9];
    const float* eg   = (const float*)d_in[10];
    const float* eu   = (const float*)d_in[11];
    const float* ed   = (const float*)d_in[12];
    const float* sg   = (const float*)d_in[13];
    const float* su   = (const float*)d_in[14];
    const float* sd   = (const float*)d_in[15];
    float* out = (float*)d_out;

    float* x1;
    __half *hxn, *hq0, *hk0, *hv0, *hqr, *hkr, *hctx, *hxg, *hgb, *hgs;
    cudaGetSymbolAddress((void**)&x1,  d_x1);
    cudaGetSymbolAddress((void**)&hxn, h_xn);
    cudaGetSymbolAddress((void**)&hq0, h_q0);
    cudaGetSymbolAddress((void**)&hk0, h_k0);
    cudaGetSymbolAddress((void**)&hv0, h_v0);
    cudaGetSymbolAddress((void**)&hqr, h_qr);
    cudaGetSymbolAddress((void**)&hkr, h_kr);
    cudaGetSymbolAddress((void**)&hctx, h_ctx);
    cudaGetSymbolAddress((void**)&hxg, h_xg);
    cudaGetSymbolAddress((void**)&hgb, h_gb);
    cudaGetSymbolAddress((void**)&hgs, h_gs);

    cudaFuncSetAttribute(hoproj_k,
        cudaFuncAttributeMaxDynamicSharedMemorySize, SMEM_BYTES);
    cudaFuncSetAttribute(hfinal_k,
        cudaFuncAttributeMaxDynamicSharedMemorySize, SMEM_BYTES);
    cudaFuncSetAttribute(hqkv_k,
        cudaFuncAttributeMaxDynamicSharedMemorySize, SMEM_BYTES);
    cudaFuncSetAttribute(hup_all_k,
        cudaFuncAttributeMaxDynamicSharedMemorySize, SMEM_BYTES);
    cudaFuncSetAttribute(hmoedn_k,
        cudaFuncAttributeMaxDynamicSharedMemorySize, SMEM_BYTES);
    cudaFuncSetAttribute(flash_part_k,
        cudaFuncAttributeMaxDynamicSharedMemorySize, FLASH_SMEM);

    // ---- all weight conversions in one launch (ILP=4) ----
    conv_all_k<<<(CONV_TOT + 1023) / 1024, 256>>>(q_w, k_w, v_w, o_w,
                                                  eg, eu, ed, sg, su, sd);

    const dim3 gQKV(NHID / BN, NT / BM, 3);
    const dim3 gFlash(NS / 128, NB * NHEAD, 2);            // split-KV
    const dim3 gProj(NHID / BN, NT / BM);
    const dim3 gUpAll(NSI / BN, NSLOT / BM, 2 * NEXP + 2); // (16, 32, 18)
    const dim3 gMoeDn(NHID / BN, NSLOT / BM, NEXP);

    // ---- attention ----
    rmsnorm_k<<<NT, 256>>>(hs, ln1, hxn);          // also zeroes d_cnt
    hqkv_k<<<gQKV, 256, SMEM_BYTES>>>(hxn);
    rope_k<<<NT, 256>>>(hq0, hk0, cosp, sinp, hqr, hkr);
    flash_part_k<<<gFlash, 256, FLASH_SMEM>>>(hqr, hkr, hv0);
    flash_merge_k<<<NT, 256>>>(hctx);
    hoproj_k<<<gProj, 256, SMEM_BYTES>>>(hctx, x1, hs);

    // ---- MoE routing (fused rmsnorm + gating), gather ----
    rmsnorm_gate_k<<<NT, 256>>>(x1, ln2, gate, hxn);
    gather_k<<<NT, 256>>>(hxn);

    // ---- merged MoE-up + shared-up GEMMs ----
    hup_all_k<<<gUpAll, 256, SMEM_BYTES>>>(hxg, hxn);

    // ---- merged silu·mul over both regions ----
    silumul_all_k<<<(unsigned)((N2_MOE + N2_SH + 255) / 256), 256>>>();

    // ---- MoE down ----
    hmoedn_k<<<gMoeDn, 256, SMEM_BYTES>>>(hgb);

    // ---- final GEMM with fused combine: out = x1 + shdown + routed ----
    hfinal_k<<<gProj, 256, SMEM_BYTES>>>(hgs, out, x1);
}

// round 17
// speedup vs baseline: 1.1815x; 1.0042x over previous
#include <cuda_runtime.h>
#include <cuda_fp16.h>
#include <math.h>

// ---------------------------------------------------------------------------
// Problem constants
// ---------------------------------------------------------------------------
namespace {
constexpr int NB = 2, NS = 1024, NHID = 1024, NHEAD = 8, DHEAD = 128;
constexpr int NEXP = 8, NMI = 1024, NSI = 2048;
constexpr int NT = NB * NS;          // 2048 tokens
constexpr int NSLOT = 2 * NT;        // 4096 expert slots (top-2)

// fp16 GEMM tile: 128x128x32(halves), 8 warps of 64x32, 4-stage cp.async
constexpr int BM = 128, BN = 128, BKH = 32;
constexpr int PAD32 = 20;                        // row stride in b32 (80B)
constexpr int STAGES = 4;
constexpr int STAGE_WORDS = BM * PAD32;          // 2560 b32 per tile-stage
constexpr int SMEM_BYTES = 2 * STAGES * STAGE_WORDS * 4;   // 81920

// flash attention smem: Q + 2xK + 2xV tiles of 128 rows x 68 words
constexpr int FPW = 68;                          // words per row (136 halves)
constexpr int FTILE_W = 128 * FPW;               // 8704 words per tile
constexpr int FLASH_SMEM = 5 * FTILE_W * 4;      // 174080 bytes

constexpr int KVCH = 4;                          // KV tiles per split chunk
}

// ---------------------------------------------------------------------------
// Static device scratch (no allocations allowed)
// ---------------------------------------------------------------------------
// fp32 buffers
__device__ float d_x1[NT * NHID];
__device__ float d_pO0[NT * NHID];    // flash split-KV partial O, chunk 0
__device__ float d_pO1[NT * NHID];    // chunk 1
__device__ float d_pm0[NB * NHEAD * NS], d_pl0[NB * NHEAD * NS];
__device__ float d_pm1[NB * NHEAD * NS], d_pl1[NB * NHEAD * NS];
// fp16 weights
__device__ __half h_qw[NHID * NHID];
__device__ __half h_kw[NHID * NHID];
__device__ __half h_vw[NHID * NHID];
__device__ __half h_ow[NHID * NHID];
__device__ __half h_eg[NEXP * NMI * NHID];
__device__ __half h_eu[NEXP * NMI * NHID];
__device__ __half h_ed[NEXP * NHID * NMI];
__device__ __half h_sg[NSI * NHID];
__device__ __half h_su[NSI * NHID];
__device__ __half h_sd[NHID * NSI];
// fp16 activations
__device__ __half h_xn[NT * NHID];
__device__ __half h_q0[NT * NHID];    // QKV GEMM outputs, (t, head*128+d)
__device__ __half h_k0[NT * NHID];
__device__ __half h_v0[NT * NHID];
__device__ __half h_qr[NT * NHID];    // rope'd + scaled
__device__ __half h_kr[NT * NHID];
__device__ __half h_ctx[NT * NHID];   // flash output
__device__ __half h_xg[NSLOT * NHID];
__device__ __half h_gbuf[NSLOT * NMI];   // MoE gate GEMM out (half)
__device__ __half h_ubuf[NSLOT * NMI];   // MoE up GEMM out (half)
__device__ __half h_gb[NSLOT * NMI];     // silu(g)*u (half)
__device__ __half h_ybuf[NSLOT * NHID];  // MoE down out (half)
__device__ __half h_gs32[NT * NSI];      // shared gate GEMM out (half)
__device__ __half h_us32[NT * NSI];      // shared up GEMM out (half)
__device__ __half h_gs[NT * NSI];        // silu(g)*u (half)
// routing state
__device__ int   d_cnt[NEXP];
__device__ int   d_e0[NT], d_e1[NT], d_r0[NT], d_r1[NT], d_s0[NT], d_s1[NT];
__device__ float d_w0[NT], d_w1[NT];

// ---------------------------------------------------------------------------
// helpers
// ---------------------------------------------------------------------------
__device__ __forceinline__ unsigned smem_u32(const void* p) {
    return (unsigned)__cvta_generic_to_shared(p);
}

__device__ __forceinline__ void cp16(unsigned dst, const void* src, bool pred) {
    int sz = pred ? 16 : 0;
    asm volatile("cp.async.cg.shared.global [%0], [%1], 16, %2;\n"
                 :: "r"(dst), "l"(src), "r"(sz));
}

__device__ __forceinline__ void ldsm4(unsigned& r0, unsigned& r1,
                                      unsigned& r2, unsigned& r3, unsigned addr)
{
    asm volatile("ldmatrix.sync.aligned.m8n8.x4.shared.b16 {%0,%1,%2,%3}, [%4];"
                 : "=r"(r0), "=r"(r1), "=r"(r2), "=r"(r3) : "r"(addr));
}

__device__ __forceinline__ void ldsm4t(unsigned& r0, unsigned& r1,
                                       unsigned& r2, unsigned& r3, unsigned addr)
{
    asm volatile("ldmatrix.sync.aligned.m8n8.x4.trans.shared.b16 {%0,%1,%2,%3}, [%4];"
                 : "=r"(r0), "=r"(r1), "=r"(r2), "=r"(r3) : "r"(addr));
}

__device__ __forceinline__ void mma_f16(float c[4],
    unsigned a0, unsigned a1, unsigned a2, unsigned a3,
    unsigned b0, unsigned b1)
{
    asm volatile(
        "mma.sync.aligned.m16n8k16.row.col.f32.f16.f16.f32 "
        "{%0,%1,%2,%3}, {%4,%5,%6,%7}, {%8,%9}, {%0,%1,%2,%3};\n"
        : "+f"(c[0]), "+f"(c[1]), "+f"(c[2]), "+f"(c[3])
        : "r"(a0), "r"(a1), "r"(a2), "r"(a3), "r"(b0), "r"(b1));
}

__device__ __forceinline__ unsigned packh2(float a, float b) {
    __half2 h = __floats2half2_rn(a, b);
    return *reinterpret_cast<unsigned*>(&h);
}

// ---------------------------------------------------------------------------
// FP16 tensor-core GEMM:  C[M,N] = A[M,K] * B^T  (B stored (N,K) row-major,
// offsets in HALVES).  128x128 block, 8 warps of 64x32 (4x4 m16n8k16),
// 4-stage cp.async, ldmatrix operand loads.  OutT = float or __half.
// FINAL: fuse the MoE combine — out = resid + gemm + w0*yb[s0] + w1*yb[s1].
// ---------------------------------------------------------------------------
template <typename OutT, bool FINAL>
__device__ __forceinline__ void hgemm_body(
    const __half* __restrict__ A, const __half* __restrict__ Bm,
    OutT* __restrict__ C, const float* __restrict__ resid,
    int M, int K, int lda, int ldb, int ldc)
{
    extern __shared__ unsigned smu[];
    unsigned* Asm = smu;                         // [STAGES][BM][PAD32]
    unsigned* Bsm = smu + STAGES * STAGE_WORDS;

    const int tid  = threadIdx.x;
    const int wid  = tid >> 5;
    const int lane = tid & 31;
    const int g    = lane >> 2;
    const int tg   = lane & 3;
    const int wm   = (wid & 1) * 64;
    const int wn   = (wid >> 1) * 32;
    const int row0 = blockIdx.y * BM;
    const int col0 = blockIdx.x * BN;
    if (row0 >= M) return;

    const int rA = (lane & 7) + ((lane >> 3) & 1) * 8;
    const int cA = ((lane >> 4) & 1) * 4;
    const int rB = (lane & 7) + ((lane >> 4) & 1) * 8;
    const int cB = ((lane >> 3) & 1) * 4;

    float c[4][4][4];
#pragma unroll
    for (int mi = 0; mi < 4; ++mi)
#pragma unroll
        for (int ni = 0; ni < 4; ++ni)
#pragma unroll
            for (int r = 0; r < 4; ++r) c[mi][ni][r] = 0.f;

    const int lr = tid >> 1;
    const int lqh = (tid & 1) * 16;
    const int lqw = (tid & 1) * 8;
    const int niter = K / BKH;

#pragma unroll
    for (int st = 0; st < STAGES - 1; ++st) {
        if (st < niter) {
            const int k0 = st * BKH;
            const __half* ga = A + (long)(row0 + lr) * lda + k0 + lqh;
            unsigned da = smem_u32(Asm + st * STAGE_WORDS + lr * PAD32 + lqw);
            bool pa = (row0 + lr) < M;
            cp16(da,      ga,     pa);
            cp16(da + 16, ga + 8, pa);
            const __half* gb = Bm + (long)(col0 + lr) * ldb + k0 + lqh;
            unsigned db = smem_u32(Bsm + st * STAGE_WORDS + lr * PAD32 + lqw);
            cp16(db,      gb,     true);
            cp16(db + 16, gb + 8, true);
        }
        asm volatile("cp.async.commit_group;\n");
    }

    int s = 0;
    for (int it = 0; it < niter; ++it) {
        asm volatile("cp.async.wait_group 2;\n");
        __syncthreads();

        const int pf = it + STAGES - 1;
        if (pf < niter) {
            int sl = s + STAGES - 1; if (sl >= STAGES) sl -= STAGES;
            const int k0 = pf * BKH;
            const __half* ga = A + (long)(row0 + lr) * lda + k0 + lqh;
            unsigned da = smem_u32(Asm + sl * STAGE_WORDS + lr * PAD32 + lqw);
            bool pa = (row0 + lr) < M;
            cp16(da,      ga,     pa);
            cp16(da + 16, ga + 8, pa);
            const __half* gb = Bm + (long)(col0 + lr) * ldb + k0 + lqh;
            unsigned db = smem_u32(Bsm + sl * STAGE_WORDS + lr * PAD32 + lqw);
            cp16(db,      gb,     true);
            cp16(db + 16, gb + 8, true);
        }
        asm volatile("cp.async.commit_group;\n");

        const unsigned a_base = smem_u32(Asm + s * STAGE_WORDS);
        const unsigned b_base = smem_u32(Bsm + s * STAGE_WORDS);
#pragma unroll
        for (int kk = 0; kk < 2; ++kk) {
            const int kb = kk * 8;
            unsigned af[4][4], bf[4][2];
#pragma unroll
            for (int mi = 0; mi < 4; ++mi) {
                unsigned addr = a_base +
                    4u * ((wm + mi * 16 + rA) * PAD32 + kb + cA);
                ldsm4(af[mi][0], af[mi][1], af[mi][2], af[mi][3], addr);
            }
#pragma unroll
            for (int p = 0; p < 2; ++p) {
                unsigned addr = b_base +
                    4u * ((wn + p * 16 + rB) * PAD32 + kb + cB);
                ldsm4(bf[2 * p][0], bf[2 * p][1],
                      bf[2 * p + 1][0], bf[2 * p + 1][1], addr);
            }
#pragma unroll
            for (int mi = 0; mi < 4; ++mi)
#pragma unroll
                for (int ni = 0; ni < 4; ++ni)
                    mma_f16(c[mi][ni], af[mi][0], af[mi][1], af[mi][2], af[mi][3],
                            bf[ni][0], bf[ni][1]);
        }
        if (++s >= STAGES) s = 0;
    }

    // ---- epilogue ----
#pragma unroll
    for (int mi = 0; mi < 4; ++mi) {
#pragma unroll
        for (int half = 0; half < 2; ++half) {
            int r = row0 + wm + mi * 16 + g + half * 8;
            if (r < M) {
                float w0 = 0.f, w1 = 0.f;
                long y0 = 0, y1 = 0;
                if (FINAL) {
                    w0 = d_w0[r]; w1 = d_w1[r];
                    y0 = (long)d_s0[r] * NHID;
                    y1 = (long)d_s1[r] * NHID;
                }
#pragma unroll
                for (int ni = 0; ni < 4; ++ni) {
                    int colg = col0 + wn + ni * 8 + tg * 2;
                    long off = (long)r * ldc + colg;
                    float vx = c[mi][ni][half * 2 + 0];
                    float vy = c[mi][ni][half * 2 + 1];
                    if (resid) {
                        float2 rr = *(const float2*)(resid + off);
                        vx += rr.x; vy += rr.y;
                    }
                    if (FINAL) {
                        __half2 a0 = *(const __half2*)(h_ybuf + y0 + colg);
                        __half2 a1 = *(const __half2*)(h_ybuf + y1 + colg);
                        vx += w0 * __low2float(a0)  + w1 * __low2float(a1);
                        vy += w0 * __high2float(a0) + w1 * __high2float(a1);
                    }
                    if constexpr (sizeof(OutT) == 4) {
                        float2 v; v.x = vx; v.y = vy;
                        *(float2*)((float*)C + off) = v;
                    } else {
                        __half2 hv = __floats2half2_rn(vx, vy);
                        *(__half2*)((__half*)C + off) = hv;
                    }
                }
            }
        }
    }
}

// ---- O-proj (float out, residual)
__global__ __launch_bounds__(256, 2)
void hoproj_k(const __half* __restrict__ A, float* __restrict__ C,
              const float* __restrict__ resid)
{
    hgemm_body<float, false>(A, h_ow, C, resid, NT, NHID, NHID, NHID, NHID);
}

// ---- FINAL shared-down GEMM: writes out = x1 + shdown + routed
__global__ __launch_bounds__(256, 2)
void hfinal_k(const __half* __restrict__ A, float* __restrict__ C,
              const float* __restrict__ resid)
{
    hgemm_body<float, true>(A, h_sd, C, resid, NT, NSI, NSI, NSI, NHID);
}

// ---- fused Q/K/V projection (half out)
__global__ __launch_bounds__(256, 2)
void hqkv_k(const __half* __restrict__ xn)
{
    int z = blockIdx.z;
    const __half* B = (z == 0) ? h_qw : (z == 1) ? h_kw : h_vw;
    __half* C       = (z == 0) ? h_q0 : (z == 1) ? h_k0 : h_v0;
    hgemm_body<__half, false>(xn, B, C, nullptr, NT, NHID, NHID, NHID, NHID);
}

// ---- merged up-projection launch (MoE grouped + shared)
__global__ __launch_bounds__(256, 2)
void hup_all_k(const __half* __restrict__ xg, const __half* __restrict__ xn)
{
    int z = blockIdx.z;
    if (z < 2 * NEXP) {
        if (blockIdx.x >= NMI / BN) return;
        int e = z >> 1;
        int M = d_cnt[e];
        int off = 0;
        for (int i = 0; i < NEXP; ++i) if (i < e) off += d_cnt[i];
        const __half* B = (z & 1) ? h_eu : h_eg;
        __half* C       = (z & 1) ? h_ubuf : h_gbuf;
        hgemm_body<__half, false>(xg + (long)off * NHID, B + (long)e * NMI * NHID,
                                  C + (long)off * NMI, nullptr,
                                  M, NHID, NHID, NHID, NMI);
    } else {
        if (blockIdx.y >= NT / BM) return;
        int w = z - 2 * NEXP;
        hgemm_body<__half, false>(xn, w ? h_su : h_sg, w ? h_us32 : h_gs32,
                                  nullptr, NT, NHID, NHID, NHID, NSI);
    }
}

// ---- MoE down grouped (half out)
__global__ __launch_bounds__(256, 2)
void hmoedn_k(const __half* __restrict__ gb)
{
    int e = blockIdx.z;
    int M = d_cnt[e];
    int off = 0;
    for (int i = 0; i < NEXP; ++i) if (i < e) off += d_cnt[i];
    hgemm_body<__half, false>(gb + (long)off * NMI, h_ed + (long)e * NHID * NMI,
                              h_ybuf + (long)off * NHID, nullptr, M, NMI, NMI, NMI, NHID);
}

// ---------------------------------------------------------------------------
// Flash attention, split-KV: grid (qi=8, bh=16, chunk=2). Chunk 0 covers KV
// tiles [0, min(qi+1,4)), chunk 1 covers [4, qi+1) (qi>=4 only).
// CTAs covering the WHOLE causal range (qi<KVCH, chunk 0) normalize and
// write half ctx directly; the rest write fp32 partials, merged by merge_k.
// ---------------------------------------------------------------------------
__global__ __launch_bounds__(256, 1)
void flash_part_k(const __half* __restrict__ q, const __half* __restrict__ k,
                  const __half* __restrict__ v, __half* __restrict__ octx)
{
    const int qi  = blockIdx.x;
    const int ch  = blockIdx.z;
    const int t0  = ch * KVCH;
    const int t1  = min(qi + 1, t0 + KVCH);
    if (t0 >= qi + 1) return;
    const bool direct = (t0 == 0) && (t1 == qi + 1);

    extern __shared__ unsigned fsm[];
    unsigned* Qs = fsm;
    unsigned* Ks = fsm + FTILE_W;
    unsigned* Vs = fsm + 3 * FTILE_W;

    const int bh  = blockIdx.y;
    const int b   = bh >> 3, n = bh & 7;
    const int tid = threadIdx.x, wid = tid >> 5, lane = tid & 31;
    const int g   = lane >> 2, tg = lane & 3;
    const int wq  = wid * 16;
    const int row0 = qi * 128;

    const long qbase  = ((long)b * NS + row0) * NHID + n * DHEAD;
    const long kvbase = ((long)b * NS) * NHID + n * DHEAD;

    const int rA = (lane & 7) + ((lane >> 3) & 1) * 8;
    const int cA = ((lane >> 4) & 1) * 4;
    const int rB = (lane & 7) + ((lane >> 4) & 1) * 8;
    const int cB = ((lane >> 3) & 1) * 4;
    const int rV = lane & 15;
    const int cV = (lane >> 4) * 4;

    {
        int r = tid >> 1, hh = tid & 1;
        const __half* gq = q + qbase + (long)r * NHID + hh * 64;
        unsigned dq = smem_u32(Qs + r * FPW + hh * 32);
#pragma unroll
        for (int c2 = 0; c2 < 8; ++c2) cp16(dq + c2 * 16, gq + c2 * 8, true);
    }
    {
        int r = tid >> 1, hh = tid & 1;
        const __half* gk = k + kvbase + ((long)t0 * 128 + r) * NHID + hh * 64;
        const __half* gv = v + kvbase + ((long)t0 * 128 + r) * NHID + hh * 64;
        unsigned dk = smem_u32(Ks + r * FPW + hh * 32);
        unsigned dv = smem_u32(Vs + r * FPW + hh * 32);
#pragma unroll
        for (int c2 = 0; c2 < 8; ++c2) {
            cp16(dk + c2 * 16, gk + c2 * 8, true);
            cp16(dv + c2 * 16, gv + c2 * 8, true);
        }
    }
    asm volatile("cp.async.commit_group;\n");
    asm volatile("cp.async.wait_group 0;\n");
    __syncthreads();

    float oacc[16][4];
#pragma unroll
    for (int j = 0; j < 16; ++j)
#pragma unroll
        for (int r = 0; r < 4; ++r) oacc[j][r] = 0.f;
    float m0 = -1e30f, m1 = -1e30f, l0 = 0.f, l1 = 0.f;

    for (int t = t0; t < t1; ++t) {
        const int cur = (t - t0) & 1;
        if (t + 1 < t1) {
            int nxt = (t + 1 - t0) & 1;
            int r = tid >> 1, hh = tid & 1;
            const __half* gk = k + kvbase + ((long)(t + 1) * 128 + r) * NHID + hh * 64;
            const __half* gv = v + kvbase + ((long)(t + 1) * 128 + r) * NHID + hh * 64;
            unsigned dk = smem_u32(Ks + nxt * FTILE_W + r * FPW + hh * 32);
            unsigned dv = smem_u32(Vs + nxt * FTILE_W + r * FPW + hh * 32);
#pragma unroll
            for (int c2 = 0; c2 < 8; ++c2) {
                cp16(dk + c2 * 16, gk + c2 * 8, true);
                cp16(dv + c2 * 16, gv + c2 * 8, true);
            }
        }
        asm volatile("cp.async.commit_group;\n");

        const unsigned kbase = smem_u32(Ks + cur * FTILE_W);
        const unsigned vbase = smem_u32(Vs + cur * FTILE_W);
        const unsigned qbse  = smem_u32(Qs);

        float sacc[16][4];
#pragma unroll
        for (int j = 0; j < 16; ++j)
#pragma unroll
            for (int r = 0; r < 4; ++r) sacc[j][r] = 0.f;

#pragma unroll
        for (int ks = 0; ks < 8; ++ks) {
            unsigned qa[4];
            ldsm4(qa[0], qa[1], qa[2], qa[3],
                  qbse + 4u * ((wq + rA) * FPW + ks * 8 + cA));
#pragma unroll
            for (int p = 0; p < 8; ++p) {
                unsigned b0, b1, b2, b3;
                ldsm4(b0, b1, b2, b3,
                      kbase + 4u * ((p * 16 + rB) * FPW + ks * 8 + cB));
                mma_f16(sacc[2 * p],     qa[0], qa[1], qa[2], qa[3], b0, b1);
                mma_f16(sacc[2 * p + 1], qa[0], qa[1], qa[2], qa[3], b2, b3);
            }
        }

        if (t == qi) {
            int r0l = wq + g, r1l = wq + g + 8;
#pragma unroll
            for (int j = 0; j < 16; ++j) {
                int col = 8 * j + 2 * tg;
                if (col     > r0l) sacc[j][0] = -1e30f;
                if (col + 1 > r0l) sacc[j][1] = -1e30f;
                if (col     > r1l) sacc[j][2] = -1e30f;
                if (col + 1 > r1l) sacc[j][3] = -1e30f;
            }
        }

        float tm0 = -1e30f, tm1 = -1e30f;
#pragma unroll
        for (int j = 0; j < 16; ++j) {
            tm0 = fmaxf(tm0, fmaxf(sacc[j][0], sacc[j][1]));
            tm1 = fmaxf(tm1, fmaxf(sacc[j][2], sacc[j][3]));
        }
        tm0 = fmaxf(tm0, __shfl_xor_sync(0xffffffffu, tm0, 1));
        tm0 = fmaxf(tm0, __shfl_xor_sync(0xffffffffu, tm0, 2));
        tm1 = fmaxf(tm1, __shfl_xor_sync(0xffffffffu, tm1, 1));
        tm1 = fmaxf(tm1, __shfl_xor_sync(0xffffffffu, tm1, 2));
        float nm0 = fmaxf(m0, tm0), nm1 = fmaxf(m1, tm1);
        float al0 = __expf(m0 - nm0), al1 = __expf(m1 - nm1);

        float rs0 = 0.f, rs1 = 0.f;
        unsigned pf[8][4];
#pragma unroll
        for (int j = 0; j < 16; ++j) {
            float p0 = __expf(sacc[j][0] - nm0);
            float p1 = __expf(sacc[j][1] - nm0);
            float p2 = __expf(sacc[j][2] - nm1);
            float p3 = __expf(sacc[j][3] - nm1);
            rs0 += p0 + p1; rs1 += p2 + p3;
            int ks = j >> 1;
            if ((j & 1) == 0) { pf[ks][0] = packh2(p0, p1); pf[ks][1] = packh2(p2, p3); }
            else              { pf[ks][2] = packh2(p0, p1); pf[ks][3] = packh2(p2, p3); }
        }
        rs0 += __shfl_xor_sync(0xffffffffu, rs0, 1);
        rs0 += __shfl_xor_sync(0xffffffffu, rs0, 2);
        rs1 += __shfl_xor_sync(0xffffffffu, rs1, 1);
        rs1 += __shfl_xor_sync(0xffffffffu, rs1, 2);
        m0 = nm0; m1 = nm1;
        l0 = l0 * al0 + rs0;
        l1 = l1 * al1 + rs1;

#pragma unroll
        for (int j = 0; j < 16; ++j) {
            oacc[j][0] *= al0; oacc[j][1] *= al0;
            oacc[j][2] *= al1; oacc[j][3] *= al1;
        }

#pragma unroll
        for (int ks = 0; ks < 8; ++ks) {
#pragma unroll
            for (int p = 0; p < 8; ++p) {
                unsigned v0, v1, v2, v3;
                ldsm4t(v0, v1, v2, v3,
                       vbase + 4u * ((ks * 16 + rV) * FPW + p * 8 + cV));
                mma_f16(oacc[2 * p],     pf[ks][0], pf[ks][1], pf[ks][2], pf[ks][3], v0, v1);
                mma_f16(oacc[2 * p + 1], pf[ks][0], pf[ks][1], pf[ks][2], pf[ks][3], v2, v3);
            }
        }

        asm volatile("cp.async.wait_group 0;\n");
        __syncthreads();
    }

    long obase0 = ((long)b * NS + row0 + wq + g) * NHID + n * DHEAD;
    long obase1 = obase0 + 8L * NHID;

    if (direct) {
        // ---- whole causal range done here: normalize & write half ctx ----
        float il0 = 1.f / l0, il1 = 1.f / l1;
#pragma unroll
        for (int j = 0; j < 16; ++j) {
            int col = 8 * j + 2 * tg;
            __half2 h0 = __floats2half2_rn(oacc[j][0] * il0, oacc[j][1] * il0);
            __half2 h1 = __floats2half2_rn(oacc[j][2] * il1, oacc[j][3] * il1);
            *(__half2*)(octx + obase0 + col) = h0;
            *(__half2*)(octx + obase1 + col) = h1;
        }
    } else {
        // ---- store UNNORMALIZED partial O (fp32) + per-row m, l ----
        float* pO = ch ? d_pO1 : d_pO0;
        float* pm = ch ? d_pm1 : d_pm0;
        float* pl = ch ? d_pl1 : d_pl0;
#pragma unroll
        for (int j = 0; j < 16; ++j) {
            int col = 8 * j + 2 * tg;
            float2 v0; v0.x = oacc[j][0]; v0.y = oacc[j][1];
            float2 v1; v1.x = oacc[j][2]; v1.y = oacc[j][3];
            *(float2*)(pO + obase0 + col) = v0;
            *(float2*)(pO + obase1 + col) = v1;
        }
        if (tg == 0) {
            int midx = bh * NS + row0 + wq + g;
            pm[midx]     = m0; pl[midx]     = l0;
            pm[midx + 8] = m1; pl[midx + 8] = l1;
        }
    }
}

// ---- merge split-KV partials for tokens with qi>=KVCH (s >= 512) ----
__global__ void flash_merge_k(__half* __restrict__ o)
{
    int i = blockIdx.x;                  // 0..NT/2-1
    int b = i >> 9;                      // 512 merge-tokens per batch
    int s = (KVCH * 128) + (i & 511);
    int t = b * NS + s;
    __shared__ float sc0[NHEAD], sc1[NHEAD];
    int tid = threadIdx.x;
    if (tid < NHEAD) {
        int midx = (b * NHEAD + tid) * NS + s;
        float m0 = d_pm0[midx], m1 = d_pm1[midx];
        float M = fmaxf(m0, m1);
        float e0 = __expf(m0 - M), e1 = __expf(m1 - M);
        float inv = 1.f / (e0 * d_pl0[midx] + e1 * d_pl1[midx]);
        sc0[tid] = e0 * inv;
        sc1[tid] = e1 * inv;
    }
    __syncthreads();
    long base = (long)t * NHID;
#pragma unroll
    for (int u = 0; u < 2; ++u) {
        int e2 = tid + u * 256;              // half2 index 0..511
        int n = e2 >> 6;                     // head
        long off = base + 2 * e2;
        float2 v = *(const float2*)(d_pO0 + off);
        float2 w = *(const float2*)(d_pO1 + off);
        float r0 = v.x * sc0[n] + w.x * sc1[n];
        float r1 = v.y * sc0[n] + w.y * sc1[n];
        *(__half2*)(o + off) = __floats2half2_rn(r0, r1);
    }
}

// ---------------------------------------------------------------------------
// fused weight conversion fp32 -> fp16, ILP=4 float4s per thread
// ---------------------------------------------------------------------------
namespace {
constexpr int W1 = NHID * NHID / 4;
constexpr int WE = NEXP * NMI * NHID / 4;
constexpr int WS = NSI * NHID / 4;
constexpr int CONV_TOT = 4 * W1 + 3 * WE + 3 * WS;
}

__device__ __forceinline__ void conv_one(
    int i,
    const float* qw, const float* kw, const float* vw, const float* ow,
    const float* eg, const float* eu, const float* ed,
    const float* sg, const float* su, const float* sd)
{
    const float* src; __half* dst; int j = i;
    if      (j < 1 * W1) { src = qw; dst = h_qw; }
    else if (j < 2 * W1) { src = kw; dst = h_kw; j -= 1 * W1; }
    else if (j < 3 * W1) { src = vw; dst = h_vw; j -= 2 * W1; }
    else if (j < 4 * W1) { src = ow; dst = h_ow; j -= 3 * W1; }
    else {
        j -= 4 * W1;
        if      (j < 1 * WE) { src = eg; dst = h_eg; }
        else if (j < 2 * WE) { src = eu; dst = h_eu; j -= 1 * WE; }
        else if (j < 3 * WE) { src = ed; dst = h_ed; j -= 2 * WE; }
        else {
            j -= 3 * WE;
            if      (j < 1 * WS) { src = sg; dst = h_sg; }
            else if (j < 2 * WS) { src = su; dst = h_su; j -= 1 * WS; }
            else                 { src = sd; dst = h_sd; j -= 2 * WS; }
        }
    }
    float4 v = *(const float4*)(src + 4 * (long)j);
    __half2 h0 = __floats2half2_rn(v.x, v.y);
    __half2 h1 = __floats2half2_rn(v.z, v.w);
    *(__half2*)(dst + 4 * (long)j)     = h0;
    *(__half2*)(dst + 4 * (long)j + 2) = h1;
}

__global__ void conv_all_k(
    const float* __restrict__ qw, const float* __restrict__ kw,
    const float* __restrict__ vw, const float* __restrict__ ow,
    const float* __restrict__ eg, const float* __restrict__ eu,
    const float* __restrict__ ed, const float* __restrict__ sg,
    const float* __restrict__ su, const float* __restrict__ sd)
{
    int base = blockIdx.x * 1024 + threadIdx.x;
#pragma unroll
    for (int u = 0; u < 4; ++u) {
        int i = base + u * 256;
        if (i < CONV_TOT)
            conv_one(i, qw, kw, vw, ow, eg, eu, ed, sg, su, sd);
    }
}

// ---------------------------------------------------------------------------
// Elementwise / reduction kernels
// ---------------------------------------------------------------------------
__global__ void rmsnorm_k(const float* __restrict__ x,
                          const float* __restrict__ w,
                          __half* __restrict__ oh)
{
    int t = blockIdx.x;
    if (t == 0 && threadIdx.x < NEXP) d_cnt[threadIdx.x] = 0;
    const float* xr = x + (long)t * NHID;
    __shared__ float red[256];
    float s = 0.f;
    for (int i = threadIdx.x; i < NHID; i += 256) { float v = xr[i]; s += v * v; }
    red[threadIdx.x] = s;
    __syncthreads();
    for (int st = 128; st > 0; st >>= 1) {
        if (threadIdx.x < st) red[threadIdx.x] += red[threadIdx.x + st];
        __syncthreads();
    }
    float scale = rsqrtf(red[0] / (float)NHID + 1e-6f);
    for (int i = threadIdx.x; i < NHID; i += 256)
        oh[(long)t * NHID + i] = __float2half_rn(xr[i] * scale * w[i]);
}

__global__ void rmsnorm_gate_k(const float* __restrict__ x,
                               const float* __restrict__ w,
                               const float* __restrict__ gw,
                               __half* __restrict__ oh)
{
    int t = blockIdx.x;
    int tid = threadIdx.x, wd = tid >> 5, lane = tid & 31;
    const float* xr = x + (long)t * NHID;
    __shared__ float red[256];
    __shared__ float xs[NHID];
    float s = 0.f;
    for (int i = tid; i < NHID; i += 256) { float v = xr[i]; s += v * v; }
    red[tid] = s;
    __syncthreads();
    for (int st = 128; st > 0; st >>= 1) {
        if (tid < st) red[tid] += red[tid + st];
        __syncthreads();
    }
    float scale = rsqrtf(red[0] / (float)NHID + 1e-6f);
    for (int i = tid; i < NHID; i += 256) {
        float v = xr[i] * scale * w[i];
        xs[i] = v;
        oh[(long)t * NHID + i] = __float2half_rn(v);
    }
    __syncthreads();

    const float* gr = gw + (long)wd * NHID;
    float gsum = 0.f;
    for (int i = lane; i < NHID; i += 32) gsum += xs[i] * gr[i];
    for (int o = 16; o; o >>= 1) gsum += __shfl_xor_sync(0xffffffffu, gsum, o);
    __shared__ float lg[NEXP];
    if (lane == 0) lg[wd] = gsum;
    __syncthreads();
    if (tid == 0) {
        float mx = lg[0];
        for (int e = 1; e < NEXP; ++e) mx = fmaxf(mx, lg[e]);
        float p[NEXP];
        for (int e = 0; e < NEXP; ++e) p[e] = expf(lg[e] - mx);
        int e0 = 0; float b0 = p[0];
        for (int e = 1; e < NEXP; ++e) if (p[e] > b0) { b0 = p[e]; e0 = e; }
        int e1 = -1; float b1 = -1.f;
        for (int e = 0; e < NEXP; ++e)
            if (e != e0 && p[e] > b1) { b1 = p[e]; e1 = e; }
        float denom = b0 + b1;
        d_e0[t] = e0; d_e1[t] = e1;
        d_w0[t] = b0 / denom; d_w1[t] = b1 / denom;
        d_r0[t] = atomicAdd(&d_cnt[e0], 1);
        d_r1[t] = atomicAdd(&d_cnt[e1], 1);
    }
}

// RoPE, __half2-vectorized: one (n, d-pair) element per thread.
__global__ void rope_k(const __half* __restrict__ q0, const __half* __restrict__ k0,
                       const float* __restrict__ cosp, const float* __restrict__ sinp,
                       __half* __restrict__ qr, __half* __restrict__ kr)
{
    int t = blockIdx.x;
    int s = t % NS;
    const float inv = 0.08838834764831845f;  // 1/sqrt(128)
    int i = threadIdx.x;                     // 0..255 = NHEAD*32 exactly
    int n = i >> 5, d = (i & 31) * 2;
    long base = (long)t * NHID + n * DHEAD;
    float2 c  = *(const float2*)(cosp + s * DHEAD + d);
    float2 sn = *(const float2*)(sinp + s * DHEAD + d);

    __half2 a0 = *(const __half2*)(q0 + base + d);
    __half2 a1 = *(const __half2*)(q0 + base + d + 64);
    float a0x = __low2float(a0), a0y = __high2float(a0);
    float a1x = __low2float(a1), a1y = __high2float(a1);
    *(__half2*)(qr + base + d) =
        __floats2half2_rn((a0x * c.x - a1x * sn.x) * inv,
                          (a0y * c.y - a1y * sn.y) * inv);
    *(__half2*)(qr + base + d + 64) =
        __floats2half2_rn((a1x * c.x + a0x * sn.x) * inv,
                          (a1y * c.y + a0y * sn.y) * inv);

    __half2 b0 = *(const __half2*)(k0 + base + d);
    __half2 b1 = *(const __half2*)(k0 + base + d + 64);
    float b0x = __low2float(b0), b0y = __high2float(b0);
    float b1x = __low2float(b1), b1y = __high2float(b1);
    *(__half2*)(kr + base + d) =
        __floats2half2_rn(b0x * c.x - b1x * sn.x,
                          b0y * c.y - b1y * sn.y);
    *(__half2*)(kr + base + d + 64) =
        __floats2half2_rn(b1x * c.x + b0x * sn.x,
                          b1y * c.y + b0y * sn.y);
}

// gather: computes slot = prefix(d_cnt)[e] + rank inline (d_cnt final here)
__global__ void gather_k(const __half* __restrict__ xnh)
{
    int t = blockIdx.x;
    __shared__ int ss[2];
    if (threadIdx.x == 0) {
        int pre[NEXP];
        int a = 0;
        for (int e = 0; e < NEXP; ++e) { pre[e] = a; a += d_cnt[e]; }
        int s0 = pre[d_e0[t]] + d_r0[t];
        int s1 = pre[d_e1[t]] + d_r1[t];
        d_s0[t] = s0; d_s1[t] = s1;
        ss[0] = s0; ss[1] = s1;
    }
    __syncthreads();
    const uint4* src = (const uint4*)(xnh + (long)t * NHID);
    uint4* dst0 = (uint4*)(h_xg + (long)ss[0] * NHID);
    uint4* dst1 = (uint4*)(h_xg + (long)ss[1] * NHID);
    for (int i = threadIdx.x; i < NHID / 8; i += 256) {
        uint4 v = src[i];
        dst0[i] = v;
        dst1[i] = v;
    }
}

// merged silu(g)*u over MoE + shared regions (half2 elements)
namespace {
constexpr long N2_MOE = (long)NSLOT * NMI / 2;
constexpr long N2_SH  = (long)NT * NSI / 2;
}
__global__ void silumul_all_k()
{
    long i = (long)blockIdx.x * 256 + threadIdx.x;
    const __half2* g; const __half2* u; __half2* o; long j;
    if (i < N2_MOE) {
        g = (const __half2*)h_gbuf; u = (const __half2*)h_ubuf;
        o = (__half2*)h_gb; j = i;
    } else if (i < N2_MOE + N2_SH) {
        g = (const __half2*)h_gs32; u = (const __half2*)h_us32;
        o = (__half2*)h_gs; j = i - N2_MOE;
    } else return;
    __half2 gh = g[j];
    __half2 uh = u[j];
    float g0 = __low2float(gh),  g1 = __high2float(gh);
    float u0 = __low2float(uh),  u1 = __high2float(uh);
    float r0 = g0 / (1.f + __expf(-g0)) * u0;
    float r1 = g1 / (1.f + __expf(-g1)) * u1;
    o[j] = __floats2half2_rn(r0, r1);
}

// ---------------------------------------------------------------------------
// Launch
// ---------------------------------------------------------------------------
extern "C" void kernel_launch(void* const* d_in, const int* in_sizes, int n_in,
                              void* d_out, int out_size)
{
    (void)in_sizes; (void)n_in; (void)out_size;

    const float* hs   = (const float*)d_in[0];
    const float* ln1  = (const float*)d_in[1];
    const float* ln2  = (const float*)d_in[2];
    const float* q_w  = (const float*)d_in[3];
    const float* k_w  = (const float*)d_in[4];
    const float* v_w  = (const float*)d_in[5];
    const float* o_w  = (const float*)d_in[6];
    const float* cosp = (const float*)d_in[7];
    const float* sinp = (const float*)d_in[8];
    const float* gate = (const float*)d_in[9];
    const float* eg   = (const float*)d_in[10];
    const float* eu   = (const float*)d_in[11];
    const float* ed   = (const float*)d_in[12];
    const float* sg   = (const float*)d_in[13];
    const float* su   = (const float*)d_in[14];
    const float* sd   = (const float*)d_in[15];
    float* out = (float*)d_out;

    float* x1;
    __half *hxn, *hq0, *hk0, *hv0, *hqr, *hkr, *hctx, *hxg, *hgb, *hgs;
    cudaGetSymbolAddress((void**)&x1,  d_x1);
    cudaGetSymbolAddress((void**)&hxn, h_xn);
    cudaGetSymbolAddress((void**)&hq0, h_q0);
    cudaGetSymbolAddress((void**)&hk0, h_k0);
    cudaGetSymbolAddress((void**)&hv0, h_v0);
    cudaGetSymbolAddress((void**)&hqr, h_qr);
    cudaGetSymbolAddress((void**)&hkr, h_kr);
    cudaGetSymbolAddress((void**)&hctx, h_ctx);
    cudaGetSymbolAddress((void**)&hxg, h_xg);
    cudaGetSymbolAddress((void**)&hgb, h_gb);
    cudaGetSymbolAddress((void**)&hgs, h_gs);

    cudaFuncSetAttribute(hoproj_k,
        cudaFuncAttributeMaxDynamicSharedMemorySize, SMEM_BYTES);
    cudaFuncSetAttribute(hfinal_k,
        cudaFuncAttributeMaxDynamicSharedMemorySize, SMEM_BYTES);
    cudaFuncSetAttribute(hqkv_k,
        cudaFuncAttributeMaxDynamicSharedMemorySize, SMEM_BYTES);
    cudaFuncSetAttribute(hup_all_k,
        cudaFuncAttributeMaxDynamicSharedMemorySize, SMEM_BYTES);
    cudaFuncSetAttribute(hmoedn_k,
        cudaFuncAttributeMaxDynamicSharedMemorySize, SMEM_BYTES);
    cudaFuncSetAttribute(flash_part_k,
        cudaFuncAttributeMaxDynamicSharedMemorySize, FLASH_SMEM);

    // ---- all weight conversions in one launch (ILP=4) ----
    conv_all_k<<<(CONV_TOT + 1023) / 1024, 256>>>(q_w, k_w, v_w, o_w,
                                                  eg, eu, ed, sg, su, sd);

    const dim3 gQKV(NHID / BN, NT / BM, 3);
    const dim3 gFlash(NS / 128, NB * NHEAD, 2);            // split-KV
    const dim3 gProj(NHID / BN, NT / BM);
    const dim3 gUpAll(NSI / BN, NSLOT / BM, 2 * NEXP + 2); // (16, 32, 18)
    const dim3 gMoeDn(NHID / BN, NSLOT / BM, NEXP);

    // ---- attention ----
    rmsnorm_k<<<NT, 256>>>(hs, ln1, hxn);          // also zeroes d_cnt
    hqkv_k<<<gQKV, 256, SMEM_BYTES>>>(hxn);
    rope_k<<<NT, 256>>>(hq0, hk0, cosp, sinp, hqr, hkr);
    flash_part_k<<<gFlash, 256, FLASH_SMEM>>>(hqr, hkr, hv0, hctx);
    flash_merge_k<<<NT / 2, 256>>>(hctx);
    hoproj_k<<<gProj, 256, SMEM_BYTES>>>(hctx, x1, hs);

    // ---- MoE routing (fused rmsnorm + gating), gather ----
    rmsnorm_gate_k<<<NT, 256>>>(x1, ln2, gate, hxn);
    gather_k<<<NT, 256>>>(hxn);

    // ---- merged MoE-up + shared-up GEMMs ----
    hup_all_k<<<gUpAll, 256, SMEM_BYTES>>>(hxg, hxn);

    // ---- merged silu·mul over both regions ----
    silumul_all_k<<<(unsigned)((N2_MOE + N2_SH + 255) / 256), 256>>>();

    // ---- MoE down ----
    hmoedn_k<<<gMoeDn, 256, SMEM_BYTES>>>(hgb);

    // ---- final GEMM with fused combine: out = x1 + shdown + routed ----
    hfinal_k<<<gProj, 256, SMEM_BYTES>>>(hgs, out, x1);
}